// round 7
// baseline (speedup 1.0000x reference)
#include <cuda_runtime.h>
#include <math.h>
#include <stdint.h>

// ---------------- problem constants ----------------
#define BGPT 4
#define TGPT 1024
#define DGPT 1024
#define HGPT 16
#define HDH  64
#define LGPT 8
#define VGPT 4096
#define MGPT (BGPT*TGPT)   // 4096 tokens
#define FGPT (4*DGPT)      // 4096 ff dim

// ---------------- scratch (device globals; no allocs allowed) ----------------
__device__ float g_x [MGPT*DGPT];    // residual stream
__device__ float g_h [MGPT*DGPT];    // LN out / attn out
__device__ float g_q [MGPT*DGPT];
__device__ float g_k [MGPT*DGPT];
__device__ float g_v [MGPT*DGPT];
__device__ float g_ff[MGPT*FGPT];    // gelu out

// ---------------- packed f32x2 helpers ----------------
#define FMA2(c, a, b) asm("fma.rn.f32x2 %0, %1, %2, %0;" : "+l"(c) : "l"(a), "l"(b))
#define PACK2(d, f)   asm("mov.b64 %0, {%1, %1};" : "=l"(d) : "f"(f))

// ---------------- embedding ----------------
__global__ void embed_kernel(const int* __restrict__ idx,
                             const float* __restrict__ tok,
                             const float* __restrict__ pos,
                             float* __restrict__ x)
{
    int i = blockIdx.x * blockDim.x + threadIdx.x;
    if (i >= MGPT * DGPT) return;
    int row = i / DGPT;
    int d   = i - row * DGPT;
    int t   = row & (TGPT - 1);
    x[i] = tok[(size_t)idx[row] * DGPT + d] + pos[(size_t)t * DGPT + d];
}

// ---------------- layernorm (fp32 -> fp32) ----------------
__global__ void __launch_bounds__(256) ln_kernel(const float* __restrict__ in,
                                                 float* __restrict__ out,
                                                 const float* __restrict__ w,
                                                 const float* __restrict__ b)
{
    int row = blockIdx.x;
    const float* x = in + (size_t)row * DGPT;
    int tid = threadIdx.x;
    __shared__ float red[8];

    float s = 0.f;
    for (int d = tid; d < DGPT; d += 256) s += x[d];
    #pragma unroll
    for (int o = 16; o; o >>= 1) s += __shfl_xor_sync(0xffffffffu, s, o);
    if ((tid & 31) == 0) red[tid >> 5] = s;
    __syncthreads();
    if (tid < 32) {
        float v = (tid < 8) ? red[tid] : 0.f;
        #pragma unroll
        for (int o = 4; o; o >>= 1) v += __shfl_xor_sync(0xffffffffu, v, o);
        if (tid == 0) red[0] = v;
    }
    __syncthreads();
    float mean = red[0] * (1.f / DGPT);

    float q = 0.f;
    for (int d = tid; d < DGPT; d += 256) { float t = x[d] - mean; q += t * t; }
    __syncthreads();
    #pragma unroll
    for (int o = 16; o; o >>= 1) q += __shfl_xor_sync(0xffffffffu, q, o);
    if ((tid & 31) == 0) red[tid >> 5] = q;
    __syncthreads();
    if (tid < 32) {
        float v = (tid < 8) ? red[tid] : 0.f;
        #pragma unroll
        for (int o = 4; o; o >>= 1) v += __shfl_xor_sync(0xffffffffu, v, o);
        if (tid == 0) red[0] = v;
    }
    __syncthreads();
    float rstd = rsqrtf(red[0] * (1.f / DGPT) + 1e-5f);

    for (int d = tid; d < DGPT; d += 256)
        out[(size_t)row * DGPT + d] = (x[d] - mean) * rstd * w[d] + b[d];
}

// ---------------- f32x2 GEMM: C[M,N] = A[M,K] @ W[N,K]^T (+epilogue) ------
// CTA tile 128(M) x 256(N), BK=32, 256 threads, thread tile 8x16.
// MODE: 0 = +bias | 1 = +bias, exact GELU | 2 = +bias +res | 3 = plain
#define TMf 128
#define TNf 256
#define BKf 32
#define AS_STRIDE 128
#define BS_STRIDE 256
#define AS_BUF (BKf*AS_STRIDE)              // 4096 floats
#define BS_BUF (BKf*BS_STRIDE)              // 8192 floats
#define F_SMEM ((2*AS_BUF + 2*BS_BUF)*4)    // 98304 bytes

template<int MODE>
__global__ void __launch_bounds__(256, 1) gemm_f2(
    const float* __restrict__ A, const float* __restrict__ W,
    const float* __restrict__ bias, const float* __restrict__ res,
    float* __restrict__ C, int M, int N, int K)
{
    extern __shared__ __align__(16) float sm[];
    float* sA = sm;                 // [2][BK][128]
    float* sB = sm + 2 * AS_BUF;    // [2][BK][256]

    const int tid = threadIdx.x;
    const int ty  = tid >> 4;       // 0..15 (8-row group)
    const int tx  = tid & 15;       // 0..15 (8-col group, x2 halves)
    const int bm  = blockIdx.y * TMf;
    const int bn  = blockIdx.x * TNf;

    unsigned long long accL[32], accR[32];
    #pragma unroll
    for (int i = 0; i < 32; i++) { accL[i] = 0ull; accR[i] = 0ull; }

    // loader mapping: A: 2 threads/row (16 floats each); B: 1 thread/row (32 floats)
    const int rA  = tid >> 1;
    const int kcA = (tid & 1) * 16;
    const int rB  = tid;
    const float* Abase = A + (size_t)(bm + rA) * K + kcA;
    const float* Bbase = W + (size_t)(bn + rB) * K;

    float4 pa[4], pb[8];
    auto ldg = [&](int s) {
        const float* ap = Abase + s * BKf;
        #pragma unroll
        for (int c = 0; c < 4; c++) pa[c] = *(const float4*)(ap + c * 4);
        const float* bp = Bbase + s * BKf;
        #pragma unroll
        for (int c = 0; c < 8; c++) pb[c] = *(const float4*)(bp + c * 4);
    };
    auto sts = [&](float* sAb, float* sBb) {
        #pragma unroll
        for (int c = 0; c < 4; c++) {
            float* p = sAb + (kcA + c * 4) * AS_STRIDE + rA;
            p[0 * AS_STRIDE] = pa[c].x; p[1 * AS_STRIDE] = pa[c].y;
            p[2 * AS_STRIDE] = pa[c].z; p[3 * AS_STRIDE] = pa[c].w;
        }
        #pragma unroll
        for (int c = 0; c < 8; c++) {
            float* p = sBb + (c * 4) * BS_STRIDE + rB;
            p[0 * BS_STRIDE] = pb[c].x; p[1 * BS_STRIDE] = pb[c].y;
            p[2 * BS_STRIDE] = pb[c].z; p[3 * BS_STRIDE] = pb[c].w;
        }
    };
    auto compute = [&](const float* sAb, const float* sBb, int klo, int khi) {
        #pragma unroll 4
        for (int kk = klo; kk < khi; kk++) {
            const float* ar = sAb + kk * AS_STRIDE + ty * 8;
            float4 a0 = *(const float4*)ar;
            float4 a1 = *(const float4*)(ar + 4);
            unsigned long long ap2[8];
            PACK2(ap2[0], a0.x); PACK2(ap2[1], a0.y);
            PACK2(ap2[2], a0.z); PACK2(ap2[3], a0.w);
            PACK2(ap2[4], a1.x); PACK2(ap2[5], a1.y);
            PACK2(ap2[6], a1.z); PACK2(ap2[7], a1.w);
            const float* br = sBb + kk * BS_STRIDE + tx * 8;
            ulonglong2 b0 = *(const ulonglong2*)br;
            ulonglong2 b1 = *(const ulonglong2*)(br + 4);
            ulonglong2 b2 = *(const ulonglong2*)(br + 128);
            ulonglong2 b3 = *(const ulonglong2*)(br + 132);
            unsigned long long bL[4] = { b0.x, b0.y, b1.x, b1.y };
            unsigned long long bR[4] = { b2.x, b2.y, b3.x, b3.y };
            #pragma unroll
            for (int i = 0; i < 8; i++) {
                #pragma unroll
                for (int p = 0; p < 4; p++) {
                    FMA2(accL[i * 4 + p], ap2[i], bL[p]);
                    FMA2(accR[i * 4 + p], ap2[i], bR[p]);
                }
            }
        }
    };

    const int NS = K / BKf;
    ldg(0);
    sts(sA, sB);
    __syncthreads();

    for (int s = 0; s < NS; s++) {
        float* sAb = sA + (s & 1) * AS_BUF;
        float* sBb = sB + (s & 1) * BS_BUF;
        if (s + 1 < NS) {
            ldg(s + 1);
            compute(sAb, sBb, 0, 24);
            sts(sA + ((s + 1) & 1) * AS_BUF, sB + ((s + 1) & 1) * BS_BUF);
            compute(sAb, sBb, 24, 32);
        } else {
            compute(sAb, sBb, 0, 32);
        }
        __syncthreads();
    }

    // ---- epilogue ----
    const int cL = bn + tx * 8;
    const int cR = cL + 128;
    float bb[16];
    if (MODE != 3) {
        #pragma unroll
        for (int j = 0; j < 8; j++) { bb[j] = bias[cL + j]; bb[8 + j] = bias[cR + j]; }
    }
    #pragma unroll
    for (int i = 0; i < 8; i++) {
        const size_t row = (size_t)(bm + ty * 8 + i);
        float o[16];
        #pragma unroll
        for (int p = 0; p < 4; p++) {
            float2 fL = *(float2*)&accL[i * 4 + p];
            float2 fR = *(float2*)&accR[i * 4 + p];
            o[2 * p]     = fL.x; o[2 * p + 1]     = fL.y;
            o[8 + 2 * p] = fR.x; o[8 + 2 * p + 1] = fR.y;
        }
        #pragma unroll
        for (int j = 0; j < 16; j++) {
            float v = o[j];
            if (MODE != 3) v += bb[j];
            if (MODE == 1) v = 0.5f * v * (1.f + erff(v * 0.70710678118654752f));
            if (MODE == 2) v += res[row * N + (j < 8 ? cL + j : cR + j - 8)];
            o[j] = v;
        }
        *(float4*)(C + row * N + cL)     = *(float4*)&o[0];
        *(float4*)(C + row * N + cL + 4) = *(float4*)&o[4];
        *(float4*)(C + row * N + cR)     = *(float4*)&o[8];
        *(float4*)(C + row * N + cR + 4) = *(float4*)&o[12];
    }
}

// ---------------- causal flash attention (fp32) ------------------------
__global__ void __launch_bounds__(256) attn_kernel(const float* __restrict__ q,
                                                   const float* __restrict__ k,
                                                   const float* __restrict__ v,
                                                   float* __restrict__ y)
{
    __shared__ __align__(16) float Qs[64][68];
    __shared__ __align__(16) float Ks[32][68];
    __shared__ __align__(16) float Vs[32][68];
    __shared__ __align__(16) float Ss[64][36];

    int bh = blockIdx.x;
    int b  = bh / HGPT;
    int h  = bh % HGPT;
    int qb = blockIdx.y;
    int tid = threadIdx.x;

    const float* qbase = q + ((size_t)(b * TGPT + qb * 64)) * DGPT + h * HDH;
    const float* kbase = k + ((size_t)(b * TGPT)) * DGPT + h * HDH;
    const float* vbase = v + ((size_t)(b * TGPT)) * DGPT + h * HDH;

    for (int f = tid; f < 1024; f += 256) {
        int r = f >> 4, c4 = (f & 15) * 4;
        *(float4*)&Qs[r][c4] = *(const float4*)(qbase + (size_t)r * DGPT + c4);
    }

    int i  = tid >> 2;
    int cg = tid & 3;
    int d0 = cg * 16;
    int qglob = qb * 64 + i;

    float O[16];
    #pragma unroll
    for (int dd = 0; dd < 16; dd++) O[dd] = 0.f;
    float m_run = -1e30f, l_run = 0.f;

    int nchunks = 2 * qb + 2;
    __syncthreads();

    for (int ch = 0; ch < nchunks; ch++) {
        int j0 = ch * 32;
        for (int f = tid; f < 512; f += 256) {
            int r = f >> 4, c4 = (f & 15) * 4;
            *(float4*)&Ks[r][c4] = *(const float4*)(kbase + (size_t)(j0 + r) * DGPT + c4);
            *(float4*)&Vs[r][c4] = *(const float4*)(vbase + (size_t)(j0 + r) * DGPT + c4);
        }
        __syncthreads();

        float sv[8];
        #pragma unroll
        for (int cc = 0; cc < 8; cc++) sv[cc] = 0.f;
        #pragma unroll 8
        for (int d = 0; d < 64; d++) {
            float qd = Qs[i][d];
            #pragma unroll
            for (int cc = 0; cc < 8; cc++)
                sv[cc] = fmaf(qd, Ks[cg * 8 + cc][d], sv[cc]);
        }
        float mloc = -1e30f;
        #pragma unroll
        for (int cc = 0; cc < 8; cc++) {
            float s = sv[cc] * 0.125f;
            if (j0 + cg * 8 + cc > qglob) s = -1e30f;
            sv[cc] = s;
            mloc = fmaxf(mloc, s);
        }
        mloc = fmaxf(mloc, __shfl_xor_sync(0xffffffffu, mloc, 1));
        mloc = fmaxf(mloc, __shfl_xor_sync(0xffffffffu, mloc, 2));

        float mnew = fmaxf(m_run, mloc);
        float corr = expf(m_run - mnew);
        float psum = 0.f;
        #pragma unroll
        for (int cc = 0; cc < 8; cc++) {
            float p = expf(sv[cc] - mnew);
            Ss[i][cg * 8 + cc] = p;
            psum += p;
        }
        psum += __shfl_xor_sync(0xffffffffu, psum, 1);
        psum += __shfl_xor_sync(0xffffffffu, psum, 2);
        l_run = l_run * corr + psum;
        m_run = mnew;
        #pragma unroll
        for (int dd = 0; dd < 16; dd++) O[dd] *= corr;
        __syncwarp();

        #pragma unroll 4
        for (int c = 0; c < 32; c++) {
            float p = Ss[i][c];
            float4 v0 = *(const float4*)&Vs[c][d0];
            float4 v1 = *(const float4*)&Vs[c][d0 + 4];
            float4 v2 = *(const float4*)&Vs[c][d0 + 8];
            float4 v3 = *(const float4*)&Vs[c][d0 + 12];
            O[0]  = fmaf(p, v0.x, O[0]);  O[1]  = fmaf(p, v0.y, O[1]);
            O[2]  = fmaf(p, v0.z, O[2]);  O[3]  = fmaf(p, v0.w, O[3]);
            O[4]  = fmaf(p, v1.x, O[4]);  O[5]  = fmaf(p, v1.y, O[5]);
            O[6]  = fmaf(p, v1.z, O[6]);  O[7]  = fmaf(p, v1.w, O[7]);
            O[8]  = fmaf(p, v2.x, O[8]);  O[9]  = fmaf(p, v2.y, O[9]);
            O[10] = fmaf(p, v2.z, O[10]); O[11] = fmaf(p, v2.w, O[11]);
            O[12] = fmaf(p, v3.x, O[12]); O[13] = fmaf(p, v3.y, O[13]);
            O[14] = fmaf(p, v3.z, O[14]); O[15] = fmaf(p, v3.w, O[15]);
        }
        __syncthreads();
    }

    float inv = 1.f / l_run;
    float* yp = y + ((size_t)(b * TGPT + qglob)) * DGPT + h * HDH + d0;
    #pragma unroll
    for (int dd = 0; dd < 16; dd++) yp[dd] = O[dd] * inv;
}

// ---------------- launcher ----------------
extern "C" void kernel_launch(void* const* d_in, const int* in_sizes, int n_in,
                              void* d_out, int out_size)
{
    const int*   idx    = (const int*)  d_in[0];
    const float* tok    = (const float*)d_in[1];
    const float* pos    = (const float*)d_in[2];
    const float* ln1_w  = (const float*)d_in[3];
    const float* ln1_b  = (const float*)d_in[4];
    const float* Wq     = (const float*)d_in[5];
    const float* bq     = (const float*)d_in[6];
    const float* Wk     = (const float*)d_in[7];
    const float* bk     = (const float*)d_in[8];
    const float* Wv     = (const float*)d_in[9];
    const float* bv     = (const float*)d_in[10];
    const float* Wproj  = (const float*)d_in[11];
    const float* bproj  = (const float*)d_in[12];
    const float* ln2_w  = (const float*)d_in[13];
    const float* ln2_b  = (const float*)d_in[14];
    const float* W1     = (const float*)d_in[15];
    const float* b1     = (const float*)d_in[16];
    const float* W2     = (const float*)d_in[17];
    const float* b2     = (const float*)d_in[18];
    const float* lnf_w  = (const float*)d_in[19];
    const float* lnf_b  = (const float*)d_in[20];
    const float* Wlogit = (const float*)d_in[21];
    const float* Wdev   = (const float*)d_in[22];
    float* out = (float*)d_out;

    float *xp, *hp, *qp, *kp, *vp, *fp;
    cudaGetSymbolAddress((void**)&xp, g_x);
    cudaGetSymbolAddress((void**)&hp, g_h);
    cudaGetSymbolAddress((void**)&qp, g_q);
    cudaGetSymbolAddress((void**)&kp, g_k);
    cudaGetSymbolAddress((void**)&vp, g_v);
    cudaGetSymbolAddress((void**)&fp, g_ff);

    cudaFuncSetAttribute(gemm_f2<0>, cudaFuncAttributeMaxDynamicSharedMemorySize, F_SMEM);
    cudaFuncSetAttribute(gemm_f2<1>, cudaFuncAttributeMaxDynamicSharedMemorySize, F_SMEM);
    cudaFuncSetAttribute(gemm_f2<2>, cudaFuncAttributeMaxDynamicSharedMemorySize, F_SMEM);
    cudaFuncSetAttribute(gemm_f2<3>, cudaFuncAttributeMaxDynamicSharedMemorySize, F_SMEM);

    dim3 gD(DGPT / TNf, MGPT / TMf);   // (4, 32)
    dim3 gF(FGPT / TNf, MGPT / TMf);   // (16, 32)
    dim3 gV(VGPT / TNf, MGPT / TMf);   // (16, 32)
    dim3 gA(BGPT * HGPT, TGPT / 64);

    embed_kernel<<<(MGPT * DGPT + 255) / 256, 256>>>(idx, tok, pos, xp);

    for (int l = 0; l < LGPT; l++) {
        size_t oD  = (size_t)l * DGPT * DGPT;
        size_t oF  = (size_t)l * FGPT * DGPT;
        size_t ob  = (size_t)l * DGPT;
        size_t obf = (size_t)l * FGPT;

        ln_kernel<<<MGPT, 256>>>(xp, hp, ln1_w + ob, ln1_b + ob);
        gemm_f2<0><<<gD, 256, F_SMEM>>>(hp, Wq + oD, bq + ob, nullptr, qp, MGPT, DGPT, DGPT);
        gemm_f2<0><<<gD, 256, F_SMEM>>>(hp, Wk + oD, bk + ob, nullptr, kp, MGPT, DGPT, DGPT);
        gemm_f2<0><<<gD, 256, F_SMEM>>>(hp, Wv + oD, bv + ob, nullptr, vp, MGPT, DGPT, DGPT);
        attn_kernel<<<gA, 256>>>(qp, kp, vp, hp);
        gemm_f2<2><<<gD, 256, F_SMEM>>>(hp, Wproj + oD, bproj + ob, xp, xp, MGPT, DGPT, DGPT);

        ln_kernel<<<MGPT, 256>>>(xp, hp, ln2_w + ob, ln2_b + ob);
        gemm_f2<1><<<gF, 256, F_SMEM>>>(hp, W1 + oF, b1 + obf, nullptr, fp, MGPT, FGPT, DGPT);
        gemm_f2<2><<<gD, 256, F_SMEM>>>(fp, W2 + oF, b2 + ob, xp, xp, MGPT, DGPT, FGPT);
    }

    ln_kernel<<<MGPT, 256>>>(xp, hp, lnf_w, lnf_b);
    gemm_f2<3><<<gV, 256, F_SMEM>>>(hp, Wlogit, nullptr, nullptr, out, MGPT, VGPT, DGPT);
    gemm_f2<3><<<gV, 256, F_SMEM>>>(hp, Wdev, nullptr, nullptr, out + (size_t)MGPT * VGPT, MGPT, VGPT, DGPT);
}

// round 8
// speedup vs baseline: 1.4901x; 1.4901x over previous
#include <cuda_runtime.h>
#include <cuda_fp16.h>
#include <math.h>
#include <stdint.h>

// ---------------- problem constants ----------------
#define BGPT 4
#define TGPT 1024
#define DGPT 1024
#define HGPT 16
#define HDH  64
#define LGPT 8
#define VGPT 4096
#define MGPT (BGPT*TGPT)   // 4096 tokens
#define FGPT (4*DGPT)      // 4096 ff dim

// weight scratch offsets (elements)
#define SZ_WQ   ((size_t)LGPT*DGPT*DGPT)
#define SZ_W1   ((size_t)LGPT*FGPT*DGPT)
#define SZ_HEAD ((size_t)VGPT*DGPT)
#define O_WQ    ((size_t)0)
#define O_WK    (O_WQ + SZ_WQ)
#define O_WV    (O_WK + SZ_WQ)
#define O_WP    (O_WV + SZ_WQ)
#define O_W1    (O_WP + SZ_WQ)
#define O_W2    (O_W1 + SZ_W1)
#define O_WLG   (O_W2 + SZ_W1)
#define O_WDV   (O_WLG + SZ_HEAD)
#define WTOT    (O_WDV + SZ_HEAD)

// ---------------- scratch (device globals; no allocs allowed) ----------------
__device__ float g_x [MGPT*DGPT];              // residual stream (fp32)
__device__ float g_q [MGPT*DGPT];
__device__ float g_k [MGPT*DGPT];
__device__ float g_v [MGPT*DGPT];
__device__ __half g_ahi[(size_t)MGPT*DGPT];    // activation hi (LN out / attn out)
__device__ __half g_alo[(size_t)MGPT*DGPT];
__device__ __half g_fhi[(size_t)MGPT*FGPT];    // ff activation hi
__device__ __half g_flo[(size_t)MGPT*FGPT];
__device__ __half g_whi[WTOT];                 // split weights
__device__ __half g_wlo[WTOT];

// ---------------- helpers ----------------
__device__ __forceinline__ void split_f16(float v, __half& h, __half& l)
{
    h = __float2half_rn(v);
    l = __float2half_rn(v - __half2float(h));
}

// ---------------- embedding ----------------
__global__ void embed_kernel(const int* __restrict__ idx,
                             const float* __restrict__ tok,
                             const float* __restrict__ pos,
                             float* __restrict__ x)
{
    int i = blockIdx.x * blockDim.x + threadIdx.x;
    if (i >= MGPT * DGPT) return;
    int row = i / DGPT;
    int d   = i - row * DGPT;
    int t   = row & (TGPT - 1);
    x[i] = tok[(size_t)idx[row] * DGPT + d] + pos[(size_t)t * DGPT + d];
}

// ---------------- fp32 -> fp16 hi/lo split (weights) ----------------
__global__ void __launch_bounds__(256) convsplit_kernel(const float* __restrict__ in,
                                                        __half* __restrict__ hi,
                                                        __half* __restrict__ lo,
                                                        size_t n4)
{
    size_t i = (size_t)blockIdx.x * blockDim.x + threadIdx.x;
    if (i >= n4) return;
    size_t e = i * 4;
    float4 v = *(const float4*)(in + e);
    __half hx, hy, hz, hw, lx, ly, lz, lw;
    split_f16(v.x, hx, lx); split_f16(v.y, hy, ly);
    split_f16(v.z, hz, lz); split_f16(v.w, hw, lw);
    __half2 h01 = __halves2half2(hx, hy);
    __half2 h23 = __halves2half2(hz, hw);
    __half2 l01 = __halves2half2(lx, ly);
    __half2 l23 = __halves2half2(lz, lw);
    uint2 ho, loo;
    ho.x  = *(uint32_t*)&h01; ho.y  = *(uint32_t*)&h23;
    loo.x = *(uint32_t*)&l01; loo.y = *(uint32_t*)&l23;
    *(uint2*)(hi + e) = ho;
    *(uint2*)(lo + e) = loo;
}

// ---------------- layernorm: fp32 in -> fp16 hi/lo out ----------------
__global__ void __launch_bounds__(256) ln_kernel(const float* __restrict__ in,
                                                 __half* __restrict__ ohi,
                                                 __half* __restrict__ olo,
                                                 const float* __restrict__ w,
                                                 const float* __restrict__ b)
{
    int row = blockIdx.x;
    const float* x = in + (size_t)row * DGPT;
    int tid = threadIdx.x;
    __shared__ float red[8];

    float s = 0.f;
    for (int d = tid; d < DGPT; d += 256) s += x[d];
    #pragma unroll
    for (int o = 16; o; o >>= 1) s += __shfl_xor_sync(0xffffffffu, s, o);
    if ((tid & 31) == 0) red[tid >> 5] = s;
    __syncthreads();
    if (tid < 32) {
        float v = (tid < 8) ? red[tid] : 0.f;
        #pragma unroll
        for (int o = 4; o; o >>= 1) v += __shfl_xor_sync(0xffffffffu, v, o);
        if (tid == 0) red[0] = v;
    }
    __syncthreads();
    float mean = red[0] * (1.f / DGPT);

    float q = 0.f;
    for (int d = tid; d < DGPT; d += 256) { float t = x[d] - mean; q += t * t; }
    __syncthreads();
    #pragma unroll
    for (int o = 16; o; o >>= 1) q += __shfl_xor_sync(0xffffffffu, q, o);
    if ((tid & 31) == 0) red[tid >> 5] = q;
    __syncthreads();
    if (tid < 32) {
        float v = (tid < 8) ? red[tid] : 0.f;
        #pragma unroll
        for (int o = 4; o; o >>= 1) v += __shfl_xor_sync(0xffffffffu, v, o);
        if (tid == 0) red[0] = v;
    }
    __syncthreads();
    float rstd = rsqrtf(red[0] * (1.f / DGPT) + 1e-5f);

    for (int d = tid; d < DGPT; d += 256) {
        float v = (x[d] - mean) * rstd * w[d] + b[d];
        __half h, l;
        split_f16(v, h, l);
        ohi[(size_t)row * DGPT + d] = h;
        olo[(size_t)row * DGPT + d] = l;
    }
}

// ---------------- tensor-core GEMM helpers ----------------
__device__ __forceinline__ void ldm4(uint32_t r[4], const __half* p)
{
    uint32_t a = (uint32_t)__cvta_generic_to_shared(p);
    asm volatile("ldmatrix.sync.aligned.m8n8.x4.shared.b16 {%0,%1,%2,%3}, [%4];\n"
                 : "=r"(r[0]), "=r"(r[1]), "=r"(r[2]), "=r"(r[3]) : "r"(a));
}

// fp32-accum fp16 mma (the hi*hi term)
__device__ __forceinline__ void mma_f32(float c[4], const uint32_t a[4], const uint32_t b[2])
{
    asm volatile(
        "mma.sync.aligned.m16n8k16.row.col.f32.f16.f16.f32 "
        "{%0,%1,%2,%3}, {%4,%5,%6,%7}, {%8,%9}, {%0,%1,%2,%3};\n"
        : "+f"(c[0]), "+f"(c[1]), "+f"(c[2]), "+f"(c[3])
        : "r"(a[0]), "r"(a[1]), "r"(a[2]), "r"(a[3]), "r"(b[0]), "r"(b[1]));
}

// fp16-accum fp16 mma (the two correction terms)
__device__ __forceinline__ void mma_f16(uint32_t c[2], const uint32_t a[4], const uint32_t b[2])
{
    asm volatile(
        "mma.sync.aligned.m16n8k16.row.col.f16.f16.f16.f16 "
        "{%0,%1}, {%2,%3,%4,%5}, {%6,%7}, {%0,%1};\n"
        : "+r"(c[0]), "+r"(c[1])
        : "r"(a[0]), "r"(a[1]), "r"(a[2]), "r"(a[3]), "r"(b[0]), "r"(b[1]));
}

// ---------------- GEMM: C[M,N] = A[M,K] @ W[N,K]^T  (fp16x3, mixed acc) ----
// MODE: 0 = +bias (fp32 out) | 1 = +bias, GELU, fp16 hi/lo out
//       2 = +bias +res (fp32 out) | 3 = plain fp32 out
#define BKg 32
#define PK  40
#define SMBUF (128*PK)
#define SMMAT (2*SMBUF)
#define GSMEM_BYTES (4*SMMAT*2)  // 81920 bytes

template<int MODE>
__global__ void __launch_bounds__(256) gemm_tc(
    const __half* __restrict__ Ahi, const __half* __restrict__ Alo,
    const __half* __restrict__ Whi, const __half* __restrict__ Wlo,
    const float* __restrict__ bias, const float* __restrict__ res,
    float* __restrict__ C,
    __half* __restrict__ Chi, __half* __restrict__ Clo,
    int M, int N, int K)
{
    extern __shared__ __align__(16) __half sm[];
    __half* sAh = sm;
    __half* sAl = sm + SMMAT;
    __half* sBh = sm + 2 * SMMAT;
    __half* sBl = sm + 3 * SMMAT;

    const int tid  = threadIdx.x;
    const int lane = tid & 31;
    const int wid  = tid >> 5;
    const int wm   = wid >> 2;          // 0..1
    const int wn   = wid & 3;           // 0..3
    const int bm   = blockIdx.y * 128;
    const int bn   = blockIdx.x * 128;

    const int lrow = tid >> 1;
    const int lcol = (tid & 1) << 4;
    const __half* gAh = Ahi + (size_t)(bm + lrow) * K + lcol;
    const __half* gAl = Alo + (size_t)(bm + lrow) * K + lcol;
    const __half* gBh = Whi + (size_t)(bn + lrow) * K + lcol;
    const __half* gBl = Wlo + (size_t)(bn + lrow) * K + lcol;

    const int a_r = wm * 64 + (lane & 15);
    const int a_c = (lane >> 4) * 8;
    const int b_r = wn * 32 + (lane >> 4) * 8 + (lane & 7);
    const int b_c = ((lane >> 3) & 1) * 8;

    float acc[4][4][4];          // fp32 accumulator (hi*hi)
    uint32_t acc16[4][4][2];     // fp16x2 accumulator (hi*lo + lo*hi)
    #pragma unroll
    for (int mi = 0; mi < 4; mi++)
        #pragma unroll
        for (int ni = 0; ni < 4; ni++) {
            #pragma unroll
            for (int r = 0; r < 4; r++) acc[mi][ni][r] = 0.f;
            acc16[mi][ni][0] = 0u; acc16[mi][ni][1] = 0u;
        }

    uint4 rAh0, rAh1, rAl0, rAl1, rBh0, rBh1, rBl0, rBl1;

    const int NS = K / BKg;
    rAh0 = *(const uint4*)(gAh);     rAh1 = *(const uint4*)(gAh + 8);
    rAl0 = *(const uint4*)(gAl);     rAl1 = *(const uint4*)(gAl + 8);
    rBh0 = *(const uint4*)(gBh);     rBh1 = *(const uint4*)(gBh + 8);
    rBl0 = *(const uint4*)(gBl);     rBl1 = *(const uint4*)(gBl + 8);
    {
        __half* p = sAh + lrow * PK + lcol;
        *(uint4*)p = rAh0; *(uint4*)(p + 8) = rAh1;
        p = sAl + lrow * PK + lcol;
        *(uint4*)p = rAl0; *(uint4*)(p + 8) = rAl1;
        p = sBh + lrow * PK + lcol;
        *(uint4*)p = rBh0; *(uint4*)(p + 8) = rBh1;
        p = sBl + lrow * PK + lcol;
        *(uint4*)p = rBl0; *(uint4*)(p + 8) = rBl1;
    }
    __syncthreads();

    for (int s = 0; s < NS; s++) {
        if (s + 1 < NS) {
            int k0 = (s + 1) * BKg;
            rAh0 = *(const uint4*)(gAh + k0);  rAh1 = *(const uint4*)(gAh + k0 + 8);
            rAl0 = *(const uint4*)(gAl + k0);  rAl1 = *(const uint4*)(gAl + k0 + 8);
            rBh0 = *(const uint4*)(gBh + k0);  rBh1 = *(const uint4*)(gBh + k0 + 8);
            rBl0 = *(const uint4*)(gBl + k0);  rBl1 = *(const uint4*)(gBl + k0 + 8);
        }

        const int bo = (s & 1) * SMBUF;
        #pragma unroll
        for (int ks = 0; ks < 2; ks++) {
            const int k0 = ks * 16;
            uint32_t afh[4][4], afl[4][4];
            #pragma unroll
            for (int mi = 0; mi < 4; mi++) {
                const int off = bo + (a_r + mi * 16) * PK + k0 + a_c;
                ldm4(afh[mi], sAh + off);
                ldm4(afl[mi], sAl + off);
            }
            uint32_t bfh[4][2], bfl[4][2];
            #pragma unroll
            for (int np = 0; np < 2; np++) {
                const int off = bo + (b_r + np * 16) * PK + k0 + b_c;
                uint32_t t[4];
                ldm4(t, sBh + off);
                bfh[np * 2][0] = t[0]; bfh[np * 2][1] = t[1];
                bfh[np * 2 + 1][0] = t[2]; bfh[np * 2 + 1][1] = t[3];
                ldm4(t, sBl + off);
                bfl[np * 2][0] = t[0]; bfl[np * 2][1] = t[1];
                bfl[np * 2 + 1][0] = t[2]; bfl[np * 2 + 1][1] = t[3];
            }
            // hi*hi -> fp32 accumulators
            #pragma unroll
            for (int mi = 0; mi < 4; mi++)
                #pragma unroll
                for (int ni = 0; ni < 4; ni++)
                    mma_f32(acc[mi][ni], afh[mi], bfh[ni]);
            // hi*lo -> shared fp16 accumulators
            #pragma unroll
            for (int mi = 0; mi < 4; mi++)
                #pragma unroll
                for (int ni = 0; ni < 4; ni++)
                    mma_f16(acc16[mi][ni], afh[mi], bfl[ni]);
            // lo*hi -> same fp16 accumulators
            #pragma unroll
            for (int mi = 0; mi < 4; mi++)
                #pragma unroll
                for (int ni = 0; ni < 4; ni++)
                    mma_f16(acc16[mi][ni], afl[mi], bfh[ni]);
        }

        if (s + 1 < NS) {
            const int bo2 = ((s + 1) & 1) * SMBUF;
            __half* p = sAh + bo2 + lrow * PK + lcol;
            *(uint4*)p = rAh0; *(uint4*)(p + 8) = rAh1;
            p = sAl + bo2 + lrow * PK + lcol;
            *(uint4*)p = rAl0; *(uint4*)(p + 8) = rAl1;
            p = sBh + bo2 + lrow * PK + lcol;
            *(uint4*)p = rBh0; *(uint4*)(p + 8) = rBh1;
            p = sBl + bo2 + lrow * PK + lcol;
            *(uint4*)p = rBl0; *(uint4*)(p + 8) = rBl1;
            __syncthreads();
        }
    }

    // epilogue
    const int er = bm + wm * 64 + (lane >> 2);
    const int ec = bn + wn * 32 + (lane & 3) * 2;
    #pragma unroll
    for (int mi = 0; mi < 4; mi++) {
        #pragma unroll
        for (int ni = 0; ni < 4; ni++) {
            const int col = ec + ni * 8;
            const __half2 c01 = *(const __half2*)&acc16[mi][ni][0];
            const __half2 c23 = *(const __half2*)&acc16[mi][ni][1];
            #pragma unroll
            for (int h = 0; h < 2; h++) {
                const size_t row = (size_t)(er + mi * 16 + h * 8);
                float v0 = acc[mi][ni][h * 2];
                float v1 = acc[mi][ni][h * 2 + 1];
                if (h == 0) { v0 += __half2float(c01.x); v1 += __half2float(c01.y); }
                else        { v0 += __half2float(c23.x); v1 += __half2float(c23.y); }
                if (MODE != 3) { v0 += bias[col]; v1 += bias[col + 1]; }
                if (MODE == 1) {
                    v0 = 0.5f * v0 * (1.f + erff(v0 * 0.70710678118654752f));
                    v1 = 0.5f * v1 * (1.f + erff(v1 * 0.70710678118654752f));
                    __half h0, l0, h1, l1;
                    split_f16(v0, h0, l0);
                    split_f16(v1, h1, l1);
                    *(__half2*)(Chi + row * N + col) = __halves2half2(h0, h1);
                    *(__half2*)(Clo + row * N + col) = __halves2half2(l0, l1);
                } else {
                    if (MODE == 2) {
                        v0 += res[row * N + col];
                        v1 += res[row * N + col + 1];
                    }
                    float2 o; o.x = v0; o.y = v1;
                    *(float2*)(C + row * N + col) = o;
                }
            }
        }
    }
}

// ---------------- causal flash attention (fp32, fp16 hi/lo out) ----------
__global__ void __launch_bounds__(256) attn_kernel(const float* __restrict__ q,
                                                   const float* __restrict__ k,
                                                   const float* __restrict__ v,
                                                   __half* __restrict__ yhi,
                                                   __half* __restrict__ ylo)
{
    __shared__ __align__(16) float Qs[64][68];
    __shared__ __align__(16) float Ks[32][68];
    __shared__ __align__(16) float Vs[32][68];
    __shared__ __align__(16) float Ss[64][36];

    int bh = blockIdx.x;
    int b  = bh / HGPT;
    int h  = bh % HGPT;
    int qb = blockIdx.y;
    int tid = threadIdx.x;

    const float* qbase = q + ((size_t)(b * TGPT + qb * 64)) * DGPT + h * HDH;
    const float* kbase = k + ((size_t)(b * TGPT)) * DGPT + h * HDH;
    const float* vbase = v + ((size_t)(b * TGPT)) * DGPT + h * HDH;

    for (int f = tid; f < 1024; f += 256) {
        int r = f >> 4, c4 = (f & 15) * 4;
        *(float4*)&Qs[r][c4] = *(const float4*)(qbase + (size_t)r * DGPT + c4);
    }

    int i  = tid >> 2;
    int cg = tid & 3;
    int d0 = cg * 16;
    int qglob = qb * 64 + i;

    float O[16];
    #pragma unroll
    for (int dd = 0; dd < 16; dd++) O[dd] = 0.f;
    float m_run = -1e30f, l_run = 0.f;

    int nchunks = 2 * qb + 2;
    __syncthreads();

    for (int ch = 0; ch < nchunks; ch++) {
        int j0 = ch * 32;
        for (int f = tid; f < 512; f += 256) {
            int r = f >> 4, c4 = (f & 15) * 4;
            *(float4*)&Ks[r][c4] = *(const float4*)(kbase + (size_t)(j0 + r) * DGPT + c4);
            *(float4*)&Vs[r][c4] = *(const float4*)(vbase + (size_t)(j0 + r) * DGPT + c4);
        }
        __syncthreads();

        float sv[8];
        #pragma unroll
        for (int cc = 0; cc < 8; cc++) sv[cc] = 0.f;
        #pragma unroll 8
        for (int d = 0; d < 64; d++) {
            float qd = Qs[i][d];
            #pragma unroll
            for (int cc = 0; cc < 8; cc++)
                sv[cc] = fmaf(qd, Ks[cg * 8 + cc][d], sv[cc]);
        }
        float mloc = -1e30f;
        #pragma unroll
        for (int cc = 0; cc < 8; cc++) {
            float s = sv[cc] * 0.125f;
            if (j0 + cg * 8 + cc > qglob) s = -1e30f;
            sv[cc] = s;
            mloc = fmaxf(mloc, s);
        }
        mloc = fmaxf(mloc, __shfl_xor_sync(0xffffffffu, mloc, 1));
        mloc = fmaxf(mloc, __shfl_xor_sync(0xffffffffu, mloc, 2));

        float mnew = fmaxf(m_run, mloc);
        float corr = expf(m_run - mnew);
        float psum = 0.f;
        #pragma unroll
        for (int cc = 0; cc < 8; cc++) {
            float p = expf(sv[cc] - mnew);
            Ss[i][cg * 8 + cc] = p;
            psum += p;
        }
        psum += __shfl_xor_sync(0xffffffffu, psum, 1);
        psum += __shfl_xor_sync(0xffffffffu, psum, 2);
        l_run = l_run * corr + psum;
        m_run = mnew;
        #pragma unroll
        for (int dd = 0; dd < 16; dd++) O[dd] *= corr;
        __syncwarp();

        #pragma unroll 4
        for (int c = 0; c < 32; c++) {
            float p = Ss[i][c];
            float4 v0 = *(const float4*)&Vs[c][d0];
            float4 v1 = *(const float4*)&Vs[c][d0 + 4];
            float4 v2 = *(const float4*)&Vs[c][d0 + 8];
            float4 v3 = *(const float4*)&Vs[c][d0 + 12];
            O[0]  = fmaf(p, v0.x, O[0]);  O[1]  = fmaf(p, v0.y, O[1]);
            O[2]  = fmaf(p, v0.z, O[2]);  O[3]  = fmaf(p, v0.w, O[3]);
            O[4]  = fmaf(p, v1.x, O[4]);  O[5]  = fmaf(p, v1.y, O[5]);
            O[6]  = fmaf(p, v1.z, O[6]);  O[7]  = fmaf(p, v1.w, O[7]);
            O[8]  = fmaf(p, v2.x, O[8]);  O[9]  = fmaf(p, v2.y, O[9]);
            O[10] = fmaf(p, v2.z, O[10]); O[11] = fmaf(p, v2.w, O[11]);
            O[12] = fmaf(p, v3.x, O[12]); O[13] = fmaf(p, v3.y, O[13]);
            O[14] = fmaf(p, v3.z, O[14]); O[15] = fmaf(p, v3.w, O[15]);
        }
        __syncthreads();
    }

    float inv = 1.f / l_run;
    size_t base = ((size_t)(b * TGPT + qglob)) * DGPT + h * HDH + d0;
    #pragma unroll
    for (int dd = 0; dd < 16; dd += 2) {
        float v0 = O[dd] * inv;
        float v1 = O[dd + 1] * inv;
        __half h0, l0, h1, l1;
        split_f16(v0, h0, l0);
        split_f16(v1, h1, l1);
        *(__half2*)(yhi + base + dd) = __halves2half2(h0, h1);
        *(__half2*)(ylo + base + dd) = __halves2half2(l0, l1);
    }
}

// ---------------- launcher ----------------
static inline void convsplit(const float* in, __half* hi, __half* lo, size_t n)
{
    size_t n4 = n / 4;
    convsplit_kernel<<<(unsigned)((n4 + 255) / 256), 256>>>(in, hi, lo, n4);
}

extern "C" void kernel_launch(void* const* d_in, const int* in_sizes, int n_in,
                              void* d_out, int out_size)
{
    const int*   idx    = (const int*)  d_in[0];
    const float* tok    = (const float*)d_in[1];
    const float* pos    = (const float*)d_in[2];
    const float* ln1_w  = (const float*)d_in[3];
    const float* ln1_b  = (const float*)d_in[4];
    const float* Wq     = (const float*)d_in[5];
    const float* bq     = (const float*)d_in[6];
    const float* Wk     = (const float*)d_in[7];
    const float* bk     = (const float*)d_in[8];
    const float* Wv     = (const float*)d_in[9];
    const float* bv     = (const float*)d_in[10];
    const float* Wproj  = (const float*)d_in[11];
    const float* bproj  = (const float*)d_in[12];
    const float* ln2_w  = (const float*)d_in[13];
    const float* ln2_b  = (const float*)d_in[14];
    const float* W1     = (const float*)d_in[15];
    const float* b1     = (const float*)d_in[16];
    const float* W2     = (const float*)d_in[17];
    const float* b2     = (const float*)d_in[18];
    const float* lnf_w  = (const float*)d_in[19];
    const float* lnf_b  = (const float*)d_in[20];
    const float* Wlogit = (const float*)d_in[21];
    const float* Wdev   = (const float*)d_in[22];
    float* out = (float*)d_out;

    float *xp, *qp, *kp, *vp;
    __half *whi, *wlo, *ahi, *alo, *fhi, *flo;
    cudaGetSymbolAddress((void**)&xp, g_x);
    cudaGetSymbolAddress((void**)&qp, g_q);
    cudaGetSymbolAddress((void**)&kp, g_k);
    cudaGetSymbolAddress((void**)&vp, g_v);
    cudaGetSymbolAddress((void**)&whi, g_whi);
    cudaGetSymbolAddress((void**)&wlo, g_wlo);
    cudaGetSymbolAddress((void**)&ahi, g_ahi);
    cudaGetSymbolAddress((void**)&alo, g_alo);
    cudaGetSymbolAddress((void**)&fhi, g_fhi);
    cudaGetSymbolAddress((void**)&flo, g_flo);

    cudaFuncSetAttribute(gemm_tc<0>, cudaFuncAttributeMaxDynamicSharedMemorySize, GSMEM_BYTES);
    cudaFuncSetAttribute(gemm_tc<1>, cudaFuncAttributeMaxDynamicSharedMemorySize, GSMEM_BYTES);
    cudaFuncSetAttribute(gemm_tc<2>, cudaFuncAttributeMaxDynamicSharedMemorySize, GSMEM_BYTES);
    cudaFuncSetAttribute(gemm_tc<3>, cudaFuncAttributeMaxDynamicSharedMemorySize, GSMEM_BYTES);

    // split all weights once
    convsplit(Wq,     whi + O_WQ,  wlo + O_WQ,  SZ_WQ);
    convsplit(Wk,     whi + O_WK,  wlo + O_WK,  SZ_WQ);
    convsplit(Wv,     whi + O_WV,  wlo + O_WV,  SZ_WQ);
    convsplit(Wproj,  whi + O_WP,  wlo + O_WP,  SZ_WQ);
    convsplit(W1,     whi + O_W1,  wlo + O_W1,  SZ_W1);
    convsplit(W2,     whi + O_W2,  wlo + O_W2,  SZ_W1);
    convsplit(Wlogit, whi + O_WLG, wlo + O_WLG, SZ_HEAD);
    convsplit(Wdev,   whi + O_WDV, wlo + O_WDV, SZ_HEAD);

    dim3 gD(DGPT / 128, MGPT / 128);
    dim3 gF(FGPT / 128, MGPT / 128);
    dim3 gV(VGPT / 128, MGPT / 128);
    dim3 gA(BGPT * HGPT, TGPT / 64);

    embed_kernel<<<(MGPT * DGPT + 255) / 256, 256>>>(idx, tok, pos, xp);

    for (int l = 0; l < LGPT; l++) {
        size_t oD  = (size_t)l * DGPT * DGPT;
        size_t oF  = (size_t)l * FGPT * DGPT;
        size_t ob  = (size_t)l * DGPT;
        size_t obf = (size_t)l * FGPT;

        ln_kernel<<<MGPT, 256>>>(xp, ahi, alo, ln1_w + ob, ln1_b + ob);
        gemm_tc<0><<<gD, 256, GSMEM_BYTES>>>(ahi, alo, whi + O_WQ + oD, wlo + O_WQ + oD,
                                             bq + ob, nullptr, qp, nullptr, nullptr,
                                             MGPT, DGPT, DGPT);
        gemm_tc<0><<<gD, 256, GSMEM_BYTES>>>(ahi, alo, whi + O_WK + oD, wlo + O_WK + oD,
                                             bk + ob, nullptr, kp, nullptr, nullptr,
                                             MGPT, DGPT, DGPT);
        gemm_tc<0><<<gD, 256, GSMEM_BYTES>>>(ahi, alo, whi + O_WV + oD, wlo + O_WV + oD,
                                             bv + ob, nullptr, vp, nullptr, nullptr,
                                             MGPT, DGPT, DGPT);
        attn_kernel<<<gA, 256>>>(qp, kp, vp, ahi, alo);
        gemm_tc<2><<<gD, 256, GSMEM_BYTES>>>(ahi, alo, whi + O_WP + oD, wlo + O_WP + oD,
                                             bproj + ob, xp, xp, nullptr, nullptr,
                                             MGPT, DGPT, DGPT);

        ln_kernel<<<MGPT, 256>>>(xp, ahi, alo, ln2_w + ob, ln2_b + ob);
        gemm_tc<1><<<gF, 256, GSMEM_BYTES>>>(ahi, alo, whi + O_W1 + oF, wlo + O_W1 + oF,
                                             b1 + obf, nullptr, nullptr, fhi, flo,
                                             MGPT, FGPT, DGPT);
        gemm_tc<2><<<gD, 256, GSMEM_BYTES>>>(fhi, flo, whi + O_W2 + oF, wlo + O_W2 + oF,
                                             b2 + ob, xp, xp, nullptr, nullptr,
                                             MGPT, DGPT, FGPT);
    }

    ln_kernel<<<MGPT, 256>>>(xp, ahi, alo, lnf_w, lnf_b);
    gemm_tc<3><<<gV, 256, GSMEM_BYTES>>>(ahi, alo, whi + O_WLG, wlo + O_WLG,
                                         nullptr, nullptr, out, nullptr, nullptr,
                                         MGPT, VGPT, DGPT);
    gemm_tc<3><<<gV, 256, GSMEM_BYTES>>>(ahi, alo, whi + O_WDV, wlo + O_WDV,
                                         nullptr, nullptr, out + (size_t)MGPT * VGPT, nullptr, nullptr,
                                         MGPT, VGPT, DGPT);
}

// round 9
// speedup vs baseline: 1.6806x; 1.1279x over previous
#include <cuda_runtime.h>
#include <cuda_fp16.h>
#include <math.h>
#include <stdint.h>

// ---------------- problem constants ----------------
#define BGPT 4
#define TGPT 1024
#define DGPT 1024
#define HGPT 16
#define HDH  64
#define LGPT 8
#define VGPT 4096
#define MGPT (BGPT*TGPT)   // 4096 tokens
#define FGPT (4*DGPT)      // 4096 ff dim

// weight scratch offsets (elements)
#define SZ_WQ   ((size_t)LGPT*DGPT*DGPT)
#define SZ_W1   ((size_t)LGPT*FGPT*DGPT)
#define SZ_HEAD ((size_t)VGPT*DGPT)
#define O_WQ    ((size_t)0)
#define O_WK    (O_WQ + SZ_WQ)
#define O_WV    (O_WK + SZ_WQ)
#define O_WP    (O_WV + SZ_WQ)
#define O_W1    (O_WP + SZ_WQ)
#define O_W2    (O_W1 + SZ_W1)
#define O_WLG   (O_W2 + SZ_W1)
#define O_WDV   (O_WLG + SZ_HEAD)
#define WTOT    (O_WDV + SZ_HEAD)

// ---------------- scratch (device globals; no allocs allowed) ----------------
__device__ float g_x [MGPT*DGPT];              // residual stream (fp32)
__device__ float g_q [MGPT*DGPT];
__device__ float g_k [MGPT*DGPT];
__device__ float g_v [MGPT*DGPT];
__device__ __half g_ahi[(size_t)MGPT*DGPT];    // activation hi (LN out / attn out)
__device__ __half g_alo[(size_t)MGPT*DGPT];    // activation lo (used by 3-term heads)
__device__ __half g_fhi[(size_t)MGPT*FGPT];    // ff activation hi
__device__ __half g_whi[WTOT];                 // split weights
__device__ __half g_wlo[WTOT];

// ---------------- helpers ----------------
__device__ __forceinline__ void split_f16(float v, __half& h, __half& l)
{
    h = __float2half_rn(v);
    l = __float2half_rn(v - __half2float(h));
}

// ---------------- embedding ----------------
__global__ void embed_kernel(const int* __restrict__ idx,
                             const float* __restrict__ tok,
                             const float* __restrict__ pos,
                             float* __restrict__ x)
{
    int i = blockIdx.x * blockDim.x + threadIdx.x;
    if (i >= MGPT * DGPT) return;
    int row = i / DGPT;
    int d   = i - row * DGPT;
    int t   = row & (TGPT - 1);
    x[i] = tok[(size_t)idx[row] * DGPT + d] + pos[(size_t)t * DGPT + d];
}

// ---------------- fp32 -> fp16 hi/lo split (weights) ----------------
__global__ void __launch_bounds__(256) convsplit_kernel(const float* __restrict__ in,
                                                        __half* __restrict__ hi,
                                                        __half* __restrict__ lo,
                                                        size_t n4)
{
    size_t i = (size_t)blockIdx.x * blockDim.x + threadIdx.x;
    if (i >= n4) return;
    size_t e = i * 4;
    float4 v = *(const float4*)(in + e);
    __half hx, hy, hz, hw, lx, ly, lz, lw;
    split_f16(v.x, hx, lx); split_f16(v.y, hy, ly);
    split_f16(v.z, hz, lz); split_f16(v.w, hw, lw);
    __half2 h01 = __halves2half2(hx, hy);
    __half2 h23 = __halves2half2(hz, hw);
    __half2 l01 = __halves2half2(lx, ly);
    __half2 l23 = __halves2half2(lz, lw);
    uint2 ho, loo;
    ho.x  = *(uint32_t*)&h01; ho.y  = *(uint32_t*)&h23;
    loo.x = *(uint32_t*)&l01; loo.y = *(uint32_t*)&l23;
    *(uint2*)(hi + e) = ho;
    *(uint2*)(lo + e) = loo;
}

// ---------------- layernorm: fp32 in -> fp16 hi/lo out ----------------
__global__ void __launch_bounds__(256) ln_kernel(const float* __restrict__ in,
                                                 __half* __restrict__ ohi,
                                                 __half* __restrict__ olo,
                                                 const float* __restrict__ w,
                                                 const float* __restrict__ b)
{
    int row = blockIdx.x;
    const float* x = in + (size_t)row * DGPT;
    int tid = threadIdx.x;
    __shared__ float red[8];

    float s = 0.f;
    for (int d = tid; d < DGPT; d += 256) s += x[d];
    #pragma unroll
    for (int o = 16; o; o >>= 1) s += __shfl_xor_sync(0xffffffffu, s, o);
    if ((tid & 31) == 0) red[tid >> 5] = s;
    __syncthreads();
    if (tid < 32) {
        float v = (tid < 8) ? red[tid] : 0.f;
        #pragma unroll
        for (int o = 4; o; o >>= 1) v += __shfl_xor_sync(0xffffffffu, v, o);
        if (tid == 0) red[0] = v;
    }
    __syncthreads();
    float mean = red[0] * (1.f / DGPT);

    float q = 0.f;
    for (int d = tid; d < DGPT; d += 256) { float t = x[d] - mean; q += t * t; }
    __syncthreads();
    #pragma unroll
    for (int o = 16; o; o >>= 1) q += __shfl_xor_sync(0xffffffffu, q, o);
    if ((tid & 31) == 0) red[tid >> 5] = q;
    __syncthreads();
    if (tid < 32) {
        float v = (tid < 8) ? red[tid] : 0.f;
        #pragma unroll
        for (int o = 4; o; o >>= 1) v += __shfl_xor_sync(0xffffffffu, v, o);
        if (tid == 0) red[0] = v;
    }
    __syncthreads();
    float rstd = rsqrtf(red[0] * (1.f / DGPT) + 1e-5f);

    for (int d = tid; d < DGPT; d += 256) {
        float v = (x[d] - mean) * rstd * w[d] + b[d];
        __half h, l;
        split_f16(v, h, l);
        ohi[(size_t)row * DGPT + d] = h;
        olo[(size_t)row * DGPT + d] = l;
    }
}

// ---------------- tensor-core GEMM helpers ----------------
__device__ __forceinline__ void ldm4(uint32_t r[4], const __half* p)
{
    uint32_t a = (uint32_t)__cvta_generic_to_shared(p);
    asm volatile("ldmatrix.sync.aligned.m8n8.x4.shared.b16 {%0,%1,%2,%3}, [%4];\n"
                 : "=r"(r[0]), "=r"(r[1]), "=r"(r[2]), "=r"(r[3]) : "r"(a));
}
__device__ __forceinline__ void mma_f32(float c[4], const uint32_t a[4], const uint32_t b[2])
{
    asm volatile(
        "mma.sync.aligned.m16n8k16.row.col.f32.f16.f16.f32 "
        "{%0,%1,%2,%3}, {%4,%5,%6,%7}, {%8,%9}, {%0,%1,%2,%3};\n"
        : "+f"(c[0]), "+f"(c[1]), "+f"(c[2]), "+f"(c[3])
        : "r"(a[0]), "r"(a[1]), "r"(a[2]), "r"(a[3]), "r"(b[0]), "r"(b[1]));
}

// ---------------- GEMM: C[M,N] = A[M,K] @ W[N,K]^T ----------------
// THREE=0: 2-term  C = Ahi*(Whi + Wlo)
// THREE=1: 3-term  C = Ahi*Whi + Ahi*Wlo + Alo*Whi
// MODE: 0 = +bias fp32 out | 1 = +bias, GELU, fp16 hi out | 2 = +bias +res fp32 | 3 = plain fp32
#define BKg 32
#define PK  40
#define SMBUF (128*PK)
#define SMMAT (2*SMBUF)
#define GS2 (3*SMMAT*2)   // 61440 B (2-term: Ah, Bh, Bl)
#define GS3 (4*SMMAT*2)   // 81920 B (3-term: + Al)

template<int MODE, int THREE>
__global__ void __launch_bounds__(256) gemm_tc(
    const __half* __restrict__ Ahi, const __half* __restrict__ Alo,
    const __half* __restrict__ Whi, const __half* __restrict__ Wlo,
    const float* __restrict__ bias, const float* __restrict__ res,
    float* __restrict__ C, __half* __restrict__ Chi,
    int M, int N, int K)
{
    extern __shared__ __align__(16) __half sm[];
    __half* sAh = sm;
    __half* sBh = sm + SMMAT;
    __half* sBl = sm + 2 * SMMAT;
    __half* sAl = sm + 3 * SMMAT;     // only used when THREE

    const int tid  = threadIdx.x;
    const int lane = tid & 31;
    const int wid  = tid >> 5;
    const int wm   = wid >> 2;          // 0..1
    const int wn   = wid & 3;           // 0..3
    const int bm   = blockIdx.y * 128;
    const int bn   = blockIdx.x * 128;

    const int lrow = tid >> 1;
    const int lcol = (tid & 1) << 4;
    const __half* gAh = Ahi + (size_t)(bm + lrow) * K + lcol;
    const __half* gAl = THREE ? (Alo + (size_t)(bm + lrow) * K + lcol) : nullptr;
    const __half* gBh = Whi + (size_t)(bn + lrow) * K + lcol;
    const __half* gBl = Wlo + (size_t)(bn + lrow) * K + lcol;

    const int a_r = wm * 64 + (lane & 15);
    const int a_c = (lane >> 4) * 8;
    const int b_r = wn * 32 + (lane >> 4) * 8 + (lane & 7);
    const int b_c = ((lane >> 3) & 1) * 8;

    float acc[4][4][4];
    #pragma unroll
    for (int mi = 0; mi < 4; mi++)
        #pragma unroll
        for (int ni = 0; ni < 4; ni++)
            #pragma unroll
            for (int r = 0; r < 4; r++) acc[mi][ni][r] = 0.f;

    uint4 rAh0, rAh1, rAl0, rAl1, rBh0, rBh1, rBl0, rBl1;

    const int NS = K / BKg;
    rAh0 = *(const uint4*)(gAh);     rAh1 = *(const uint4*)(gAh + 8);
    rBh0 = *(const uint4*)(gBh);     rBh1 = *(const uint4*)(gBh + 8);
    rBl0 = *(const uint4*)(gBl);     rBl1 = *(const uint4*)(gBl + 8);
    if (THREE) { rAl0 = *(const uint4*)(gAl); rAl1 = *(const uint4*)(gAl + 8); }
    {
        __half* p = sAh + lrow * PK + lcol;
        *(uint4*)p = rAh0; *(uint4*)(p + 8) = rAh1;
        p = sBh + lrow * PK + lcol;
        *(uint4*)p = rBh0; *(uint4*)(p + 8) = rBh1;
        p = sBl + lrow * PK + lcol;
        *(uint4*)p = rBl0; *(uint4*)(p + 8) = rBl1;
        if (THREE) {
            p = sAl + lrow * PK + lcol;
            *(uint4*)p = rAl0; *(uint4*)(p + 8) = rAl1;
        }
    }
    __syncthreads();

    for (int s = 0; s < NS; s++) {
        if (s + 1 < NS) {
            int k0 = (s + 1) * BKg;
            rAh0 = *(const uint4*)(gAh + k0);  rAh1 = *(const uint4*)(gAh + k0 + 8);
            rBh0 = *(const uint4*)(gBh + k0);  rBh1 = *(const uint4*)(gBh + k0 + 8);
            rBl0 = *(const uint4*)(gBl + k0);  rBl1 = *(const uint4*)(gBl + k0 + 8);
            if (THREE) { rAl0 = *(const uint4*)(gAl + k0); rAl1 = *(const uint4*)(gAl + k0 + 8); }
        }

        const int bo = (s & 1) * SMBUF;
        #pragma unroll
        for (int ks = 0; ks < 2; ks++) {
            const int k0 = ks * 16;
            uint32_t afh[4][4];
            #pragma unroll
            for (int mi = 0; mi < 4; mi++)
                ldm4(afh[mi], sAh + bo + (a_r + mi * 16) * PK + k0 + a_c);
            uint32_t bfh[4][2], bfl[4][2];
            #pragma unroll
            for (int np = 0; np < 2; np++) {
                const int off = bo + (b_r + np * 16) * PK + k0 + b_c;
                uint32_t t[4];
                ldm4(t, sBh + off);
                bfh[np * 2][0] = t[0]; bfh[np * 2][1] = t[1];
                bfh[np * 2 + 1][0] = t[2]; bfh[np * 2 + 1][1] = t[3];
                ldm4(t, sBl + off);
                bfl[np * 2][0] = t[0]; bfl[np * 2][1] = t[1];
                bfl[np * 2 + 1][0] = t[2]; bfl[np * 2 + 1][1] = t[3];
            }
            // hi*hi
            #pragma unroll
            for (int mi = 0; mi < 4; mi++)
                #pragma unroll
                for (int ni = 0; ni < 4; ni++)
                    mma_f32(acc[mi][ni], afh[mi], bfh[ni]);
            // hi*lo
            #pragma unroll
            for (int mi = 0; mi < 4; mi++)
                #pragma unroll
                for (int ni = 0; ni < 4; ni++)
                    mma_f32(acc[mi][ni], afh[mi], bfl[ni]);
            // lo*hi (3-term only)
            if (THREE) {
                uint32_t afl[4][4];
                #pragma unroll
                for (int mi = 0; mi < 4; mi++)
                    ldm4(afl[mi], sAl + bo + (a_r + mi * 16) * PK + k0 + a_c);
                #pragma unroll
                for (int mi = 0; mi < 4; mi++)
                    #pragma unroll
                    for (int ni = 0; ni < 4; ni++)
                        mma_f32(acc[mi][ni], afl[mi], bfh[ni]);
            }
        }

        if (s + 1 < NS) {
            const int bo2 = ((s + 1) & 1) * SMBUF;
            __half* p = sAh + bo2 + lrow * PK + lcol;
            *(uint4*)p = rAh0; *(uint4*)(p + 8) = rAh1;
            p = sBh + bo2 + lrow * PK + lcol;
            *(uint4*)p = rBh0; *(uint4*)(p + 8) = rBh1;
            p = sBl + bo2 + lrow * PK + lcol;
            *(uint4*)p = rBl0; *(uint4*)(p + 8) = rBl1;
            if (THREE) {
                p = sAl + bo2 + lrow * PK + lcol;
                *(uint4*)p = rAl0; *(uint4*)(p + 8) = rAl1;
            }
            __syncthreads();
        }
    }

    // epilogue
    const int er = bm + wm * 64 + (lane >> 2);
    const int ec = bn + wn * 32 + (lane & 3) * 2;
    #pragma unroll
    for (int mi = 0; mi < 4; mi++) {
        #pragma unroll
        for (int ni = 0; ni < 4; ni++) {
            const int col = ec + ni * 8;
            #pragma unroll
            for (int h = 0; h < 2; h++) {
                const size_t row = (size_t)(er + mi * 16 + h * 8);
                float v0 = acc[mi][ni][h * 2];
                float v1 = acc[mi][ni][h * 2 + 1];
                if (MODE != 3) { v0 += bias[col]; v1 += bias[col + 1]; }
                if (MODE == 1) {
                    v0 = 0.5f * v0 * (1.f + erff(v0 * 0.70710678118654752f));
                    v1 = 0.5f * v1 * (1.f + erff(v1 * 0.70710678118654752f));
                    *(__half2*)(Chi + row * N + col) =
                        __halves2half2(__float2half_rn(v0), __float2half_rn(v1));
                } else {
                    if (MODE == 2) {
                        v0 += res[row * N + col];
                        v1 += res[row * N + col + 1];
                    }
                    float2 o; o.x = v0; o.y = v1;
                    *(float2*)(C + row * N + col) = o;
                }
            }
        }
    }
}

// ---------------- causal flash attention (fp32, fp16 hi out) ----------
__global__ void __launch_bounds__(256) attn_kernel(const float* __restrict__ q,
                                                   const float* __restrict__ k,
                                                   const float* __restrict__ v,
                                                   __half* __restrict__ yhi)
{
    __shared__ __align__(16) float Qs[64][68];
    __shared__ __align__(16) float Ks[32][68];
    __shared__ __align__(16) float Vs[32][68];
    __shared__ __align__(16) float Ss[64][36];

    int bh = blockIdx.x;
    int b  = bh / HGPT;
    int h  = bh % HGPT;
    int qb = blockIdx.y;
    int tid = threadIdx.x;

    const float* qbase = q + ((size_t)(b * TGPT + qb * 64)) * DGPT + h * HDH;
    const float* kbase = k + ((size_t)(b * TGPT)) * DGPT + h * HDH;
    const float* vbase = v + ((size_t)(b * TGPT)) * DGPT + h * HDH;

    for (int f = tid; f < 1024; f += 256) {
        int r = f >> 4, c4 = (f & 15) * 4;
        *(float4*)&Qs[r][c4] = *(const float4*)(qbase + (size_t)r * DGPT + c4);
    }

    int i  = tid >> 2;
    int cg = tid & 3;
    int d0 = cg * 16;
    int qglob = qb * 64 + i;

    float O[16];
    #pragma unroll
    for (int dd = 0; dd < 16; dd++) O[dd] = 0.f;
    float m_run = -1e30f, l_run = 0.f;

    int nchunks = 2 * qb + 2;
    __syncthreads();

    for (int ch = 0; ch < nchunks; ch++) {
        int j0 = ch * 32;
        for (int f = tid; f < 512; f += 256) {
            int r = f >> 4, c4 = (f & 15) * 4;
            *(float4*)&Ks[r][c4] = *(const float4*)(kbase + (size_t)(j0 + r) * DGPT + c4);
            *(float4*)&Vs[r][c4] = *(const float4*)(vbase + (size_t)(j0 + r) * DGPT + c4);
        }
        __syncthreads();

        float sv[8];
        #pragma unroll
        for (int cc = 0; cc < 8; cc++) sv[cc] = 0.f;
        #pragma unroll 8
        for (int d = 0; d < 64; d++) {
            float qd = Qs[i][d];
            #pragma unroll
            for (int cc = 0; cc < 8; cc++)
                sv[cc] = fmaf(qd, Ks[cg * 8 + cc][d], sv[cc]);
        }
        float mloc = -1e30f;
        #pragma unroll
        for (int cc = 0; cc < 8; cc++) {
            float s = sv[cc] * 0.125f;
            if (j0 + cg * 8 + cc > qglob) s = -1e30f;
            sv[cc] = s;
            mloc = fmaxf(mloc, s);
        }
        mloc = fmaxf(mloc, __shfl_xor_sync(0xffffffffu, mloc, 1));
        mloc = fmaxf(mloc, __shfl_xor_sync(0xffffffffu, mloc, 2));

        float mnew = fmaxf(m_run, mloc);
        float corr = expf(m_run - mnew);
        float psum = 0.f;
        #pragma unroll
        for (int cc = 0; cc < 8; cc++) {
            float p = expf(sv[cc] - mnew);
            Ss[i][cg * 8 + cc] = p;
            psum += p;
        }
        psum += __shfl_xor_sync(0xffffffffu, psum, 1);
        psum += __shfl_xor_sync(0xffffffffu, psum, 2);
        l_run = l_run * corr + psum;
        m_run = mnew;
        #pragma unroll
        for (int dd = 0; dd < 16; dd++) O[dd] *= corr;
        __syncwarp();

        #pragma unroll 4
        for (int c = 0; c < 32; c++) {
            float p = Ss[i][c];
            float4 v0 = *(const float4*)&Vs[c][d0];
            float4 v1 = *(const float4*)&Vs[c][d0 + 4];
            float4 v2 = *(const float4*)&Vs[c][d0 + 8];
            float4 v3 = *(const float4*)&Vs[c][d0 + 12];
            O[0]  = fmaf(p, v0.x, O[0]);  O[1]  = fmaf(p, v0.y, O[1]);
            O[2]  = fmaf(p, v0.z, O[2]);  O[3]  = fmaf(p, v0.w, O[3]);
            O[4]  = fmaf(p, v1.x, O[4]);  O[5]  = fmaf(p, v1.y, O[5]);
            O[6]  = fmaf(p, v1.z, O[6]);  O[7]  = fmaf(p, v1.w, O[7]);
            O[8]  = fmaf(p, v2.x, O[8]);  O[9]  = fmaf(p, v2.y, O[9]);
            O[10] = fmaf(p, v2.z, O[10]); O[11] = fmaf(p, v2.w, O[11]);
            O[12] = fmaf(p, v3.x, O[12]); O[13] = fmaf(p, v3.y, O[13]);
            O[14] = fmaf(p, v3.z, O[14]); O[15] = fmaf(p, v3.w, O[15]);
        }
        __syncthreads();
    }

    float inv = 1.f / l_run;
    size_t base = ((size_t)(b * TGPT + qglob)) * DGPT + h * HDH + d0;
    #pragma unroll
    for (int dd = 0; dd < 16; dd += 2) {
        *(__half2*)(yhi + base + dd) =
            __halves2half2(__float2half_rn(O[dd] * inv), __float2half_rn(O[dd + 1] * inv));
    }
}

// ---------------- launcher ----------------
static inline void convsplit(const float* in, __half* hi, __half* lo, size_t n)
{
    size_t n4 = n / 4;
    convsplit_kernel<<<(unsigned)((n4 + 255) / 256), 256>>>(in, hi, lo, n4);
}

extern "C" void kernel_launch(void* const* d_in, const int* in_sizes, int n_in,
                              void* d_out, int out_size)
{
    const int*   idx    = (const int*)  d_in[0];
    const float* tok    = (const float*)d_in[1];
    const float* pos    = (const float*)d_in[2];
    const float* ln1_w  = (const float*)d_in[3];
    const float* ln1_b  = (const float*)d_in[4];
    const float* Wq     = (const float*)d_in[5];
    const float* bq     = (const float*)d_in[6];
    const float* Wk     = (const float*)d_in[7];
    const float* bk     = (const float*)d_in[8];
    const float* Wv     = (const float*)d_in[9];
    const float* bv     = (const float*)d_in[10];
    const float* Wproj  = (const float*)d_in[11];
    const float* bproj  = (const float*)d_in[12];
    const float* ln2_w  = (const float*)d_in[13];
    const float* ln2_b  = (const float*)d_in[14];
    const float* W1     = (const float*)d_in[15];
    const float* b1     = (const float*)d_in[16];
    const float* W2     = (const float*)d_in[17];
    const float* b2     = (const float*)d_in[18];
    const float* lnf_w  = (const float*)d_in[19];
    const float* lnf_b  = (const float*)d_in[20];
    const float* Wlogit = (const float*)d_in[21];
    const float* Wdev   = (const float*)d_in[22];
    float* out = (float*)d_out;

    float *xp, *qp, *kp, *vp;
    __half *whi, *wlo, *ahi, *alo, *fhi;
    cudaGetSymbolAddress((void**)&xp, g_x);
    cudaGetSymbolAddress((void**)&qp, g_q);
    cudaGetSymbolAddress((void**)&kp, g_k);
    cudaGetSymbolAddress((void**)&vp, g_v);
    cudaGetSymbolAddress((void**)&whi, g_whi);
    cudaGetSymbolAddress((void**)&wlo, g_wlo);
    cudaGetSymbolAddress((void**)&ahi, g_ahi);
    cudaGetSymbolAddress((void**)&alo, g_alo);
    cudaGetSymbolAddress((void**)&fhi, g_fhi);

    cudaFuncSetAttribute((const void*)gemm_tc<0,0>, cudaFuncAttributeMaxDynamicSharedMemorySize, GS2);
    cudaFuncSetAttribute((const void*)gemm_tc<1,0>, cudaFuncAttributeMaxDynamicSharedMemorySize, GS2);
    cudaFuncSetAttribute((const void*)gemm_tc<2,0>, cudaFuncAttributeMaxDynamicSharedMemorySize, GS2);
    cudaFuncSetAttribute((const void*)gemm_tc<3,1>, cudaFuncAttributeMaxDynamicSharedMemorySize, GS3);

    dim3 gD(DGPT / 128, MGPT / 128);
    dim3 gF(FGPT / 128, MGPT / 128);
    dim3 gV(VGPT / 128, MGPT / 128);
    dim3 gA(BGPT * HGPT, TGPT / 64);

    // launch order chosen so the 6th launch is a gemm_tc (ncu -s 5 -c 1)
    embed_kernel<<<(MGPT * DGPT + 255) / 256, 256>>>(idx, tok, pos, xp);     // 1
    convsplit(Wq, whi + O_WQ, wlo + O_WQ, SZ_WQ);                            // 2
    convsplit(Wk, whi + O_WK, wlo + O_WK, SZ_WQ);                            // 3
    convsplit(Wv, whi + O_WV, wlo + O_WV, SZ_WQ);                            // 4
    ln_kernel<<<MGPT, 256>>>(xp, ahi, alo, ln1_w, ln1_b);                    // 5
    gemm_tc<0,0><<<gD, 256, GS2>>>(ahi, nullptr, whi + O_WQ, wlo + O_WQ,     // 6 (profiled)
                                   bq, nullptr, qp, nullptr, MGPT, DGPT, DGPT);
    convsplit(Wproj,  whi + O_WP,  wlo + O_WP,  SZ_WQ);
    convsplit(W1,     whi + O_W1,  wlo + O_W1,  SZ_W1);
    convsplit(W2,     whi + O_W2,  wlo + O_W2,  SZ_W1);
    convsplit(Wlogit, whi + O_WLG, wlo + O_WLG, SZ_HEAD);
    convsplit(Wdev,   whi + O_WDV, wlo + O_WDV, SZ_HEAD);

    for (int l = 0; l < LGPT; l++) {
        size_t oD  = (size_t)l * DGPT * DGPT;
        size_t oF  = (size_t)l * FGPT * DGPT;
        size_t ob  = (size_t)l * DGPT;
        size_t obf = (size_t)l * FGPT;

        if (l > 0) {
            ln_kernel<<<MGPT, 256>>>(xp, ahi, alo, ln1_w + ob, ln1_b + ob);
            gemm_tc<0,0><<<gD, 256, GS2>>>(ahi, nullptr, whi + O_WQ + oD, wlo + O_WQ + oD,
                                           bq + ob, nullptr, qp, nullptr, MGPT, DGPT, DGPT);
        }
        gemm_tc<0,0><<<gD, 256, GS2>>>(ahi, nullptr, whi + O_WK + oD, wlo + O_WK + oD,
                                       bk + ob, nullptr, kp, nullptr, MGPT, DGPT, DGPT);
        gemm_tc<0,0><<<gD, 256, GS2>>>(ahi, nullptr, whi + O_WV + oD, wlo + O_WV + oD,
                                       bv + ob, nullptr, vp, nullptr, MGPT, DGPT, DGPT);
        attn_kernel<<<gA, 256>>>(qp, kp, vp, ahi);
        gemm_tc<2,0><<<gD, 256, GS2>>>(ahi, nullptr, whi + O_WP + oD, wlo + O_WP + oD,
                                       bproj + ob, xp, xp, nullptr, MGPT, DGPT, DGPT);

        ln_kernel<<<MGPT, 256>>>(xp, ahi, alo, ln2_w + ob, ln2_b + ob);
        gemm_tc<1,0><<<gF, 256, GS2>>>(ahi, nullptr, whi + O_W1 + oF, wlo + O_W1 + oF,
                                       b1 + obf, nullptr, nullptr, fhi, MGPT, FGPT, DGPT);
        gemm_tc<2,0><<<gD, 256, GS2>>>(fhi, nullptr, whi + O_W2 + oF, wlo + O_W2 + oF,
                                       b2 + ob, xp, xp, nullptr, MGPT, DGPT, FGPT);
    }

    ln_kernel<<<MGPT, 256>>>(xp, ahi, alo, lnf_w, lnf_b);
    gemm_tc<3,1><<<gV, 256, GS3>>>(ahi, alo, whi + O_WLG, wlo + O_WLG,
                                   nullptr, nullptr, out, nullptr, MGPT, VGPT, DGPT);
    gemm_tc<3,1><<<gV, 256, GS3>>>(ahi, alo, whi + O_WDV, wlo + O_WDV,
                                   nullptr, nullptr, out + (size_t)MGPT * VGPT, nullptr,
                                   MGPT, VGPT, DGPT);
}

// round 10
// speedup vs baseline: 3.6965x; 2.1995x over previous
#include <cuda_runtime.h>
#include <cuda_fp16.h>
#include <math.h>
#include <stdint.h>

// ---------------- problem constants ----------------
#define BGPT 4
#define TGPT 1024
#define DGPT 1024
#define HGPT 16
#define HDH  64
#define LGPT 8
#define VGPT 4096
#define MGPT (BGPT*TGPT)   // 4096 tokens
#define FGPT (4*DGPT)      // 4096 ff dim

// weight scratch offsets (elements)
#define SZ_WQ   ((size_t)LGPT*DGPT*DGPT)
#define SZ_W1   ((size_t)LGPT*FGPT*DGPT)
#define SZ_HEAD ((size_t)VGPT*DGPT)
#define O_WQ    ((size_t)0)
#define O_WK    (O_WQ + SZ_WQ)
#define O_WV    (O_WK + SZ_WQ)
#define O_WP    (O_WV + SZ_WQ)
#define O_W1    (O_WP + SZ_WQ)
#define O_W2    (O_W1 + SZ_W1)
#define O_WLG   (O_W2 + SZ_W1)
#define O_WDV   (O_WLG + SZ_HEAD)
#define WTOT    (O_WDV + SZ_HEAD)

// ---------------- scratch (device globals; no allocs allowed) ----------------
__device__ float g_x [MGPT*DGPT];              // residual stream (fp32)
__device__ float g_q [MGPT*DGPT];              // reused as fp16 hi||lo
__device__ float g_k [MGPT*DGPT];              // reused as fp16 hi||lo
__device__ float g_v [MGPT*DGPT];              // reused as fp16 hi||lo
__device__ __half g_ahi[(size_t)MGPT*DGPT];    // activation hi
__device__ __half g_alo[(size_t)MGPT*DGPT];    // activation lo (heads 3-term)
__device__ __half g_fhi[(size_t)MGPT*FGPT];    // ff activation hi
__device__ __half g_whi[WTOT];                 // split weights
__device__ __half g_wlo[WTOT];

// ---------------- helpers ----------------
__device__ __forceinline__ void split_f16(float v, __half& h, __half& l)
{
    h = __float2half_rn(v);
    l = __float2half_rn(v - __half2float(h));
}

// ---------------- embedding ----------------
__global__ void embed_kernel(const int* __restrict__ idx,
                             const float* __restrict__ tok,
                             const float* __restrict__ pos,
                             float* __restrict__ x)
{
    int i = blockIdx.x * blockDim.x + threadIdx.x;
    if (i >= MGPT * DGPT) return;
    int row = i / DGPT;
    int d   = i - row * DGPT;
    int t   = row & (TGPT - 1);
    x[i] = tok[(size_t)idx[row] * DGPT + d] + pos[(size_t)t * DGPT + d];
}

// ---------------- fp32 -> fp16 hi/lo split (weights) ----------------
__global__ void __launch_bounds__(256) convsplit_kernel(const float* __restrict__ in,
                                                        __half* __restrict__ hi,
                                                        __half* __restrict__ lo,
                                                        size_t n4)
{
    size_t i = (size_t)blockIdx.x * blockDim.x + threadIdx.x;
    if (i >= n4) return;
    size_t e = i * 4;
    float4 v = *(const float4*)(in + e);
    __half hx, hy, hz, hw, lx, ly, lz, lw;
    split_f16(v.x, hx, lx); split_f16(v.y, hy, ly);
    split_f16(v.z, hz, lz); split_f16(v.w, hw, lw);
    __half2 h01 = __halves2half2(hx, hy);
    __half2 h23 = __halves2half2(hz, hw);
    __half2 l01 = __halves2half2(lx, ly);
    __half2 l23 = __halves2half2(lz, lw);
    uint2 ho, loo;
    ho.x  = *(uint32_t*)&h01; ho.y  = *(uint32_t*)&h23;
    loo.x = *(uint32_t*)&l01; loo.y = *(uint32_t*)&l23;
    *(uint2*)(hi + e) = ho;
    *(uint2*)(lo + e) = loo;
}

// ---------------- layernorm: fp32 in -> fp16 hi/lo out ----------------
__global__ void __launch_bounds__(256) ln_kernel(const float* __restrict__ in,
                                                 __half* __restrict__ ohi,
                                                 __half* __restrict__ olo,
                                                 const float* __restrict__ w,
                                                 const float* __restrict__ b)
{
    int row = blockIdx.x;
    const float* x = in + (size_t)row * DGPT;
    int tid = threadIdx.x;
    __shared__ float red[8];

    float s = 0.f;
    for (int d = tid; d < DGPT; d += 256) s += x[d];
    #pragma unroll
    for (int o = 16; o; o >>= 1) s += __shfl_xor_sync(0xffffffffu, s, o);
    if ((tid & 31) == 0) red[tid >> 5] = s;
    __syncthreads();
    if (tid < 32) {
        float v = (tid < 8) ? red[tid] : 0.f;
        #pragma unroll
        for (int o = 4; o; o >>= 1) v += __shfl_xor_sync(0xffffffffu, v, o);
        if (tid == 0) red[0] = v;
    }
    __syncthreads();
    float mean = red[0] * (1.f / DGPT);

    float q = 0.f;
    for (int d = tid; d < DGPT; d += 256) { float t = x[d] - mean; q += t * t; }
    __syncthreads();
    #pragma unroll
    for (int o = 16; o; o >>= 1) q += __shfl_xor_sync(0xffffffffu, q, o);
    if ((tid & 31) == 0) red[tid >> 5] = q;
    __syncthreads();
    if (tid < 32) {
        float v = (tid < 8) ? red[tid] : 0.f;
        #pragma unroll
        for (int o = 4; o; o >>= 1) v += __shfl_xor_sync(0xffffffffu, v, o);
        if (tid == 0) red[0] = v;
    }
    __syncthreads();
    float rstd = rsqrtf(red[0] * (1.f / DGPT) + 1e-5f);

    for (int d = tid; d < DGPT; d += 256) {
        float v = (x[d] - mean) * rstd * w[d] + b[d];
        __half h, l;
        split_f16(v, h, l);
        ohi[(size_t)row * DGPT + d] = h;
        olo[(size_t)row * DGPT + d] = l;
    }
}

// ---------------- tensor-core helpers ----------------
__device__ __forceinline__ void ldm4(uint32_t r[4], const __half* p)
{
    uint32_t a = (uint32_t)__cvta_generic_to_shared(p);
    asm volatile("ldmatrix.sync.aligned.m8n8.x4.shared.b16 {%0,%1,%2,%3}, [%4];\n"
                 : "=r"(r[0]), "=r"(r[1]), "=r"(r[2]), "=r"(r[3]) : "r"(a));
}
__device__ __forceinline__ void mma_f32(float c[4], const uint32_t a[4], const uint32_t b[2])
{
    asm volatile(
        "mma.sync.aligned.m16n8k16.row.col.f32.f16.f16.f32 "
        "{%0,%1,%2,%3}, {%4,%5,%6,%7}, {%8,%9}, {%0,%1,%2,%3};\n"
        : "+f"(c[0]), "+f"(c[1]), "+f"(c[2]), "+f"(c[3])
        : "r"(a[0]), "r"(a[1]), "r"(a[2]), "r"(a[3]), "r"(b[0]), "r"(b[1]));
}

// ---------------- GEMM: C[M,N] = A[M,K] @ W[N,K]^T ----------------
// THREE=0: 2-term  C = Ahi*(Whi + Wlo) | THREE=1: 3-term (+ Alo*Whi)
// MODE: 0 = +bias, fp16 hi/lo out | 1 = +bias, GELU, fp16 hi out
//       2 = +bias +res, fp32 out  | 3 = plain fp32 out
#define BKg 32
#define PK  40
#define SMBUF (128*PK)
#define SMMAT (2*SMBUF)
#define GS2 (3*SMMAT*2)   // 61440 B
#define GS3 (4*SMMAT*2)   // 81920 B

template<int MODE, int THREE>
__global__ void __launch_bounds__(256) gemm_tc(
    const __half* __restrict__ Ahi, const __half* __restrict__ Alo,
    const __half* __restrict__ Whi, const __half* __restrict__ Wlo,
    const float* __restrict__ bias, const float* __restrict__ res,
    float* __restrict__ C, __half* __restrict__ Chi, __half* __restrict__ Clo,
    int M, int N, int K)
{
    extern __shared__ __align__(16) __half sm[];
    __half* sAh = sm;
    __half* sBh = sm + SMMAT;
    __half* sBl = sm + 2 * SMMAT;
    __half* sAl = sm + 3 * SMMAT;

    const int tid  = threadIdx.x;
    const int lane = tid & 31;
    const int wid  = tid >> 5;
    const int wm   = wid >> 2;
    const int wn   = wid & 3;
    const int bm   = blockIdx.y * 128;
    const int bn   = blockIdx.x * 128;

    const int lrow = tid >> 1;
    const int lcol = (tid & 1) << 4;
    const __half* gAh = Ahi + (size_t)(bm + lrow) * K + lcol;
    const __half* gAl = THREE ? (Alo + (size_t)(bm + lrow) * K + lcol) : nullptr;
    const __half* gBh = Whi + (size_t)(bn + lrow) * K + lcol;
    const __half* gBl = Wlo + (size_t)(bn + lrow) * K + lcol;

    const int a_r = wm * 64 + (lane & 15);
    const int a_c = (lane >> 4) * 8;
    const int b_r = wn * 32 + (lane >> 4) * 8 + (lane & 7);
    const int b_c = ((lane >> 3) & 1) * 8;

    float acc[4][4][4];
    #pragma unroll
    for (int mi = 0; mi < 4; mi++)
        #pragma unroll
        for (int ni = 0; ni < 4; ni++)
            #pragma unroll
            for (int r = 0; r < 4; r++) acc[mi][ni][r] = 0.f;

    uint4 rAh0, rAh1, rAl0, rAl1, rBh0, rBh1, rBl0, rBl1;

    const int NS = K / BKg;
    rAh0 = *(const uint4*)(gAh);     rAh1 = *(const uint4*)(gAh + 8);
    rBh0 = *(const uint4*)(gBh);     rBh1 = *(const uint4*)(gBh + 8);
    rBl0 = *(const uint4*)(gBl);     rBl1 = *(const uint4*)(gBl + 8);
    if (THREE) { rAl0 = *(const uint4*)(gAl); rAl1 = *(const uint4*)(gAl + 8); }
    {
        __half* p = sAh + lrow * PK + lcol;
        *(uint4*)p = rAh0; *(uint4*)(p + 8) = rAh1;
        p = sBh + lrow * PK + lcol;
        *(uint4*)p = rBh0; *(uint4*)(p + 8) = rBh1;
        p = sBl + lrow * PK + lcol;
        *(uint4*)p = rBl0; *(uint4*)(p + 8) = rBl1;
        if (THREE) {
            p = sAl + lrow * PK + lcol;
            *(uint4*)p = rAl0; *(uint4*)(p + 8) = rAl1;
        }
    }
    __syncthreads();

    for (int s = 0; s < NS; s++) {
        if (s + 1 < NS) {
            int k0 = (s + 1) * BKg;
            rAh0 = *(const uint4*)(gAh + k0);  rAh1 = *(const uint4*)(gAh + k0 + 8);
            rBh0 = *(const uint4*)(gBh + k0);  rBh1 = *(const uint4*)(gBh + k0 + 8);
            rBl0 = *(const uint4*)(gBl + k0);  rBl1 = *(const uint4*)(gBl + k0 + 8);
            if (THREE) { rAl0 = *(const uint4*)(gAl + k0); rAl1 = *(const uint4*)(gAl + k0 + 8); }
        }

        const int bo = (s & 1) * SMBUF;
        #pragma unroll
        for (int ks = 0; ks < 2; ks++) {
            const int k0 = ks * 16;
            uint32_t afh[4][4];
            #pragma unroll
            for (int mi = 0; mi < 4; mi++)
                ldm4(afh[mi], sAh + bo + (a_r + mi * 16) * PK + k0 + a_c);
            uint32_t bfh[4][2], bfl[4][2];
            #pragma unroll
            for (int np = 0; np < 2; np++) {
                const int off = bo + (b_r + np * 16) * PK + k0 + b_c;
                uint32_t t[4];
                ldm4(t, sBh + off);
                bfh[np * 2][0] = t[0]; bfh[np * 2][1] = t[1];
                bfh[np * 2 + 1][0] = t[2]; bfh[np * 2 + 1][1] = t[3];
                ldm4(t, sBl + off);
                bfl[np * 2][0] = t[0]; bfl[np * 2][1] = t[1];
                bfl[np * 2 + 1][0] = t[2]; bfl[np * 2 + 1][1] = t[3];
            }
            #pragma unroll
            for (int mi = 0; mi < 4; mi++)
                #pragma unroll
                for (int ni = 0; ni < 4; ni++)
                    mma_f32(acc[mi][ni], afh[mi], bfh[ni]);
            #pragma unroll
            for (int mi = 0; mi < 4; mi++)
                #pragma unroll
                for (int ni = 0; ni < 4; ni++)
                    mma_f32(acc[mi][ni], afh[mi], bfl[ni]);
            if (THREE) {
                uint32_t afl[4][4];
                #pragma unroll
                for (int mi = 0; mi < 4; mi++)
                    ldm4(afl[mi], sAl + bo + (a_r + mi * 16) * PK + k0 + a_c);
                #pragma unroll
                for (int mi = 0; mi < 4; mi++)
                    #pragma unroll
                    for (int ni = 0; ni < 4; ni++)
                        mma_f32(acc[mi][ni], afl[mi], bfh[ni]);
            }
        }

        if (s + 1 < NS) {
            const int bo2 = ((s + 1) & 1) * SMBUF;
            __half* p = sAh + bo2 + lrow * PK + lcol;
            *(uint4*)p = rAh0; *(uint4*)(p + 8) = rAh1;
            p = sBh + bo2 + lrow * PK + lcol;
            *(uint4*)p = rBh0; *(uint4*)(p + 8) = rBh1;
            p = sBl + bo2 + lrow * PK + lcol;
            *(uint4*)p = rBl0; *(uint4*)(p + 8) = rBl1;
            if (THREE) {
                p = sAl + bo2 + lrow * PK + lcol;
                *(uint4*)p = rAl0; *(uint4*)(p + 8) = rAl1;
            }
            __syncthreads();
        }
    }

    // epilogue
    const int er = bm + wm * 64 + (lane >> 2);
    const int ec = bn + wn * 32 + (lane & 3) * 2;
    #pragma unroll
    for (int mi = 0; mi < 4; mi++) {
        #pragma unroll
        for (int ni = 0; ni < 4; ni++) {
            const int col = ec + ni * 8;
            #pragma unroll
            for (int h = 0; h < 2; h++) {
                const size_t row = (size_t)(er + mi * 16 + h * 8);
                float v0 = acc[mi][ni][h * 2];
                float v1 = acc[mi][ni][h * 2 + 1];
                if (MODE != 3) { v0 += bias[col]; v1 += bias[col + 1]; }
                if (MODE == 0) {
                    __half h0, l0, h1, l1;
                    split_f16(v0, h0, l0);
                    split_f16(v1, h1, l1);
                    *(__half2*)(Chi + row * N + col) = __halves2half2(h0, h1);
                    *(__half2*)(Clo + row * N + col) = __halves2half2(l0, l1);
                } else if (MODE == 1) {
                    v0 = 0.5f * v0 * (1.f + erff(v0 * 0.70710678118654752f));
                    v1 = 0.5f * v1 * (1.f + erff(v1 * 0.70710678118654752f));
                    *(__half2*)(Chi + row * N + col) =
                        __halves2half2(__float2half_rn(v0), __float2half_rn(v1));
                } else {
                    if (MODE == 2) {
                        v0 += res[row * N + col];
                        v1 += res[row * N + col + 1];
                    }
                    float2 o; o.x = v0; o.y = v1;
                    *(float2*)(C + row * N + col) = o;
                }
            }
        }
    }
}

// ---------------- tensor-core flash attention ----------------
// grid (B*H, T/64), block 128 (4 warps, 16 q-rows each). KV chunks of 64.
// S = Qhi*Khi + Qhi*Klo + Qlo*Khi (fp32); O += P16 * (Vhi + Vlo).
#define ATS 72
#define ATT_SMEM (6*64*ATS*2)   // 55296 B

__global__ void __launch_bounds__(128) attn_mma(
    const __half* __restrict__ qh, const __half* __restrict__ qlp,
    const __half* __restrict__ kh, const __half* __restrict__ klp,
    const __half* __restrict__ vh, const __half* __restrict__ vlp,
    __half* __restrict__ yhi)
{
    extern __shared__ __align__(16) __half sa[];
    __half* sQh = sa;
    __half* sQl = sa + 64 * ATS;
    __half* sKh = sa + 2 * 64 * ATS;
    __half* sKl = sa + 3 * 64 * ATS;
    __half* sVh = sa + 4 * 64 * ATS;    // transposed: [d][kv]
    __half* sVl = sa + 5 * 64 * ATS;

    const int bh = blockIdx.x;
    const int b  = bh / HGPT;
    const int h  = bh % HGPT;
    const int qb = blockIdx.y;
    const int tid  = threadIdx.x;
    const int w    = tid >> 5;
    const int lane = tid & 31;

    const size_t base = (size_t)(b * TGPT) * DGPT + (size_t)h * HDH;

    // load Q tile (64x64, hi+lo)
    for (int f = tid; f < 512; f += 128) {
        int r = f >> 3, c8 = (f & 7) * 8;
        size_t g = base + (size_t)(qb * 64 + r) * DGPT + c8;
        *(uint4*)(sQh + r * ATS + c8) = *(const uint4*)(qh + g);
        *(uint4*)(sQl + r * ATS + c8) = *(const uint4*)(qlp + g);
    }

    float O[8][4];
    #pragma unroll
    for (int t = 0; t < 8; t++)
        #pragma unroll
        for (int r = 0; r < 4; r++) O[t][r] = 0.f;
    float m1 = -1e30f, m2 = -1e30f, l1 = 0.f, l2 = 0.f;

    const int a_row  = w * 16 + (lane & 15);
    const int a_coff = (lane >> 4) * 8;
    const int b_row  = (lane >> 4) * 8 + (lane & 7);
    const int b_coff = ((lane >> 3) & 1) * 8;
    const int rl1 = w * 16 + (lane >> 2);    // local q row (first of pair)
    const int cl0 = 2 * (lane & 3);

    const int nch = qb + 1;
    for (int ch = 0; ch < nch; ch++) {
        const int j0 = ch * 64;
        __syncthreads();    // previous chunk's K/V fully consumed
        for (int f = tid; f < 512; f += 128) {
            int r = f >> 3, c8 = (f & 7) * 8;
            size_t g = base + (size_t)(j0 + r) * DGPT + c8;
            *(uint4*)(sKh + r * ATS + c8) = *(const uint4*)(kh + g);
            *(uint4*)(sKl + r * ATS + c8) = *(const uint4*)(klp + g);
        }
        for (int f = tid; f < 1024; f += 128) {     // V transposed store
            int r = f >> 4, c4 = (f & 15) * 4;
            size_t g = base + (size_t)(j0 + r) * DGPT + c4;
            uint2 hv = *(const uint2*)(vh + g);
            uint2 lv = *(const uint2*)(vlp + g);
            __half2 h01 = *(__half2*)&hv.x, h23 = *(__half2*)&hv.y;
            __half2 l01 = *(__half2*)&lv.x, l23 = *(__half2*)&lv.y;
            sVh[(c4 + 0) * ATS + r] = __low2half(h01);
            sVh[(c4 + 1) * ATS + r] = __high2half(h01);
            sVh[(c4 + 2) * ATS + r] = __low2half(h23);
            sVh[(c4 + 3) * ATS + r] = __high2half(h23);
            sVl[(c4 + 0) * ATS + r] = __low2half(l01);
            sVl[(c4 + 1) * ATS + r] = __high2half(l01);
            sVl[(c4 + 2) * ATS + r] = __low2half(l23);
            sVl[(c4 + 3) * ATS + r] = __high2half(l23);
        }
        __syncthreads();

        float S[8][4];
        #pragma unroll
        for (int t = 0; t < 8; t++)
            #pragma unroll
            for (int r = 0; r < 4; r++) S[t][r] = 0.f;

        #pragma unroll
        for (int ks = 0; ks < 4; ks++) {
            uint32_t aqh[4], aql[4];
            ldm4(aqh, sQh + a_row * ATS + ks * 16 + a_coff);
            ldm4(aql, sQl + a_row * ATS + ks * 16 + a_coff);
            #pragma unroll
            for (int nb = 0; nb < 4; nb++) {
                uint32_t t4[4];
                ldm4(t4, sKh + (nb * 16 + b_row) * ATS + ks * 16 + b_coff);
                uint32_t bh0[2] = { t4[0], t4[1] };
                uint32_t bh1[2] = { t4[2], t4[3] };
                ldm4(t4, sKl + (nb * 16 + b_row) * ATS + ks * 16 + b_coff);
                uint32_t bl0[2] = { t4[0], t4[1] };
                uint32_t bl1[2] = { t4[2], t4[3] };
                mma_f32(S[2 * nb],     aqh, bh0);
                mma_f32(S[2 * nb + 1], aqh, bh1);
                mma_f32(S[2 * nb],     aqh, bl0);
                mma_f32(S[2 * nb + 1], aqh, bl1);
                mma_f32(S[2 * nb],     aql, bh0);
                mma_f32(S[2 * nb + 1], aql, bh1);
            }
        }

        const bool diag = (ch == qb);
        #pragma unroll
        for (int t = 0; t < 8; t++) {
            S[t][0] *= 0.125f; S[t][1] *= 0.125f;
            S[t][2] *= 0.125f; S[t][3] *= 0.125f;
            if (diag) {
                int c0 = t * 8 + cl0, c1 = c0 + 1;
                if (c0 > rl1)     S[t][0] = -1e30f;
                if (c1 > rl1)     S[t][1] = -1e30f;
                if (c0 > rl1 + 8) S[t][2] = -1e30f;
                if (c1 > rl1 + 8) S[t][3] = -1e30f;
            }
        }

        float mx1 = -1e30f, mx2 = -1e30f;
        #pragma unroll
        for (int t = 0; t < 8; t++) {
            mx1 = fmaxf(mx1, fmaxf(S[t][0], S[t][1]));
            mx2 = fmaxf(mx2, fmaxf(S[t][2], S[t][3]));
        }
        mx1 = fmaxf(mx1, __shfl_xor_sync(0xffffffffu, mx1, 1));
        mx1 = fmaxf(mx1, __shfl_xor_sync(0xffffffffu, mx1, 2));
        mx2 = fmaxf(mx2, __shfl_xor_sync(0xffffffffu, mx2, 1));
        mx2 = fmaxf(mx2, __shfl_xor_sync(0xffffffffu, mx2, 2));

        float mn1 = fmaxf(m1, mx1), mn2 = fmaxf(m2, mx2);
        float cr1 = __expf(m1 - mn1), cr2 = __expf(m2 - mn2);
        m1 = mn1; m2 = mn2;

        float s1 = 0.f, s2 = 0.f;
        uint32_t Pf[4][4];
        #pragma unroll
        for (int t = 0; t < 8; t++) {
            float p0 = __expf(S[t][0] - mn1);
            float p1 = __expf(S[t][1] - mn1);
            float p2 = __expf(S[t][2] - mn2);
            float p3 = __expf(S[t][3] - mn2);
            s1 += p0 + p1; s2 += p2 + p3;
            __half2 ph01 = __halves2half2(__float2half_rn(p0), __float2half_rn(p1));
            __half2 ph23 = __halves2half2(__float2half_rn(p2), __float2half_rn(p3));
            const int kt = t >> 1, hf = (t & 1) * 2;
            Pf[kt][hf + 0] = *(uint32_t*)&ph01;
            Pf[kt][hf + 1] = *(uint32_t*)&ph23;
        }
        s1 += __shfl_xor_sync(0xffffffffu, s1, 1);
        s1 += __shfl_xor_sync(0xffffffffu, s1, 2);
        s2 += __shfl_xor_sync(0xffffffffu, s2, 1);
        s2 += __shfl_xor_sync(0xffffffffu, s2, 2);
        l1 = l1 * cr1 + s1;
        l2 = l2 * cr2 + s2;
        #pragma unroll
        for (int t = 0; t < 8; t++) {
            O[t][0] *= cr1; O[t][1] *= cr1;
            O[t][2] *= cr2; O[t][3] *= cr2;
        }

        #pragma unroll
        for (int kt = 0; kt < 4; kt++) {
            #pragma unroll
            for (int nb = 0; nb < 4; nb++) {
                uint32_t t4[4];
                ldm4(t4, sVh + (nb * 16 + b_row) * ATS + kt * 16 + b_coff);
                uint32_t bv0[2] = { t4[0], t4[1] };
                uint32_t bv1[2] = { t4[2], t4[3] };
                mma_f32(O[2 * nb],     Pf[kt], bv0);
                mma_f32(O[2 * nb + 1], Pf[kt], bv1);
                ldm4(t4, sVl + (nb * 16 + b_row) * ATS + kt * 16 + b_coff);
                uint32_t bw0[2] = { t4[0], t4[1] };
                uint32_t bw1[2] = { t4[2], t4[3] };
                mma_f32(O[2 * nb],     Pf[kt], bw0);
                mma_f32(O[2 * nb + 1], Pf[kt], bw1);
            }
        }
    }

    // epilogue: normalize + store fp16 hi
    const float inv1 = 1.f / l1, inv2 = 1.f / l2;
    const size_t row1 = base + (size_t)(qb * 64 + rl1) * DGPT;
    const size_t row2 = base + (size_t)(qb * 64 + rl1 + 8) * DGPT;
    #pragma unroll
    for (int t = 0; t < 8; t++) {
        const int col = t * 8 + cl0;
        *(__half2*)(yhi + row1 + col) =
            __halves2half2(__float2half_rn(O[t][0] * inv1), __float2half_rn(O[t][1] * inv1));
        *(__half2*)(yhi + row2 + col) =
            __halves2half2(__float2half_rn(O[t][2] * inv2), __float2half_rn(O[t][3] * inv2));
    }
}

// ---------------- launcher ----------------
static inline void convsplit(const float* in, __half* hi, __half* lo, size_t n)
{
    size_t n4 = n / 4;
    convsplit_kernel<<<(unsigned)((n4 + 255) / 256), 256>>>(in, hi, lo, n4);
}

extern "C" void kernel_launch(void* const* d_in, const int* in_sizes, int n_in,
                              void* d_out, int out_size)
{
    const int*   idx    = (const int*)  d_in[0];
    const float* tok    = (const float*)d_in[1];
    const float* pos    = (const float*)d_in[2];
    const float* ln1_w  = (const float*)d_in[3];
    const float* ln1_b  = (const float*)d_in[4];
    const float* Wq     = (const float*)d_in[5];
    const float* bq     = (const float*)d_in[6];
    const float* Wk     = (const float*)d_in[7];
    const float* bk     = (const float*)d_in[8];
    const float* Wv     = (const float*)d_in[9];
    const float* bv     = (const float*)d_in[10];
    const float* Wproj  = (const float*)d_in[11];
    const float* bproj  = (const float*)d_in[12];
    const float* ln2_w  = (const float*)d_in[13];
    const float* ln2_b  = (const float*)d_in[14];
    const float* W1     = (const float*)d_in[15];
    const float* b1     = (const float*)d_in[16];
    const float* W2     = (const float*)d_in[17];
    const float* b2     = (const float*)d_in[18];
    const float* lnf_w  = (const float*)d_in[19];
    const float* lnf_b  = (const float*)d_in[20];
    const float* Wlogit = (const float*)d_in[21];
    const float* Wdev   = (const float*)d_in[22];
    float* out = (float*)d_out;

    float *xp, *qp, *kp, *vp;
    __half *whi, *wlo, *ahi, *alo, *fhi;
    cudaGetSymbolAddress((void**)&xp, g_x);
    cudaGetSymbolAddress((void**)&qp, g_q);
    cudaGetSymbolAddress((void**)&kp, g_k);
    cudaGetSymbolAddress((void**)&vp, g_v);
    cudaGetSymbolAddress((void**)&whi, g_whi);
    cudaGetSymbolAddress((void**)&wlo, g_wlo);
    cudaGetSymbolAddress((void**)&ahi, g_ahi);
    cudaGetSymbolAddress((void**)&alo, g_alo);
    cudaGetSymbolAddress((void**)&fhi, g_fhi);

    __half* qhi = (__half*)qp;  __half* qlo = qhi + (size_t)MGPT * DGPT;
    __half* khi = (__half*)kp;  __half* klo = khi + (size_t)MGPT * DGPT;
    __half* vhi = (__half*)vp;  __half* vlo = vhi + (size_t)MGPT * DGPT;

    cudaFuncSetAttribute((const void*)gemm_tc<0,0>, cudaFuncAttributeMaxDynamicSharedMemorySize, GS2);
    cudaFuncSetAttribute((const void*)gemm_tc<1,0>, cudaFuncAttributeMaxDynamicSharedMemorySize, GS2);
    cudaFuncSetAttribute((const void*)gemm_tc<2,0>, cudaFuncAttributeMaxDynamicSharedMemorySize, GS2);
    cudaFuncSetAttribute((const void*)gemm_tc<3,1>, cudaFuncAttributeMaxDynamicSharedMemorySize, GS3);
    cudaFuncSetAttribute((const void*)attn_mma,     cudaFuncAttributeMaxDynamicSharedMemorySize, ATT_SMEM);

    convsplit(Wq,     whi + O_WQ,  wlo + O_WQ,  SZ_WQ);
    convsplit(Wk,     whi + O_WK,  wlo + O_WK,  SZ_WQ);
    convsplit(Wv,     whi + O_WV,  wlo + O_WV,  SZ_WQ);
    convsplit(Wproj,  whi + O_WP,  wlo + O_WP,  SZ_WQ);
    convsplit(W1,     whi + O_W1,  wlo + O_W1,  SZ_W1);
    convsplit(W2,     whi + O_W2,  wlo + O_W2,  SZ_W1);
    convsplit(Wlogit, whi + O_WLG, wlo + O_WLG, SZ_HEAD);
    convsplit(Wdev,   whi + O_WDV, wlo + O_WDV, SZ_HEAD);

    dim3 gD(DGPT / 128, MGPT / 128);
    dim3 gF(FGPT / 128, MGPT / 128);
    dim3 gV(VGPT / 128, MGPT / 128);
    dim3 gA(BGPT * HGPT, TGPT / 64);

    embed_kernel<<<(MGPT * DGPT + 255) / 256, 256>>>(idx, tok, pos, xp);

    for (int l = 0; l < LGPT; l++) {
        size_t oD  = (size_t)l * DGPT * DGPT;
        size_t oF  = (size_t)l * FGPT * DGPT;
        size_t ob  = (size_t)l * DGPT;
        size_t obf = (size_t)l * FGPT;

        ln_kernel<<<MGPT, 256>>>(xp, ahi, alo, ln1_w + ob, ln1_b + ob);
        gemm_tc<0,0><<<gD, 256, GS2>>>(ahi, nullptr, whi + O_WQ + oD, wlo + O_WQ + oD,
                                       bq + ob, nullptr, nullptr, qhi, qlo, MGPT, DGPT, DGPT);
        gemm_tc<0,0><<<gD, 256, GS2>>>(ahi, nullptr, whi + O_WK + oD, wlo + O_WK + oD,
                                       bk + ob, nullptr, nullptr, khi, klo, MGPT, DGPT, DGPT);
        gemm_tc<0,0><<<gD, 256, GS2>>>(ahi, nullptr, whi + O_WV + oD, wlo + O_WV + oD,
                                       bv + ob, nullptr, nullptr, vhi, vlo, MGPT, DGPT, DGPT);
        attn_mma<<<gA, 128, ATT_SMEM>>>(qhi, qlo, khi, klo, vhi, vlo, ahi);
        gemm_tc<2,0><<<gD, 256, GS2>>>(ahi, nullptr, whi + O_WP + oD, wlo + O_WP + oD,
                                       bproj + ob, xp, xp, nullptr, nullptr, MGPT, DGPT, DGPT);

        ln_kernel<<<MGPT, 256>>>(xp, ahi, alo, ln2_w + ob, ln2_b + ob);
        gemm_tc<1,0><<<gF, 256, GS2>>>(ahi, nullptr, whi + O_W1 + oF, wlo + O_W1 + oF,
                                       b1 + obf, nullptr, nullptr, fhi, nullptr, MGPT, FGPT, DGPT);
        gemm_tc<2,0><<<gD, 256, GS2>>>(fhi, nullptr, whi + O_W2 + oF, wlo + O_W2 + oF,
                                       b2 + ob, xp, xp, nullptr, nullptr, MGPT, DGPT, FGPT);
    }

    ln_kernel<<<MGPT, 256>>>(xp, ahi, alo, lnf_w, lnf_b);
    gemm_tc<3,1><<<gV, 256, GS3>>>(ahi, alo, whi + O_WLG, wlo + O_WLG,
                                   nullptr, nullptr, out, nullptr, nullptr, MGPT, VGPT, DGPT);
    gemm_tc<3,1><<<gV, 256, GS3>>>(ahi, alo, whi + O_WDV, wlo + O_WDV,
                                   nullptr, nullptr, out + (size_t)MGPT * VGPT, nullptr, nullptr,
                                   MGPT, VGPT, DGPT);
}

// round 11
// speedup vs baseline: 5.7595x; 1.5581x over previous
#include <cuda_runtime.h>
#include <cuda_fp16.h>
#include <math.h>
#include <stdint.h>

// ---------------- problem constants ----------------
#define BGPT 4
#define TGPT 1024
#define DGPT 1024
#define HGPT 16
#define HDH  64
#define LGPT 8
#define VGPT 4096
#define MGPT (BGPT*TGPT)   // 4096 tokens
#define FGPT (4*DGPT)      // 4096 ff dim

// weight scratch offsets (elements)
#define SZ_WQ   ((size_t)LGPT*DGPT*DGPT)
#define SZ_W1   ((size_t)LGPT*FGPT*DGPT)
#define SZ_HEAD ((size_t)VGPT*DGPT)
#define O_WQ    ((size_t)0)
#define O_WK    (O_WQ + SZ_WQ)
#define O_WV    (O_WK + SZ_WQ)
#define O_WP    (O_WV + SZ_WQ)
#define O_W1    (O_WP + SZ_WQ)
#define O_W2    (O_W1 + SZ_W1)
#define O_WLG   (O_W2 + SZ_W1)
#define O_WDV   (O_WLG + SZ_HEAD)
#define WTOT    (O_WDV + SZ_HEAD)

// ---------------- scratch (device globals; no allocs allowed) ----------------
__device__ float g_x [MGPT*DGPT];              // residual stream (fp32)
__device__ float g_q [MGPT*DGPT];              // reused as fp16 hi||lo
__device__ float g_k [MGPT*DGPT];              // reused as fp16 hi||lo
__device__ float g_v [MGPT*DGPT];              // reused as fp16 hi||lo
__device__ __half g_ahi[(size_t)MGPT*DGPT];    // activation hi
__device__ __half g_alo[(size_t)MGPT*DGPT];    // activation lo (heads 3-term)
__device__ __half g_fhi[(size_t)MGPT*FGPT];    // ff activation hi
__device__ __half g_whi[WTOT];                 // split weights
__device__ __half g_wlo[WTOT];                 // weight lo (heads only now)

// ---------------- helpers ----------------
__device__ __forceinline__ void split_f16(float v, __half& h, __half& l)
{
    h = __float2half_rn(v);
    l = __float2half_rn(v - __half2float(h));
}

// ---------------- embedding ----------------
__global__ void embed_kernel(const int* __restrict__ idx,
                             const float* __restrict__ tok,
                             const float* __restrict__ pos,
                             float* __restrict__ x)
{
    int i = blockIdx.x * blockDim.x + threadIdx.x;
    if (i >= MGPT * DGPT) return;
    int row = i / DGPT;
    int d   = i - row * DGPT;
    int t   = row & (TGPT - 1);
    x[i] = tok[(size_t)idx[row] * DGPT + d] + pos[(size_t)t * DGPT + d];
}

// ---------------- fp32 -> fp16 hi/lo split (weights) ----------------
__global__ void __launch_bounds__(256) convsplit_kernel(const float* __restrict__ in,
                                                        __half* __restrict__ hi,
                                                        __half* __restrict__ lo,
                                                        size_t n4)
{
    size_t i = (size_t)blockIdx.x * blockDim.x + threadIdx.x;
    if (i >= n4) return;
    size_t e = i * 4;
    float4 v = *(const float4*)(in + e);
    __half hx, hy, hz, hw, lx, ly, lz, lw;
    split_f16(v.x, hx, lx); split_f16(v.y, hy, ly);
    split_f16(v.z, hz, lz); split_f16(v.w, hw, lw);
    __half2 h01 = __halves2half2(hx, hy);
    __half2 h23 = __halves2half2(hz, hw);
    __half2 l01 = __halves2half2(lx, ly);
    __half2 l23 = __halves2half2(lz, lw);
    uint2 ho, loo;
    ho.x  = *(uint32_t*)&h01; ho.y  = *(uint32_t*)&h23;
    loo.x = *(uint32_t*)&l01; loo.y = *(uint32_t*)&l23;
    *(uint2*)(hi + e) = ho;
    *(uint2*)(lo + e) = loo;
}

// ---------------- layernorm: fp32 in -> fp16 hi/lo out ----------------
__global__ void __launch_bounds__(256) ln_kernel(const float* __restrict__ in,
                                                 __half* __restrict__ ohi,
                                                 __half* __restrict__ olo,
                                                 const float* __restrict__ w,
                                                 const float* __restrict__ b)
{
    int row = blockIdx.x;
    const float* x = in + (size_t)row * DGPT;
    int tid = threadIdx.x;
    __shared__ float red[8];

    float s = 0.f;
    for (int d = tid; d < DGPT; d += 256) s += x[d];
    #pragma unroll
    for (int o = 16; o; o >>= 1) s += __shfl_xor_sync(0xffffffffu, s, o);
    if ((tid & 31) == 0) red[tid >> 5] = s;
    __syncthreads();
    if (tid < 32) {
        float v = (tid < 8) ? red[tid] : 0.f;
        #pragma unroll
        for (int o = 4; o; o >>= 1) v += __shfl_xor_sync(0xffffffffu, v, o);
        if (tid == 0) red[0] = v;
    }
    __syncthreads();
    float mean = red[0] * (1.f / DGPT);

    float q = 0.f;
    for (int d = tid; d < DGPT; d += 256) { float t = x[d] - mean; q += t * t; }
    __syncthreads();
    #pragma unroll
    for (int o = 16; o; o >>= 1) q += __shfl_xor_sync(0xffffffffu, q, o);
    if ((tid & 31) == 0) red[tid >> 5] = q;
    __syncthreads();
    if (tid < 32) {
        float v = (tid < 8) ? red[tid] : 0.f;
        #pragma unroll
        for (int o = 4; o; o >>= 1) v += __shfl_xor_sync(0xffffffffu, v, o);
        if (tid == 0) red[0] = v;
    }
    __syncthreads();
    float rstd = rsqrtf(red[0] * (1.f / DGPT) + 1e-5f);

    for (int d = tid; d < DGPT; d += 256) {
        float v = (x[d] - mean) * rstd * w[d] + b[d];
        __half h, l;
        split_f16(v, h, l);
        ohi[(size_t)row * DGPT + d] = h;
        olo[(size_t)row * DGPT + d] = l;
    }
}

// ---------------- tensor-core helpers ----------------
__device__ __forceinline__ void ldm4(uint32_t r[4], const __half* p)
{
    uint32_t a = (uint32_t)__cvta_generic_to_shared(p);
    asm volatile("ldmatrix.sync.aligned.m8n8.x4.shared.b16 {%0,%1,%2,%3}, [%4];\n"
                 : "=r"(r[0]), "=r"(r[1]), "=r"(r[2]), "=r"(r[3]) : "r"(a));
}
__device__ __forceinline__ void mma_f32(float c[4], const uint32_t a[4], const uint32_t b[2])
{
    asm volatile(
        "mma.sync.aligned.m16n8k16.row.col.f32.f16.f16.f32 "
        "{%0,%1,%2,%3}, {%4,%5,%6,%7}, {%8,%9}, {%0,%1,%2,%3};\n"
        : "+f"(c[0]), "+f"(c[1]), "+f"(c[2]), "+f"(c[3])
        : "r"(a[0]), "r"(a[1]), "r"(a[2]), "r"(a[3]), "r"(b[0]), "r"(b[1]));
}

// ---------------- GEMM: C[M,N] = A[M,K] @ W[N,K]^T ----------------
// TERMS=1: C = Ahi*Whi | TERMS=3: C = Ahi*Whi + Ahi*Wlo + Alo*Whi (heads)
// MODE: 0 = +bias, fp16 hi/lo out | 1 = +bias, GELU, fp16 hi out
//       2 = +bias +res, fp32 out  | 3 = plain fp32 out
#define BKg 32
#define PK  40
#define SMBUF (128*PK)
#define SMMAT (2*SMBUF)
#define GS1 (2*SMMAT*2)   // 40960 B (1-term: Ah, Bh)
#define GS3 (4*SMMAT*2)   // 81920 B (3-term: + Bl, Al)

template<int MODE, int TERMS>
__global__ void __launch_bounds__(256) gemm_tc(
    const __half* __restrict__ Ahi, const __half* __restrict__ Alo,
    const __half* __restrict__ Whi, const __half* __restrict__ Wlo,
    const float* __restrict__ bias, const float* __restrict__ res,
    float* __restrict__ C, __half* __restrict__ Chi, __half* __restrict__ Clo,
    int M, int N, int K)
{
    extern __shared__ __align__(16) __half sm[];
    __half* sAh = sm;
    __half* sBh = sm + SMMAT;
    __half* sBl = sm + 2 * SMMAT;   // TERMS==3 only
    __half* sAl = sm + 3 * SMMAT;   // TERMS==3 only

    const int tid  = threadIdx.x;
    const int lane = tid & 31;
    const int wid  = tid >> 5;
    const int wm   = wid >> 2;
    const int wn   = wid & 3;
    const int bm   = blockIdx.y * 128;
    const int bn   = blockIdx.x * 128;

    const int lrow = tid >> 1;
    const int lcol = (tid & 1) << 4;
    const __half* gAh = Ahi + (size_t)(bm + lrow) * K + lcol;
    const __half* gAl = (TERMS == 3) ? (Alo + (size_t)(bm + lrow) * K + lcol) : nullptr;
    const __half* gBh = Whi + (size_t)(bn + lrow) * K + lcol;
    const __half* gBl = (TERMS == 3) ? (Wlo + (size_t)(bn + lrow) * K + lcol) : nullptr;

    const int a_r = wm * 64 + (lane & 15);
    const int a_c = (lane >> 4) * 8;
    const int b_r = wn * 32 + (lane >> 4) * 8 + (lane & 7);
    const int b_c = ((lane >> 3) & 1) * 8;

    float acc[4][4][4];
    #pragma unroll
    for (int mi = 0; mi < 4; mi++)
        #pragma unroll
        for (int ni = 0; ni < 4; ni++)
            #pragma unroll
            for (int r = 0; r < 4; r++) acc[mi][ni][r] = 0.f;

    uint4 rAh0, rAh1, rAl0, rAl1, rBh0, rBh1, rBl0, rBl1;

    const int NS = K / BKg;
    rAh0 = *(const uint4*)(gAh);     rAh1 = *(const uint4*)(gAh + 8);
    rBh0 = *(const uint4*)(gBh);     rBh1 = *(const uint4*)(gBh + 8);
    if (TERMS == 3) {
        rBl0 = *(const uint4*)(gBl); rBl1 = *(const uint4*)(gBl + 8);
        rAl0 = *(const uint4*)(gAl); rAl1 = *(const uint4*)(gAl + 8);
    }
    {
        __half* p = sAh + lrow * PK + lcol;
        *(uint4*)p = rAh0; *(uint4*)(p + 8) = rAh1;
        p = sBh + lrow * PK + lcol;
        *(uint4*)p = rBh0; *(uint4*)(p + 8) = rBh1;
        if (TERMS == 3) {
            p = sBl + lrow * PK + lcol;
            *(uint4*)p = rBl0; *(uint4*)(p + 8) = rBl1;
            p = sAl + lrow * PK + lcol;
            *(uint4*)p = rAl0; *(uint4*)(p + 8) = rAl1;
        }
    }
    __syncthreads();

    for (int s = 0; s < NS; s++) {
        if (s + 1 < NS) {
            int k0 = (s + 1) * BKg;
            rAh0 = *(const uint4*)(gAh + k0);  rAh1 = *(const uint4*)(gAh + k0 + 8);
            rBh0 = *(const uint4*)(gBh + k0);  rBh1 = *(const uint4*)(gBh + k0 + 8);
            if (TERMS == 3) {
                rBl0 = *(const uint4*)(gBl + k0); rBl1 = *(const uint4*)(gBl + k0 + 8);
                rAl0 = *(const uint4*)(gAl + k0); rAl1 = *(const uint4*)(gAl + k0 + 8);
            }
        }

        const int bo = (s & 1) * SMBUF;
        #pragma unroll
        for (int ks = 0; ks < 2; ks++) {
            const int k0 = ks * 16;
            uint32_t afh[4][4];
            #pragma unroll
            for (int mi = 0; mi < 4; mi++)
                ldm4(afh[mi], sAh + bo + (a_r + mi * 16) * PK + k0 + a_c);
            uint32_t bfh[4][2];
            #pragma unroll
            for (int np = 0; np < 2; np++) {
                uint32_t t[4];
                ldm4(t, sBh + bo + (b_r + np * 16) * PK + k0 + b_c);
                bfh[np * 2][0] = t[0]; bfh[np * 2][1] = t[1];
                bfh[np * 2 + 1][0] = t[2]; bfh[np * 2 + 1][1] = t[3];
            }
            #pragma unroll
            for (int mi = 0; mi < 4; mi++)
                #pragma unroll
                for (int ni = 0; ni < 4; ni++)
                    mma_f32(acc[mi][ni], afh[mi], bfh[ni]);
            if (TERMS == 3) {
                uint32_t bfl[4][2];
                #pragma unroll
                for (int np = 0; np < 2; np++) {
                    uint32_t t[4];
                    ldm4(t, sBl + bo + (b_r + np * 16) * PK + k0 + b_c);
                    bfl[np * 2][0] = t[0]; bfl[np * 2][1] = t[1];
                    bfl[np * 2 + 1][0] = t[2]; bfl[np * 2 + 1][1] = t[3];
                }
                #pragma unroll
                for (int mi = 0; mi < 4; mi++)
                    #pragma unroll
                    for (int ni = 0; ni < 4; ni++)
                        mma_f32(acc[mi][ni], afh[mi], bfl[ni]);
                uint32_t afl[4][4];
                #pragma unroll
                for (int mi = 0; mi < 4; mi++)
                    ldm4(afl[mi], sAl + bo + (a_r + mi * 16) * PK + k0 + a_c);
                #pragma unroll
                for (int mi = 0; mi < 4; mi++)
                    #pragma unroll
                    for (int ni = 0; ni < 4; ni++)
                        mma_f32(acc[mi][ni], afl[mi], bfh[ni]);
            }
        }

        if (s + 1 < NS) {
            const int bo2 = ((s + 1) & 1) * SMBUF;
            __half* p = sAh + bo2 + lrow * PK + lcol;
            *(uint4*)p = rAh0; *(uint4*)(p + 8) = rAh1;
            p = sBh + bo2 + lrow * PK + lcol;
            *(uint4*)p = rBh0; *(uint4*)(p + 8) = rBh1;
            if (TERMS == 3) {
                p = sBl + bo2 + lrow * PK + lcol;
                *(uint4*)p = rBl0; *(uint4*)(p + 8) = rBl1;
                p = sAl + bo2 + lrow * PK + lcol;
                *(uint4*)p = rAl0; *(uint4*)(p + 8) = rAl1;
            }
            __syncthreads();
        }
    }

    // epilogue
    const int er = bm + wm * 64 + (lane >> 2);
    const int ec = bn + wn * 32 + (lane & 3) * 2;
    #pragma unroll
    for (int mi = 0; mi < 4; mi++) {
        #pragma unroll
        for (int ni = 0; ni < 4; ni++) {
            const int col = ec + ni * 8;
            #pragma unroll
            for (int h = 0; h < 2; h++) {
                const size_t row = (size_t)(er + mi * 16 + h * 8);
                float v0 = acc[mi][ni][h * 2];
                float v1 = acc[mi][ni][h * 2 + 1];
                if (MODE != 3) { v0 += bias[col]; v1 += bias[col + 1]; }
                if (MODE == 0) {
                    __half h0, l0, h1, l1;
                    split_f16(v0, h0, l0);
                    split_f16(v1, h1, l1);
                    *(__half2*)(Chi + row * N + col) = __halves2half2(h0, h1);
                    *(__half2*)(Clo + row * N + col) = __halves2half2(l0, l1);
                } else if (MODE == 1) {
                    v0 = 0.5f * v0 * (1.f + erff(v0 * 0.70710678118654752f));
                    v1 = 0.5f * v1 * (1.f + erff(v1 * 0.70710678118654752f));
                    *(__half2*)(Chi + row * N + col) =
                        __halves2half2(__float2half_rn(v0), __float2half_rn(v1));
                } else {
                    if (MODE == 2) {
                        v0 += res[row * N + col];
                        v1 += res[row * N + col + 1];
                    }
                    float2 o; o.x = v0; o.y = v1;
                    *(float2*)(C + row * N + col) = o;
                }
            }
        }
    }
}

// ---------------- tensor-core flash attention ----------------
// grid (B*H, T/64), block 128 (4 warps, 16 q-rows each). KV chunks of 64.
// S = Qhi*Khi + Qhi*Klo + Qlo*Khi (fp32); O += P16 * (Vhi + Vlo).
#define ATS 72
#define ATT_SMEM (6*64*ATS*2)   // 55296 B

__global__ void __launch_bounds__(128) attn_mma(
    const __half* __restrict__ qh, const __half* __restrict__ qlp,
    const __half* __restrict__ kh, const __half* __restrict__ klp,
    const __half* __restrict__ vh, const __half* __restrict__ vlp,
    __half* __restrict__ yhi)
{
    extern __shared__ __align__(16) __half sa[];
    __half* sQh = sa;
    __half* sQl = sa + 64 * ATS;
    __half* sKh = sa + 2 * 64 * ATS;
    __half* sKl = sa + 3 * 64 * ATS;
    __half* sVh = sa + 4 * 64 * ATS;    // transposed: [d][kv]
    __half* sVl = sa + 5 * 64 * ATS;

    const int bh = blockIdx.x;
    const int b  = bh / HGPT;
    const int h  = bh % HGPT;
    const int qb = blockIdx.y;
    const int tid  = threadIdx.x;
    const int w    = tid >> 5;
    const int lane = tid & 31;

    const size_t base = (size_t)(b * TGPT) * DGPT + (size_t)h * HDH;

    // load Q tile (64x64, hi+lo)
    for (int f = tid; f < 512; f += 128) {
        int r = f >> 3, c8 = (f & 7) * 8;
        size_t g = base + (size_t)(qb * 64 + r) * DGPT + c8;
        *(uint4*)(sQh + r * ATS + c8) = *(const uint4*)(qh + g);
        *(uint4*)(sQl + r * ATS + c8) = *(const uint4*)(qlp + g);
    }

    float O[8][4];
    #pragma unroll
    for (int t = 0; t < 8; t++)
        #pragma unroll
        for (int r = 0; r < 4; r++) O[t][r] = 0.f;
    float m1 = -1e30f, m2 = -1e30f, l1 = 0.f, l2 = 0.f;

    const int a_row  = w * 16 + (lane & 15);
    const int a_coff = (lane >> 4) * 8;
    const int b_row  = (lane >> 4) * 8 + (lane & 7);
    const int b_coff = ((lane >> 3) & 1) * 8;
    const int rl1 = w * 16 + (lane >> 2);
    const int cl0 = 2 * (lane & 3);

    const int nch = qb + 1;
    for (int ch = 0; ch < nch; ch++) {
        const int j0 = ch * 64;
        __syncthreads();
        for (int f = tid; f < 512; f += 128) {
            int r = f >> 3, c8 = (f & 7) * 8;
            size_t g = base + (size_t)(j0 + r) * DGPT + c8;
            *(uint4*)(sKh + r * ATS + c8) = *(const uint4*)(kh + g);
            *(uint4*)(sKl + r * ATS + c8) = *(const uint4*)(klp + g);
        }
        for (int f = tid; f < 1024; f += 128) {
            int r = f >> 4, c4 = (f & 15) * 4;
            size_t g = base + (size_t)(j0 + r) * DGPT + c4;
            uint2 hv = *(const uint2*)(vh + g);
            uint2 lv = *(const uint2*)(vlp + g);
            __half2 h01 = *(__half2*)&hv.x, h23 = *(__half2*)&hv.y;
            __half2 l01 = *(__half2*)&lv.x, l23 = *(__half2*)&lv.y;
            sVh[(c4 + 0) * ATS + r] = __low2half(h01);
            sVh[(c4 + 1) * ATS + r] = __high2half(h01);
            sVh[(c4 + 2) * ATS + r] = __low2half(h23);
            sVh[(c4 + 3) * ATS + r] = __high2half(h23);
            sVl[(c4 + 0) * ATS + r] = __low2half(l01);
            sVl[(c4 + 1) * ATS + r] = __high2half(l01);
            sVl[(c4 + 2) * ATS + r] = __low2half(l23);
            sVl[(c4 + 3) * ATS + r] = __high2half(l23);
        }
        __syncthreads();

        float S[8][4];
        #pragma unroll
        for (int t = 0; t < 8; t++)
            #pragma unroll
            for (int r = 0; r < 4; r++) S[t][r] = 0.f;

        #pragma unroll
        for (int ks = 0; ks < 4; ks++) {
            uint32_t aqh[4], aql[4];
            ldm4(aqh, sQh + a_row * ATS + ks * 16 + a_coff);
            ldm4(aql, sQl + a_row * ATS + ks * 16 + a_coff);
            #pragma unroll
            for (int nb = 0; nb < 4; nb++) {
                uint32_t t4[4];
                ldm4(t4, sKh + (nb * 16 + b_row) * ATS + ks * 16 + b_coff);
                uint32_t bh0[2] = { t4[0], t4[1] };
                uint32_t bh1[2] = { t4[2], t4[3] };
                ldm4(t4, sKl + (nb * 16 + b_row) * ATS + ks * 16 + b_coff);
                uint32_t bl0[2] = { t4[0], t4[1] };
                uint32_t bl1[2] = { t4[2], t4[3] };
                mma_f32(S[2 * nb],     aqh, bh0);
                mma_f32(S[2 * nb + 1], aqh, bh1);
                mma_f32(S[2 * nb],     aqh, bl0);
                mma_f32(S[2 * nb + 1], aqh, bl1);
                mma_f32(S[2 * nb],     aql, bh0);
                mma_f32(S[2 * nb + 1], aql, bh1);
            }
        }

        const bool diag = (ch == qb);
        #pragma unroll
        for (int t = 0; t < 8; t++) {
            S[t][0] *= 0.125f; S[t][1] *= 0.125f;
            S[t][2] *= 0.125f; S[t][3] *= 0.125f;
            if (diag) {
                int c0 = t * 8 + cl0, c1 = c0 + 1;
                if (c0 > rl1)     S[t][0] = -1e30f;
                if (c1 > rl1)     S[t][1] = -1e30f;
                if (c0 > rl1 + 8) S[t][2] = -1e30f;
                if (c1 > rl1 + 8) S[t][3] = -1e30f;
            }
        }

        float mx1 = -1e30f, mx2 = -1e30f;
        #pragma unroll
        for (int t = 0; t < 8; t++) {
            mx1 = fmaxf(mx1, fmaxf(S[t][0], S[t][1]));
            mx2 = fmaxf(mx2, fmaxf(S[t][2], S[t][3]));
        }
        mx1 = fmaxf(mx1, __shfl_xor_sync(0xffffffffu, mx1, 1));
        mx1 = fmaxf(mx1, __shfl_xor_sync(0xffffffffu, mx1, 2));
        mx2 = fmaxf(mx2, __shfl_xor_sync(0xffffffffu, mx2, 1));
        mx2 = fmaxf(mx2, __shfl_xor_sync(0xffffffffu, mx2, 2));

        float mn1 = fmaxf(m1, mx1), mn2 = fmaxf(m2, mx2);
        float cr1 = __expf(m1 - mn1), cr2 = __expf(m2 - mn2);
        m1 = mn1; m2 = mn2;

        float s1 = 0.f, s2 = 0.f;
        uint32_t Pf[4][4];
        #pragma unroll
        for (int t = 0; t < 8; t++) {
            float p0 = __expf(S[t][0] - mn1);
            float p1 = __expf(S[t][1] - mn1);
            float p2 = __expf(S[t][2] - mn2);
            float p3 = __expf(S[t][3] - mn2);
            s1 += p0 + p1; s2 += p2 + p3;
            __half2 ph01 = __halves2half2(__float2half_rn(p0), __float2half_rn(p1));
            __half2 ph23 = __halves2half2(__float2half_rn(p2), __float2half_rn(p3));
            const int kt = t >> 1, hf = (t & 1) * 2;
            Pf[kt][hf + 0] = *(uint32_t*)&ph01;
            Pf[kt][hf + 1] = *(uint32_t*)&ph23;
        }
        s1 += __shfl_xor_sync(0xffffffffu, s1, 1);
        s1 += __shfl_xor_sync(0xffffffffu, s1, 2);
        s2 += __shfl_xor_sync(0xffffffffu, s2, 1);
        s2 += __shfl_xor_sync(0xffffffffu, s2, 2);
        l1 = l1 * cr1 + s1;
        l2 = l2 * cr2 + s2;
        #pragma unroll
        for (int t = 0; t < 8; t++) {
            O[t][0] *= cr1; O[t][1] *= cr1;
            O[t][2] *= cr2; O[t][3] *= cr2;
        }

        #pragma unroll
        for (int kt = 0; kt < 4; kt++) {
            #pragma unroll
            for (int nb = 0; nb < 4; nb++) {
                uint32_t t4[4];
                ldm4(t4, sVh + (nb * 16 + b_row) * ATS + kt * 16 + b_coff);
                uint32_t bv0[2] = { t4[0], t4[1] };
                uint32_t bv1[2] = { t4[2], t4[3] };
                mma_f32(O[2 * nb],     Pf[kt], bv0);
                mma_f32(O[2 * nb + 1], Pf[kt], bv1);
                ldm4(t4, sVl + (nb * 16 + b_row) * ATS + kt * 16 + b_coff);
                uint32_t bw0[2] = { t4[0], t4[1] };
                uint32_t bw1[2] = { t4[2], t4[3] };
                mma_f32(O[2 * nb],     Pf[kt], bw0);
                mma_f32(O[2 * nb + 1], Pf[kt], bw1);
            }
        }
    }

    // epilogue: normalize + store fp16 hi
    const float inv1 = 1.f / l1, inv2 = 1.f / l2;
    const size_t row1 = base + (size_t)(qb * 64 + rl1) * DGPT;
    const size_t row2 = base + (size_t)(qb * 64 + rl1 + 8) * DGPT;
    #pragma unroll
    for (int t = 0; t < 8; t++) {
        const int col = t * 8 + cl0;
        *(__half2*)(yhi + row1 + col) =
            __halves2half2(__float2half_rn(O[t][0] * inv1), __float2half_rn(O[t][1] * inv1));
        *(__half2*)(yhi + row2 + col) =
            __halves2half2(__float2half_rn(O[t][2] * inv2), __float2half_rn(O[t][3] * inv2));
    }
}

// ---------------- launcher ----------------
static inline void convsplit(const float* in, __half* hi, __half* lo, size_t n)
{
    size_t n4 = n / 4;
    convsplit_kernel<<<(unsigned)((n4 + 255) / 256), 256>>>(in, hi, lo, n4);
}

extern "C" void kernel_launch(void* const* d_in, const int* in_sizes, int n_in,
                              void* d_out, int out_size)
{
    const int*   idx    = (const int*)  d_in[0];
    const float* tok    = (const float*)d_in[1];
    const float* pos    = (const float*)d_in[2];
    const float* ln1_w  = (const float*)d_in[3];
    const float* ln1_b  = (const float*)d_in[4];
    const float* Wq     = (const float*)d_in[5];
    const float* bq     = (const float*)d_in[6];
    const float* Wk     = (const float*)d_in[7];
    const float* bk     = (const float*)d_in[8];
    const float* Wv     = (const float*)d_in[9];
    const float* bv     = (const float*)d_in[10];
    const float* Wproj  = (const float*)d_in[11];
    const float* bproj  = (const float*)d_in[12];
    const float* ln2_w  = (const float*)d_in[13];
    const float* ln2_b  = (const float*)d_in[14];
    const float* W1     = (const float*)d_in[15];
    const float* b1     = (const float*)d_in[16];
    const float* W2     = (const float*)d_in[17];
    const float* b2     = (const float*)d_in[18];
    const float* lnf_w  = (const float*)d_in[19];
    const float* lnf_b  = (const float*)d_in[20];
    const float* Wlogit = (const float*)d_in[21];
    const float* Wdev   = (const float*)d_in[22];
    float* out = (float*)d_out;

    float *xp, *qp, *kp, *vp;
    __half *whi, *wlo, *ahi, *alo, *fhi;
    cudaGetSymbolAddress((void**)&xp, g_x);
    cudaGetSymbolAddress((void**)&qp, g_q);
    cudaGetSymbolAddress((void**)&kp, g_k);
    cudaGetSymbolAddress((void**)&vp, g_v);
    cudaGetSymbolAddress((void**)&whi, g_whi);
    cudaGetSymbolAddress((void**)&wlo, g_wlo);
    cudaGetSymbolAddress((void**)&ahi, g_ahi);
    cudaGetSymbolAddress((void**)&alo, g_alo);
    cudaGetSymbolAddress((void**)&fhi, g_fhi);

    __half* qhi = (__half*)qp;  __half* qlo = qhi + (size_t)MGPT * DGPT;
    __half* khi = (__half*)kp;  __half* klo = khi + (size_t)MGPT * DGPT;
    __half* vhi = (__half*)vp;  __half* vlo = vhi + (size_t)MGPT * DGPT;

    cudaFuncSetAttribute((const void*)gemm_tc<0,1>, cudaFuncAttributeMaxDynamicSharedMemorySize, GS1);
    cudaFuncSetAttribute((const void*)gemm_tc<1,1>, cudaFuncAttributeMaxDynamicSharedMemorySize, GS1);
    cudaFuncSetAttribute((const void*)gemm_tc<2,1>, cudaFuncAttributeMaxDynamicSharedMemorySize, GS1);
    cudaFuncSetAttribute((const void*)gemm_tc<3,3>, cudaFuncAttributeMaxDynamicSharedMemorySize, GS3);
    cudaFuncSetAttribute((const void*)attn_mma,     cudaFuncAttributeMaxDynamicSharedMemorySize, ATT_SMEM);

    // weights: hi only for layer GEMMs; hi+lo for heads (lo written for all, cheap)
    convsplit(Wq,     whi + O_WQ,  wlo + O_WQ,  SZ_WQ);
    convsplit(Wk,     whi + O_WK,  wlo + O_WK,  SZ_WQ);
    convsplit(Wv,     whi + O_WV,  wlo + O_WV,  SZ_WQ);
    convsplit(Wproj,  whi + O_WP,  wlo + O_WP,  SZ_WQ);
    convsplit(W1,     whi + O_W1,  wlo + O_W1,  SZ_W1);
    convsplit(W2,     whi + O_W2,  wlo + O_W2,  SZ_W1);
    convsplit(Wlogit, whi + O_WLG, wlo + O_WLG, SZ_HEAD);
    convsplit(Wdev,   whi + O_WDV, wlo + O_WDV, SZ_HEAD);

    dim3 gD(DGPT / 128, MGPT / 128);
    dim3 gF(FGPT / 128, MGPT / 128);
    dim3 gV(VGPT / 128, MGPT / 128);
    dim3 gA(BGPT * HGPT, TGPT / 64);

    embed_kernel<<<(MGPT * DGPT + 255) / 256, 256>>>(idx, tok, pos, xp);

    for (int l = 0; l < LGPT; l++) {
        size_t oD  = (size_t)l * DGPT * DGPT;
        size_t oF  = (size_t)l * FGPT * DGPT;
        size_t ob  = (size_t)l * DGPT;
        size_t obf = (size_t)l * FGPT;

        ln_kernel<<<MGPT, 256>>>(xp, ahi, alo, ln1_w + ob, ln1_b + ob);
        gemm_tc<0,1><<<gD, 256, GS1>>>(ahi, nullptr, whi + O_WQ + oD, nullptr,
                                       bq + ob, nullptr, nullptr, qhi, qlo, MGPT, DGPT, DGPT);
        gemm_tc<0,1><<<gD, 256, GS1>>>(ahi, nullptr, whi + O_WK + oD, nullptr,
                                       bk + ob, nullptr, nullptr, khi, klo, MGPT, DGPT, DGPT);
        gemm_tc<0,1><<<gD, 256, GS1>>>(ahi, nullptr, whi + O_WV + oD, nullptr,
                                       bv + ob, nullptr, nullptr, vhi, vlo, MGPT, DGPT, DGPT);
        attn_mma<<<gA, 128, ATT_SMEM>>>(qhi, qlo, khi, klo, vhi, vlo, ahi);
        gemm_tc<2,1><<<gD, 256, GS1>>>(ahi, nullptr, whi + O_WP + oD, nullptr,
                                       bproj + ob, xp, xp, nullptr, nullptr, MGPT, DGPT, DGPT);

        ln_kernel<<<MGPT, 256>>>(xp, ahi, alo, ln2_w + ob, ln2_b + ob);
        gemm_tc<1,1><<<gF, 256, GS1>>>(ahi, nullptr, whi + O_W1 + oF, nullptr,
                                       b1 + obf, nullptr, nullptr, fhi, nullptr, MGPT, FGPT, DGPT);
        gemm_tc<2,1><<<gD, 256, GS1>>>(fhi, nullptr, whi + O_W2 + oF, nullptr,
                                       b2 + ob, xp, xp, nullptr, nullptr, MGPT, DGPT, FGPT);
    }

    ln_kernel<<<MGPT, 256>>>(xp, ahi, alo, lnf_w, lnf_b);
    gemm_tc<3,3><<<gV, 256, GS3>>>(ahi, alo, whi + O_WLG, wlo + O_WLG,
                                   nullptr, nullptr, out, nullptr, nullptr, MGPT, VGPT, DGPT);
    gemm_tc<3,3><<<gV, 256, GS3>>>(ahi, alo, whi + O_WDV, wlo + O_WDV,
                                   nullptr, nullptr, out + (size_t)MGPT * VGPT, nullptr, nullptr,
                                   MGPT, VGPT, DGPT);
}

// round 12
// speedup vs baseline: 5.7775x; 1.0031x over previous
#include <cuda_runtime.h>
#include <cuda_fp16.h>
#include <math.h>
#include <stdint.h>

// ---------------- problem constants ----------------
#define BGPT 4
#define TGPT 1024
#define DGPT 1024
#define HGPT 16
#define HDH  64
#define LGPT 8
#define VGPT 4096
#define MGPT (BGPT*TGPT)   // 4096 tokens
#define FGPT (4*DGPT)      // 4096 ff dim

// weight scratch offsets (elements)
#define SZ_WQ   ((size_t)LGPT*DGPT*DGPT)
#define SZ_W1   ((size_t)LGPT*FGPT*DGPT)
#define SZ_HEAD ((size_t)VGPT*DGPT)
#define O_WQ    ((size_t)0)
#define O_WK    (O_WQ + SZ_WQ)
#define O_WV    (O_WK + SZ_WQ)
#define O_WP    (O_WV + SZ_WQ)
#define O_W1    (O_WP + SZ_WQ)
#define O_W2    (O_W1 + SZ_W1)
#define O_WLG   (O_W2 + SZ_W1)
#define O_WDV   (O_WLG + SZ_HEAD)
#define WTOT    (O_WDV + SZ_HEAD)

// ---------------- scratch (device globals; no allocs allowed) ----------------
__device__ float g_x [MGPT*DGPT];              // residual stream (fp32)
__device__ float g_q [MGPT*DGPT];              // reused as fp16 hi||lo
__device__ float g_k [MGPT*DGPT];              // reused as fp16 hi||lo
__device__ float g_v [MGPT*DGPT];              // reused as fp16 hi||lo
__device__ __half g_ahi[(size_t)MGPT*DGPT];    // activation hi
__device__ __half g_alo[(size_t)MGPT*DGPT];    // activation lo (final LN only)
__device__ __half g_fhi[(size_t)MGPT*FGPT];    // ff activation hi
__device__ __half g_whi[WTOT];                 // split weights (hi)
__device__ __half g_wlo[(size_t)2*SZ_HEAD];    // weight lo (heads only)
#define OL_WLG 0
#define OL_WDV SZ_HEAD

// ---------------- helpers ----------------
__device__ __forceinline__ void split_f16(float v, __half& h, __half& l)
{
    h = __float2half_rn(v);
    l = __float2half_rn(v - __half2float(h));
}

// ---------------- embedding ----------------
__global__ void embed_kernel(const int* __restrict__ idx,
                             const float* __restrict__ tok,
                             const float* __restrict__ pos,
                             float* __restrict__ x)
{
    int i = blockIdx.x * blockDim.x + threadIdx.x;
    if (i >= MGPT * DGPT) return;
    int row = i / DGPT;
    int d   = i - row * DGPT;
    int t   = row & (TGPT - 1);
    x[i] = tok[(size_t)idx[row] * DGPT + d] + pos[(size_t)t * DGPT + d];
}

// ---------------- fp32 -> fp16 hi/lo split (head weights) ----------------
__global__ void __launch_bounds__(256) convsplit_kernel(const float* __restrict__ in,
                                                        __half* __restrict__ hi,
                                                        __half* __restrict__ lo,
                                                        size_t n4)
{
    size_t i = (size_t)blockIdx.x * blockDim.x + threadIdx.x;
    if (i >= n4) return;
    size_t e = i * 4;
    float4 v = *(const float4*)(in + e);
    __half hx, hy, hz, hw, lx, ly, lz, lw;
    split_f16(v.x, hx, lx); split_f16(v.y, hy, ly);
    split_f16(v.z, hz, lz); split_f16(v.w, hw, lw);
    __half2 h01 = __halves2half2(hx, hy);
    __half2 h23 = __halves2half2(hz, hw);
    __half2 l01 = __halves2half2(lx, ly);
    __half2 l23 = __halves2half2(lz, lw);
    uint2 ho, loo;
    ho.x  = *(uint32_t*)&h01; ho.y  = *(uint32_t*)&h23;
    loo.x = *(uint32_t*)&l01; loo.y = *(uint32_t*)&l23;
    *(uint2*)(hi + e) = ho;
    *(uint2*)(lo + e) = loo;
}

// ---------------- fp32 -> fp16 hi only (layer weights) ----------------
__global__ void __launch_bounds__(256) convhi_kernel(const float* __restrict__ in,
                                                     __half* __restrict__ hi,
                                                     size_t n4)
{
    size_t i = (size_t)blockIdx.x * blockDim.x + threadIdx.x;
    if (i >= n4) return;
    size_t e = i * 4;
    float4 v = *(const float4*)(in + e);
    __half2 h01 = __halves2half2(__float2half_rn(v.x), __float2half_rn(v.y));
    __half2 h23 = __halves2half2(__float2half_rn(v.z), __float2half_rn(v.w));
    uint2 ho;
    ho.x = *(uint32_t*)&h01; ho.y = *(uint32_t*)&h23;
    *(uint2*)(hi + e) = ho;
}

// ---------------- layernorm: fp32 in -> fp16 hi (+lo) out ----------------
template<int WLO>
__global__ void __launch_bounds__(256) ln_kernel(const float* __restrict__ in,
                                                 __half* __restrict__ ohi,
                                                 __half* __restrict__ olo,
                                                 const float* __restrict__ w,
                                                 const float* __restrict__ b)
{
    int row = blockIdx.x;
    const float* x = in + (size_t)row * DGPT;
    int tid = threadIdx.x;
    __shared__ float red[8];

    float s = 0.f;
    for (int d = tid; d < DGPT; d += 256) s += x[d];
    #pragma unroll
    for (int o = 16; o; o >>= 1) s += __shfl_xor_sync(0xffffffffu, s, o);
    if ((tid & 31) == 0) red[tid >> 5] = s;
    __syncthreads();
    if (tid < 32) {
        float v = (tid < 8) ? red[tid] : 0.f;
        #pragma unroll
        for (int o = 4; o; o >>= 1) v += __shfl_xor_sync(0xffffffffu, v, o);
        if (tid == 0) red[0] = v;
    }
    __syncthreads();
    float mean = red[0] * (1.f / DGPT);

    float q = 0.f;
    for (int d = tid; d < DGPT; d += 256) { float t = x[d] - mean; q += t * t; }
    __syncthreads();
    #pragma unroll
    for (int o = 16; o; o >>= 1) q += __shfl_xor_sync(0xffffffffu, q, o);
    if ((tid & 31) == 0) red[tid >> 5] = q;
    __syncthreads();
    if (tid < 32) {
        float v = (tid < 8) ? red[tid] : 0.f;
        #pragma unroll
        for (int o = 4; o; o >>= 1) v += __shfl_xor_sync(0xffffffffu, v, o);
        if (tid == 0) red[0] = v;
    }
    __syncthreads();
    float rstd = rsqrtf(red[0] * (1.f / DGPT) + 1e-5f);

    for (int d = tid; d < DGPT; d += 256) {
        float v = (x[d] - mean) * rstd * w[d] + b[d];
        __half h, l;
        split_f16(v, h, l);
        ohi[(size_t)row * DGPT + d] = h;
        if (WLO) olo[(size_t)row * DGPT + d] = l;
    }
}

// ---------------- tensor-core helpers ----------------
__device__ __forceinline__ void ldm4(uint32_t r[4], const __half* p)
{
    uint32_t a = (uint32_t)__cvta_generic_to_shared(p);
    asm volatile("ldmatrix.sync.aligned.m8n8.x4.shared.b16 {%0,%1,%2,%3}, [%4];\n"
                 : "=r"(r[0]), "=r"(r[1]), "=r"(r[2]), "=r"(r[3]) : "r"(a));
}
__device__ __forceinline__ void mma_f32(float c[4], const uint32_t a[4], const uint32_t b[2])
{
    asm volatile(
        "mma.sync.aligned.m16n8k16.row.col.f32.f16.f16.f32 "
        "{%0,%1,%2,%3}, {%4,%5,%6,%7}, {%8,%9}, {%0,%1,%2,%3};\n"
        : "+f"(c[0]), "+f"(c[1]), "+f"(c[2]), "+f"(c[3])
        : "r"(a[0]), "r"(a[1]), "r"(a[2]), "r"(a[3]), "r"(b[0]), "r"(b[1]));
}

// ---------------- GEMM (BN=128): C[M,N] = A[M,K] @ W[N,K]^T ----------------
// TERMS=1: C = Ahi*Whi | TERMS=3: + Ahi*Wlo + Alo*Whi (heads)
// MODE: 0 = +bias, fp16 hi/lo out | 1 = +bias, GELU, fp16 hi out
//       2 = +bias +res, fp32 out  | 3 = plain fp32 out
#define BKg 32
#define PK  40
#define SMBUF (128*PK)
#define SMMAT (2*SMBUF)
#define GS1 (2*SMMAT*2)   // 40960 B
#define GS3 (4*SMMAT*2)   // 81920 B

template<int MODE, int TERMS>
__global__ void __launch_bounds__(256) gemm_tc(
    const __half* __restrict__ Ahi, const __half* __restrict__ Alo,
    const __half* __restrict__ Whi, const __half* __restrict__ Wlo,
    const float* __restrict__ bias, const float* __restrict__ res,
    float* __restrict__ C, __half* __restrict__ Chi, __half* __restrict__ Clo,
    int M, int N, int K)
{
    extern __shared__ __align__(16) __half sm[];
    __half* sAh = sm;
    __half* sBh = sm + SMMAT;
    __half* sBl = sm + 2 * SMMAT;
    __half* sAl = sm + 3 * SMMAT;

    const int tid  = threadIdx.x;
    const int lane = tid & 31;
    const int wid  = tid >> 5;
    const int wm   = wid >> 2;
    const int wn   = wid & 3;
    const int bm   = blockIdx.y * 128;
    const int bn   = blockIdx.x * 128;

    const int lrow = tid >> 1;
    const int lcol = (tid & 1) << 4;
    const __half* gAh = Ahi + (size_t)(bm + lrow) * K + lcol;
    const __half* gAl = (TERMS == 3) ? (Alo + (size_t)(bm + lrow) * K + lcol) : nullptr;
    const __half* gBh = Whi + (size_t)(bn + lrow) * K + lcol;
    const __half* gBl = (TERMS == 3) ? (Wlo + (size_t)(bn + lrow) * K + lcol) : nullptr;

    const int a_r = wm * 64 + (lane & 15);
    const int a_c = (lane >> 4) * 8;
    const int b_r = wn * 32 + (lane >> 4) * 8 + (lane & 7);
    const int b_c = ((lane >> 3) & 1) * 8;

    float acc[4][4][4];
    #pragma unroll
    for (int mi = 0; mi < 4; mi++)
        #pragma unroll
        for (int ni = 0; ni < 4; ni++)
            #pragma unroll
            for (int r = 0; r < 4; r++) acc[mi][ni][r] = 0.f;

    uint4 rAh0, rAh1, rAl0, rAl1, rBh0, rBh1, rBl0, rBl1;

    const int NS = K / BKg;
    rAh0 = *(const uint4*)(gAh);     rAh1 = *(const uint4*)(gAh + 8);
    rBh0 = *(const uint4*)(gBh);     rBh1 = *(const uint4*)(gBh + 8);
    if (TERMS == 3) {
        rBl0 = *(const uint4*)(gBl); rBl1 = *(const uint4*)(gBl + 8);
        rAl0 = *(const uint4*)(gAl); rAl1 = *(const uint4*)(gAl + 8);
    }
    {
        __half* p = sAh + lrow * PK + lcol;
        *(uint4*)p = rAh0; *(uint4*)(p + 8) = rAh1;
        p = sBh + lrow * PK + lcol;
        *(uint4*)p = rBh0; *(uint4*)(p + 8) = rBh1;
        if (TERMS == 3) {
            p = sBl + lrow * PK + lcol;
            *(uint4*)p = rBl0; *(uint4*)(p + 8) = rBl1;
            p = sAl + lrow * PK + lcol;
            *(uint4*)p = rAl0; *(uint4*)(p + 8) = rAl1;
        }
    }
    __syncthreads();

    for (int s = 0; s < NS; s++) {
        if (s + 1 < NS) {
            int k0 = (s + 1) * BKg;
            rAh0 = *(const uint4*)(gAh + k0);  rAh1 = *(const uint4*)(gAh + k0 + 8);
            rBh0 = *(const uint4*)(gBh + k0);  rBh1 = *(const uint4*)(gBh + k0 + 8);
            if (TERMS == 3) {
                rBl0 = *(const uint4*)(gBl + k0); rBl1 = *(const uint4*)(gBl + k0 + 8);
                rAl0 = *(const uint4*)(gAl + k0); rAl1 = *(const uint4*)(gAl + k0 + 8);
            }
        }

        const int bo = (s & 1) * SMBUF;
        #pragma unroll
        for (int ks = 0; ks < 2; ks++) {
            const int k0 = ks * 16;
            uint32_t afh[4][4];
            #pragma unroll
            for (int mi = 0; mi < 4; mi++)
                ldm4(afh[mi], sAh + bo + (a_r + mi * 16) * PK + k0 + a_c);
            uint32_t bfh[4][2];
            #pragma unroll
            for (int np = 0; np < 2; np++) {
                uint32_t t[4];
                ldm4(t, sBh + bo + (b_r + np * 16) * PK + k0 + b_c);
                bfh[np * 2][0] = t[0]; bfh[np * 2][1] = t[1];
                bfh[np * 2 + 1][0] = t[2]; bfh[np * 2 + 1][1] = t[3];
            }
            #pragma unroll
            for (int mi = 0; mi < 4; mi++)
                #pragma unroll
                for (int ni = 0; ni < 4; ni++)
                    mma_f32(acc[mi][ni], afh[mi], bfh[ni]);
            if (TERMS == 3) {
                uint32_t bfl[4][2];
                #pragma unroll
                for (int np = 0; np < 2; np++) {
                    uint32_t t[4];
                    ldm4(t, sBl + bo + (b_r + np * 16) * PK + k0 + b_c);
                    bfl[np * 2][0] = t[0]; bfl[np * 2][1] = t[1];
                    bfl[np * 2 + 1][0] = t[2]; bfl[np * 2 + 1][1] = t[3];
                }
                #pragma unroll
                for (int mi = 0; mi < 4; mi++)
                    #pragma unroll
                    for (int ni = 0; ni < 4; ni++)
                        mma_f32(acc[mi][ni], afh[mi], bfl[ni]);
                uint32_t afl[4][4];
                #pragma unroll
                for (int mi = 0; mi < 4; mi++)
                    ldm4(afl[mi], sAl + bo + (a_r + mi * 16) * PK + k0 + a_c);
                #pragma unroll
                for (int mi = 0; mi < 4; mi++)
                    #pragma unroll
                    for (int ni = 0; ni < 4; ni++)
                        mma_f32(acc[mi][ni], afl[mi], bfh[ni]);
            }
        }

        if (s + 1 < NS) {
            const int bo2 = ((s + 1) & 1) * SMBUF;
            __half* p = sAh + bo2 + lrow * PK + lcol;
            *(uint4*)p = rAh0; *(uint4*)(p + 8) = rAh1;
            p = sBh + bo2 + lrow * PK + lcol;
            *(uint4*)p = rBh0; *(uint4*)(p + 8) = rBh1;
            if (TERMS == 3) {
                p = sBl + bo2 + lrow * PK + lcol;
                *(uint4*)p = rBl0; *(uint4*)(p + 8) = rBl1;
                p = sAl + bo2 + lrow * PK + lcol;
                *(uint4*)p = rAl0; *(uint4*)(p + 8) = rAl1;
            }
            __syncthreads();
        }
    }

    // epilogue
    const int er = bm + wm * 64 + (lane >> 2);
    const int ec = bn + wn * 32 + (lane & 3) * 2;
    #pragma unroll
    for (int mi = 0; mi < 4; mi++) {
        #pragma unroll
        for (int ni = 0; ni < 4; ni++) {
            const int col = ec + ni * 8;
            #pragma unroll
            for (int h = 0; h < 2; h++) {
                const size_t row = (size_t)(er + mi * 16 + h * 8);
                float v0 = acc[mi][ni][h * 2];
                float v1 = acc[mi][ni][h * 2 + 1];
                if (MODE != 3) { v0 += bias[col]; v1 += bias[col + 1]; }
                if (MODE == 0) {
                    __half h0, l0, h1, l1;
                    split_f16(v0, h0, l0);
                    split_f16(v1, h1, l1);
                    *(__half2*)(Chi + row * N + col) = __halves2half2(h0, h1);
                    *(__half2*)(Clo + row * N + col) = __halves2half2(l0, l1);
                } else if (MODE == 1) {
                    v0 = 0.5f * v0 * (1.f + erff(v0 * 0.70710678118654752f));
                    v1 = 0.5f * v1 * (1.f + erff(v1 * 0.70710678118654752f));
                    *(__half2*)(Chi + row * N + col) =
                        __halves2half2(__float2half_rn(v0), __float2half_rn(v1));
                } else {
                    if (MODE == 2) {
                        v0 += res[row * N + col];
                        v1 += res[row * N + col + 1];
                    }
                    float2 o; o.x = v0; o.y = v1;
                    *(float2*)(C + row * N + col) = o;
                }
            }
        }
    }
}

// ---------------- GEMM (BN=256, warp 64x64) for W1: GELU, fp16 hi out ------
#define W1_SA (128*PK)            // 5120 elems
#define W1_SB (256*PK)            // 10240 elems
#define W1_STG (W1_SA + W1_SB)    // 15360 elems per stage
#define GSW (2*W1_STG*2)          // 61440 bytes

__global__ void __launch_bounds__(256) gemm_w1(
    const __half* __restrict__ Ahi, const __half* __restrict__ Whi,
    const float* __restrict__ bias, __half* __restrict__ Chi,
    int M, int N, int K)
{
    extern __shared__ __align__(16) __half sm[];

    const int tid  = threadIdx.x;
    const int lane = tid & 31;
    const int wid  = tid >> 5;
    const int wm   = wid >> 2;          // 0..1 (64 rows)
    const int wn   = wid & 3;           // 0..3 (64 cols)
    const int bm   = blockIdx.y * 128;
    const int bn   = blockIdx.x * 256;

    const int lrow = tid >> 1;
    const int lcol = (tid & 1) << 4;
    const __half* gA  = Ahi + (size_t)(bm + lrow) * K + lcol;
    const __half* gB0 = Whi + (size_t)(bn + lrow) * K + lcol;
    const __half* gB1 = Whi + (size_t)(bn + 128 + lrow) * K + lcol;

    const int a_r = wm * 64 + (lane & 15);
    const int a_c = (lane >> 4) * 8;
    const int b_r = wn * 64 + (lane >> 4) * 8 + (lane & 7);
    const int b_c = ((lane >> 3) & 1) * 8;

    float acc[4][8][4];
    #pragma unroll
    for (int mi = 0; mi < 4; mi++)
        #pragma unroll
        for (int ni = 0; ni < 8; ni++)
            #pragma unroll
            for (int r = 0; r < 4; r++) acc[mi][ni][r] = 0.f;

    uint4 rA0, rA1, rB00, rB01, rB10, rB11;

    const int NS = K / BKg;
    rA0  = *(const uint4*)(gA);      rA1  = *(const uint4*)(gA + 8);
    rB00 = *(const uint4*)(gB0);     rB01 = *(const uint4*)(gB0 + 8);
    rB10 = *(const uint4*)(gB1);     rB11 = *(const uint4*)(gB1 + 8);
    {
        __half* p = sm + lrow * PK + lcol;
        *(uint4*)p = rA0; *(uint4*)(p + 8) = rA1;
        p = sm + W1_SA + lrow * PK + lcol;
        *(uint4*)p = rB00; *(uint4*)(p + 8) = rB01;
        p = sm + W1_SA + (128 + lrow) * PK + lcol;
        *(uint4*)p = rB10; *(uint4*)(p + 8) = rB11;
    }
    __syncthreads();

    for (int s = 0; s < NS; s++) {
        if (s + 1 < NS) {
            int k0 = (s + 1) * BKg;
            rA0  = *(const uint4*)(gA + k0);   rA1  = *(const uint4*)(gA + k0 + 8);
            rB00 = *(const uint4*)(gB0 + k0);  rB01 = *(const uint4*)(gB0 + k0 + 8);
            rB10 = *(const uint4*)(gB1 + k0);  rB11 = *(const uint4*)(gB1 + k0 + 8);
        }

        const __half* stg = sm + (s & 1) * W1_STG;
        const __half* sA = stg;
        const __half* sB = stg + W1_SA;
        #pragma unroll
        for (int ks = 0; ks < 2; ks++) {
            const int k0 = ks * 16;
            uint32_t af[4][4];
            #pragma unroll
            for (int mi = 0; mi < 4; mi++)
                ldm4(af[mi], sA + (a_r + mi * 16) * PK + k0 + a_c);
            uint32_t bf[8][2];
            #pragma unroll
            for (int nb = 0; nb < 4; nb++) {
                uint32_t t[4];
                ldm4(t, sB + (b_r + nb * 16) * PK + k0 + b_c);
                bf[nb * 2][0] = t[0]; bf[nb * 2][1] = t[1];
                bf[nb * 2 + 1][0] = t[2]; bf[nb * 2 + 1][1] = t[3];
            }
            #pragma unroll
            for (int mi = 0; mi < 4; mi++)
                #pragma unroll
                for (int ni = 0; ni < 8; ni++)
                    mma_f32(acc[mi][ni], af[mi], bf[ni]);
        }

        if (s + 1 < NS) {
            __half* stg2 = sm + ((s + 1) & 1) * W1_STG;
            __half* p = stg2 + lrow * PK + lcol;
            *(uint4*)p = rA0; *(uint4*)(p + 8) = rA1;
            p = stg2 + W1_SA + lrow * PK + lcol;
            *(uint4*)p = rB00; *(uint4*)(p + 8) = rB01;
            p = stg2 + W1_SA + (128 + lrow) * PK + lcol;
            *(uint4*)p = rB10; *(uint4*)(p + 8) = rB11;
            __syncthreads();
        }
    }

    // epilogue: bias + GELU + fp16 hi store
    const int er = bm + wm * 64 + (lane >> 2);
    const int ec = bn + wn * 64 + (lane & 3) * 2;
    #pragma unroll
    for (int mi = 0; mi < 4; mi++) {
        #pragma unroll
        for (int ni = 0; ni < 8; ni++) {
            const int col = ec + ni * 8;
            const float b0 = bias[col], b1 = bias[col + 1];
            #pragma unroll
            for (int h = 0; h < 2; h++) {
                const size_t row = (size_t)(er + mi * 16 + h * 8);
                float v0 = acc[mi][ni][h * 2]     + b0;
                float v1 = acc[mi][ni][h * 2 + 1] + b1;
                v0 = 0.5f * v0 * (1.f + erff(v0 * 0.70710678118654752f));
                v1 = 0.5f * v1 * (1.f + erff(v1 * 0.70710678118654752f));
                *(__half2*)(Chi + row * N + col) =
                    __halves2half2(__float2half_rn(v0), __float2half_rn(v1));
            }
        }
    }
}

// ---------------- tensor-core flash attention ----------------
#define ATS 72
#define ATT_SMEM (6*64*ATS*2)   // 55296 B

__global__ void __launch_bounds__(128) attn_mma(
    const __half* __restrict__ qh, const __half* __restrict__ qlp,
    const __half* __restrict__ kh, const __half* __restrict__ klp,
    const __half* __restrict__ vh, const __half* __restrict__ vlp,
    __half* __restrict__ yhi)
{
    extern __shared__ __align__(16) __half sa[];
    __half* sQh = sa;
    __half* sQl = sa + 64 * ATS;
    __half* sKh = sa + 2 * 64 * ATS;
    __half* sKl = sa + 3 * 64 * ATS;
    __half* sVh = sa + 4 * 64 * ATS;    // transposed: [d][kv]
    __half* sVl = sa + 5 * 64 * ATS;

    const int bh = blockIdx.x;
    const int b  = bh / HGPT;
    const int h  = bh % HGPT;
    const int qb = blockIdx.y;
    const int tid  = threadIdx.x;
    const int w    = tid >> 5;
    const int lane = tid & 31;

    const size_t base = (size_t)(b * TGPT) * DGPT + (size_t)h * HDH;

    for (int f = tid; f < 512; f += 128) {
        int r = f >> 3, c8 = (f & 7) * 8;
        size_t g = base + (size_t)(qb * 64 + r) * DGPT + c8;
        *(uint4*)(sQh + r * ATS + c8) = *(const uint4*)(qh + g);
        *(uint4*)(sQl + r * ATS + c8) = *(const uint4*)(qlp + g);
    }

    float O[8][4];
    #pragma unroll
    for (int t = 0; t < 8; t++)
        #pragma unroll
        for (int r = 0; r < 4; r++) O[t][r] = 0.f;
    float m1 = -1e30f, m2 = -1e30f, l1 = 0.f, l2 = 0.f;

    const int a_row  = w * 16 + (lane & 15);
    const int a_coff = (lane >> 4) * 8;
    const int b_row  = (lane >> 4) * 8 + (lane & 7);
    const int b_coff = ((lane >> 3) & 1) * 8;
    const int rl1 = w * 16 + (lane >> 2);
    const int cl0 = 2 * (lane & 3);

    const int nch = qb + 1;
    for (int ch = 0; ch < nch; ch++) {
        const int j0 = ch * 64;
        __syncthreads();
        for (int f = tid; f < 512; f += 128) {
            int r = f >> 3, c8 = (f & 7) * 8;
            size_t g = base + (size_t)(j0 + r) * DGPT + c8;
            *(uint4*)(sKh + r * ATS + c8) = *(const uint4*)(kh + g);
            *(uint4*)(sKl + r * ATS + c8) = *(const uint4*)(klp + g);
        }
        for (int f = tid; f < 1024; f += 128) {
            int r = f >> 4, c4 = (f & 15) * 4;
            size_t g = base + (size_t)(j0 + r) * DGPT + c4;
            uint2 hv = *(const uint2*)(vh + g);
            uint2 lv = *(const uint2*)(vlp + g);
            __half2 h01 = *(__half2*)&hv.x, h23 = *(__half2*)&hv.y;
            __half2 l01 = *(__half2*)&lv.x, l23 = *(__half2*)&lv.y;
            sVh[(c4 + 0) * ATS + r] = __low2half(h01);
            sVh[(c4 + 1) * ATS + r] = __high2half(h01);
            sVh[(c4 + 2) * ATS + r] = __low2half(h23);
            sVh[(c4 + 3) * ATS + r] = __high2half(h23);
            sVl[(c4 + 0) * ATS + r] = __low2half(l01);
            sVl[(c4 + 1) * ATS + r] = __high2half(l01);
            sVl[(c4 + 2) * ATS + r] = __low2half(l23);
            sVl[(c4 + 3) * ATS + r] = __high2half(l23);
        }
        __syncthreads();

        float S[8][4];
        #pragma unroll
        for (int t = 0; t < 8; t++)
            #pragma unroll
            for (int r = 0; r < 4; r++) S[t][r] = 0.f;

        #pragma unroll
        for (int ks = 0; ks < 4; ks++) {
            uint32_t aqh[4], aql[4];
            ldm4(aqh, sQh + a_row * ATS + ks * 16 + a_coff);
            ldm4(aql, sQl + a_row * ATS + ks * 16 + a_coff);
            #pragma unroll
            for (int nb = 0; nb < 4; nb++) {
                uint32_t t4[4];
                ldm4(t4, sKh + (nb * 16 + b_row) * ATS + ks * 16 + b_coff);
                uint32_t bh0[2] = { t4[0], t4[1] };
                uint32_t bh1[2] = { t4[2], t4[3] };
                ldm4(t4, sKl + (nb * 16 + b_row) * ATS + ks * 16 + b_coff);
                uint32_t bl0[2] = { t4[0], t4[1] };
                uint32_t bl1[2] = { t4[2], t4[3] };
                mma_f32(S[2 * nb],     aqh, bh0);
                mma_f32(S[2 * nb + 1], aqh, bh1);
                mma_f32(S[2 * nb],     aqh, bl0);
                mma_f32(S[2 * nb + 1], aqh, bl1);
                mma_f32(S[2 * nb],     aql, bh0);
                mma_f32(S[2 * nb + 1], aql, bh1);
            }
        }

        const bool diag = (ch == qb);
        #pragma unroll
        for (int t = 0; t < 8; t++) {
            S[t][0] *= 0.125f; S[t][1] *= 0.125f;
            S[t][2] *= 0.125f; S[t][3] *= 0.125f;
            if (diag) {
                int c0 = t * 8 + cl0, c1 = c0 + 1;
                if (c0 > rl1)     S[t][0] = -1e30f;
                if (c1 > rl1)     S[t][1] = -1e30f;
                if (c0 > rl1 + 8) S[t][2] = -1e30f;
                if (c1 > rl1 + 8) S[t][3] = -1e30f;
            }
        }

        float mx1 = -1e30f, mx2 = -1e30f;
        #pragma unroll
        for (int t = 0; t < 8; t++) {
            mx1 = fmaxf(mx1, fmaxf(S[t][0], S[t][1]));
            mx2 = fmaxf(mx2, fmaxf(S[t][2], S[t][3]));
        }
        mx1 = fmaxf(mx1, __shfl_xor_sync(0xffffffffu, mx1, 1));
        mx1 = fmaxf(mx1, __shfl_xor_sync(0xffffffffu, mx1, 2));
        mx2 = fmaxf(mx2, __shfl_xor_sync(0xffffffffu, mx2, 1));
        mx2 = fmaxf(mx2, __shfl_xor_sync(0xffffffffu, mx2, 2));

        float mn1 = fmaxf(m1, mx1), mn2 = fmaxf(m2, mx2);
        float cr1 = __expf(m1 - mn1), cr2 = __expf(m2 - mn2);
        m1 = mn1; m2 = mn2;

        float s1 = 0.f, s2 = 0.f;
        uint32_t Pf[4][4];
        #pragma unroll
        for (int t = 0; t < 8; t++) {
            float p0 = __expf(S[t][0] - mn1);
            float p1 = __expf(S[t][1] - mn1);
            float p2 = __expf(S[t][2] - mn2);
            float p3 = __expf(S[t][3] - mn2);
            s1 += p0 + p1; s2 += p2 + p3;
            __half2 ph01 = __halves2half2(__float2half_rn(p0), __float2half_rn(p1));
            __half2 ph23 = __halves2half2(__float2half_rn(p2), __float2half_rn(p3));
            const int kt = t >> 1, hf = (t & 1) * 2;
            Pf[kt][hf + 0] = *(uint32_t*)&ph01;
            Pf[kt][hf + 1] = *(uint32_t*)&ph23;
        }
        s1 += __shfl_xor_sync(0xffffffffu, s1, 1);
        s1 += __shfl_xor_sync(0xffffffffu, s1, 2);
        s2 += __shfl_xor_sync(0xffffffffu, s2, 1);
        s2 += __shfl_xor_sync(0xffffffffu, s2, 2);
        l1 = l1 * cr1 + s1;
        l2 = l2 * cr2 + s2;
        #pragma unroll
        for (int t = 0; t < 8; t++) {
            O[t][0] *= cr1; O[t][1] *= cr1;
            O[t][2] *= cr2; O[t][3] *= cr2;
        }

        #pragma unroll
        for (int kt = 0; kt < 4; kt++) {
            #pragma unroll
            for (int nb = 0; nb < 4; nb++) {
                uint32_t t4[4];
                ldm4(t4, sVh + (nb * 16 + b_row) * ATS + kt * 16 + b_coff);
                uint32_t bv0[2] = { t4[0], t4[1] };
                uint32_t bv1[2] = { t4[2], t4[3] };
                mma_f32(O[2 * nb],     Pf[kt], bv0);
                mma_f32(O[2 * nb + 1], Pf[kt], bv1);
                ldm4(t4, sVl + (nb * 16 + b_row) * ATS + kt * 16 + b_coff);
                uint32_t bw0[2] = { t4[0], t4[1] };
                uint32_t bw1[2] = { t4[2], t4[3] };
                mma_f32(O[2 * nb],     Pf[kt], bw0);
                mma_f32(O[2 * nb + 1], Pf[kt], bw1);
            }
        }
    }

    const float inv1 = 1.f / l1, inv2 = 1.f / l2;
    const size_t row1 = base + (size_t)(qb * 64 + rl1) * DGPT;
    const size_t row2 = base + (size_t)(qb * 64 + rl1 + 8) * DGPT;
    #pragma unroll
    for (int t = 0; t < 8; t++) {
        const int col = t * 8 + cl0;
        *(__half2*)(yhi + row1 + col) =
            __halves2half2(__float2half_rn(O[t][0] * inv1), __float2half_rn(O[t][1] * inv1));
        *(__half2*)(yhi + row2 + col) =
            __halves2half2(__float2half_rn(O[t][2] * inv2), __float2half_rn(O[t][3] * inv2));
    }
}

// ---------------- launcher ----------------
static inline void convsplit(const float* in, __half* hi, __half* lo, size_t n)
{
    size_t n4 = n / 4;
    convsplit_kernel<<<(unsigned)((n4 + 255) / 256), 256>>>(in, hi, lo, n4);
}
static inline void convhi(const float* in, __half* hi, size_t n)
{
    size_t n4 = n / 4;
    convhi_kernel<<<(unsigned)((n4 + 255) / 256), 256>>>(in, hi, n4);
}

extern "C" void kernel_launch(void* const* d_in, const int* in_sizes, int n_in,
                              void* d_out, int out_size)
{
    const int*   idx    = (const int*)  d_in[0];
    const float* tok    = (const float*)d_in[1];
    const float* pos    = (const float*)d_in[2];
    const float* ln1_w  = (const float*)d_in[3];
    const float* ln1_b  = (const float*)d_in[4];
    const float* Wq     = (const float*)d_in[5];
    const float* bq     = (const float*)d_in[6];
    const float* Wk     = (const float*)d_in[7];
    const float* bk     = (const float*)d_in[8];
    const float* Wv     = (const float*)d_in[9];
    const float* bv     = (const float*)d_in[10];
    const float* Wproj  = (const float*)d_in[11];
    const float* bproj  = (const float*)d_in[12];
    const float* ln2_w  = (const float*)d_in[13];
    const float* ln2_b  = (const float*)d_in[14];
    const float* W1     = (const float*)d_in[15];
    const float* b1     = (const float*)d_in[16];
    const float* W2     = (const float*)d_in[17];
    const float* b2     = (const float*)d_in[18];
    const float* lnf_w  = (const float*)d_in[19];
    const float* lnf_b  = (const float*)d_in[20];
    const float* Wlogit = (const float*)d_in[21];
    const float* Wdev   = (const float*)d_in[22];
    float* out = (float*)d_out;

    float *xp, *qp, *kp, *vp;
    __half *whi, *wlo, *ahi, *alo, *fhi;
    cudaGetSymbolAddress((void**)&xp, g_x);
    cudaGetSymbolAddress((void**)&qp, g_q);
    cudaGetSymbolAddress((void**)&kp, g_k);
    cudaGetSymbolAddress((void**)&vp, g_v);
    cudaGetSymbolAddress((void**)&whi, g_whi);
    cudaGetSymbolAddress((void**)&wlo, g_wlo);
    cudaGetSymbolAddress((void**)&ahi, g_ahi);
    cudaGetSymbolAddress((void**)&alo, g_alo);
    cudaGetSymbolAddress((void**)&fhi, g_fhi);

    __half* qhi = (__half*)qp;  __half* qlo = qhi + (size_t)MGPT * DGPT;
    __half* khi = (__half*)kp;  __half* klo = khi + (size_t)MGPT * DGPT;
    __half* vhi = (__half*)vp;  __half* vlo = vhi + (size_t)MGPT * DGPT;

    cudaFuncSetAttribute((const void*)gemm_tc<0,1>, cudaFuncAttributeMaxDynamicSharedMemorySize, GS1);
    cudaFuncSetAttribute((const void*)gemm_tc<2,1>, cudaFuncAttributeMaxDynamicSharedMemorySize, GS1);
    cudaFuncSetAttribute((const void*)gemm_tc<3,3>, cudaFuncAttributeMaxDynamicSharedMemorySize, GS3);
    cudaFuncSetAttribute((const void*)gemm_w1,      cudaFuncAttributeMaxDynamicSharedMemorySize, GSW);
    cudaFuncSetAttribute((const void*)attn_mma,     cudaFuncAttributeMaxDynamicSharedMemorySize, ATT_SMEM);

    // layer weights: hi only; head weights: hi + lo
    convhi(Wq,    whi + O_WQ, SZ_WQ);
    convhi(Wk,    whi + O_WK, SZ_WQ);
    convhi(Wv,    whi + O_WV, SZ_WQ);
    convhi(Wproj, whi + O_WP, SZ_WQ);
    convhi(W1,    whi + O_W1, SZ_W1);
    convhi(W2,    whi + O_W2, SZ_W1);
    convsplit(Wlogit, whi + O_WLG, wlo + OL_WLG, SZ_HEAD);
    convsplit(Wdev,   whi + O_WDV, wlo + OL_WDV, SZ_HEAD);

    dim3 gD(DGPT / 128, MGPT / 128);
    dim3 gW(FGPT / 256, MGPT / 128);   // W1 BN=256
    dim3 gV(VGPT / 128, MGPT / 128);
    dim3 gA(BGPT * HGPT, TGPT / 64);

    embed_kernel<<<(MGPT * DGPT + 255) / 256, 256>>>(idx, tok, pos, xp);

    for (int l = 0; l < LGPT; l++) {
        size_t oD  = (size_t)l * DGPT * DGPT;
        size_t oF  = (size_t)l * FGPT * DGPT;
        size_t ob  = (size_t)l * DGPT;
        size_t obf = (size_t)l * FGPT;

        ln_kernel<0><<<MGPT, 256>>>(xp, ahi, nullptr, ln1_w + ob, ln1_b + ob);
        gemm_tc<0,1><<<gD, 256, GS1>>>(ahi, nullptr, whi + O_WQ + oD, nullptr,
                                       bq + ob, nullptr, nullptr, qhi, qlo, MGPT, DGPT, DGPT);
        gemm_tc<0,1><<<gD, 256, GS1>>>(ahi, nullptr, whi + O_WK + oD, nullptr,
                                       bk + ob, nullptr, nullptr, khi, klo, MGPT, DGPT, DGPT);
        gemm_tc<0,1><<<gD, 256, GS1>>>(ahi, nullptr, whi + O_WV + oD, nullptr,
                                       bv + ob, nullptr, nullptr, vhi, vlo, MGPT, DGPT, DGPT);
        attn_mma<<<gA, 128, ATT_SMEM>>>(qhi, qlo, khi, klo, vhi, vlo, ahi);
        gemm_tc<2,1><<<gD, 256, GS1>>>(ahi, nullptr, whi + O_WP + oD, nullptr,
                                       bproj + ob, xp, xp, nullptr, nullptr, MGPT, DGPT, DGPT);

        ln_kernel<0><<<MGPT, 256>>>(xp, ahi, nullptr, ln2_w + ob, ln2_b + ob);
        gemm_w1<<<gW, 256, GSW>>>(ahi, whi + O_W1 + oF, b1 + obf, fhi, MGPT, FGPT, DGPT);
        gemm_tc<2,1><<<gD, 256, GS1>>>(fhi, nullptr, whi + O_W2 + oF, nullptr,
                                       b2 + ob, xp, xp, nullptr, nullptr, MGPT, DGPT, FGPT);
    }

    ln_kernel<1><<<MGPT, 256>>>(xp, ahi, alo, lnf_w, lnf_b);
    gemm_tc<3,3><<<gV, 256, GS3>>>(ahi, alo, whi + O_WLG, wlo + OL_WLG,
                                   nullptr, nullptr, out, nullptr, nullptr, MGPT, VGPT, DGPT);
    gemm_tc<3,3><<<gV, 256, GS3>>>(ahi, alo, whi + O_WDV, wlo + OL_WDV,
                                   nullptr, nullptr, out + (size_t)MGPT * VGPT, nullptr, nullptr,
                                   MGPT, VGPT, DGPT);
}

// round 13
// speedup vs baseline: 5.9314x; 1.0266x over previous
#include <cuda_runtime.h>
#include <cuda_fp16.h>
#include <math.h>
#include <stdint.h>

// ---------------- problem constants ----------------
#define BGPT 4
#define TGPT 1024
#define DGPT 1024
#define HGPT 16
#define HDH  64
#define LGPT 8
#define VGPT 4096
#define MGPT (BGPT*TGPT)   // 4096 tokens
#define FGPT (4*DGPT)      // 4096 ff dim
#define QKVS (3*DGPT)      // fused qkv row stride (3072)

// weight layout (fp16 hi, element offsets)
#define DD    ((size_t)DGPT*DGPT)              // 1M
#define O_QKV ((size_t)0)                      // L * 3DD (per-layer contiguous q,k,v)
#define O_WP  ((size_t)LGPT*3*DD)              // 24M
#define O_W1  (O_WP + (size_t)LGPT*DD)         // 32M
#define O_W2  (O_W1 + (size_t)LGPT*4*DD)       // 64M
#define O_WLG (O_W2 + (size_t)LGPT*4*DD)       // 96M
#define O_WDV (O_WLG + 4*DD)                   // 100M (contiguous after Wlogit)
#define WTOT  (O_WDV + 4*DD)                   // 104M elems

// ---------------- scratch (device globals; no allocs allowed) ----------------
__device__ float  g_x[MGPT*DGPT];                   // residual stream (fp32)
__device__ __half g_qkvh[(size_t)MGPT*QKVS];        // fused qkv hi
__device__ __half g_qkvl[(size_t)MGPT*QKVS];        // fused qkv lo
__device__ __half g_ahi[(size_t)MGPT*DGPT];         // activation hi
__device__ __half g_alo[(size_t)MGPT*DGPT];         // activation lo (final LN only)
__device__ __half g_fhi[(size_t)MGPT*FGPT];         // ff activation hi
__device__ __half g_whi[WTOT];                      // weights hi

// ---------------- helpers ----------------
__device__ __forceinline__ void split_f16(float v, __half& h, __half& l)
{
    h = __float2half_rn(v);
    l = __float2half_rn(v - __half2float(h));
}

// ---------------- embedding ----------------
__global__ void embed_kernel(const int* __restrict__ idx,
                             const float* __restrict__ tok,
                             const float* __restrict__ pos,
                             float* __restrict__ x)
{
    int i = blockIdx.x * blockDim.x + threadIdx.x;
    if (i >= MGPT * DGPT) return;
    int row = i / DGPT;
    int d   = i - row * DGPT;
    int t   = row & (TGPT - 1);
    x[i] = tok[(size_t)idx[row] * DGPT + d] + pos[(size_t)t * DGPT + d];
}

// ---------------- fp32 -> fp16 hi (generic) ----------------
__global__ void __launch_bounds__(256) convhi_kernel(const float* __restrict__ in,
                                                     __half* __restrict__ hi,
                                                     size_t n4)
{
    size_t i = (size_t)blockIdx.x * blockDim.x + threadIdx.x;
    if (i >= n4) return;
    size_t e = i * 4;
    float4 v = *(const float4*)(in + e);
    __half2 h01 = __halves2half2(__float2half_rn(v.x), __float2half_rn(v.y));
    __half2 h23 = __halves2half2(__float2half_rn(v.z), __float2half_rn(v.w));
    uint2 ho;
    ho.x = *(uint32_t*)&h01; ho.y = *(uint32_t*)&h23;
    *(uint2*)(hi + e) = ho;
}

// ---------------- fp32 -> fp16 hi, scattered into fused QKV layout ----------
// in: [L, D, D] (one of Wq/Wk/Wv); out layer block l*3DD, sub-block `which`.
__global__ void __launch_bounds__(256) convqkv_kernel(const float* __restrict__ in,
                                                      __half* __restrict__ hi,
                                                      int which, size_t n4)
{
    size_t i = (size_t)blockIdx.x * blockDim.x + threadIdx.x;
    if (i >= n4) return;
    size_t e = i * 4;
    size_t layer = e / DD;
    size_t rem   = e - layer * DD;
    size_t de    = layer * 3 * DD + (size_t)which * DD + rem;
    float4 v = *(const float4*)(in + e);
    __half2 h01 = __halves2half2(__float2half_rn(v.x), __float2half_rn(v.y));
    __half2 h23 = __halves2half2(__float2half_rn(v.z), __float2half_rn(v.w));
    uint2 ho;
    ho.x = *(uint32_t*)&h01; ho.y = *(uint32_t*)&h23;
    *(uint2*)(hi + de) = ho;
}

// ---------------- layernorm: fp32 in -> fp16 hi (+lo) out ----------------
template<int WLO>
__global__ void __launch_bounds__(256) ln_kernel(const float* __restrict__ in,
                                                 __half* __restrict__ ohi,
                                                 __half* __restrict__ olo,
                                                 const float* __restrict__ w,
                                                 const float* __restrict__ b)
{
    int row = blockIdx.x;
    const float* x = in + (size_t)row * DGPT;
    int tid = threadIdx.x;
    __shared__ float red[8];

    float s = 0.f;
    for (int d = tid; d < DGPT; d += 256) s += x[d];
    #pragma unroll
    for (int o = 16; o; o >>= 1) s += __shfl_xor_sync(0xffffffffu, s, o);
    if ((tid & 31) == 0) red[tid >> 5] = s;
    __syncthreads();
    if (tid < 32) {
        float v = (tid < 8) ? red[tid] : 0.f;
        #pragma unroll
        for (int o = 4; o; o >>= 1) v += __shfl_xor_sync(0xffffffffu, v, o);
        if (tid == 0) red[0] = v;
    }
    __syncthreads();
    float mean = red[0] * (1.f / DGPT);

    float q = 0.f;
    for (int d = tid; d < DGPT; d += 256) { float t = x[d] - mean; q += t * t; }
    __syncthreads();
    #pragma unroll
    for (int o = 16; o; o >>= 1) q += __shfl_xor_sync(0xffffffffu, q, o);
    if ((tid & 31) == 0) red[tid >> 5] = q;
    __syncthreads();
    if (tid < 32) {
        float v = (tid < 8) ? red[tid] : 0.f;
        #pragma unroll
        for (int o = 4; o; o >>= 1) v += __shfl_xor_sync(0xffffffffu, v, o);
        if (tid == 0) red[0] = v;
    }
    __syncthreads();
    float rstd = rsqrtf(red[0] * (1.f / DGPT) + 1e-5f);

    for (int d = tid; d < DGPT; d += 256) {
        float v = (x[d] - mean) * rstd * w[d] + b[d];
        __half h, l;
        split_f16(v, h, l);
        ohi[(size_t)row * DGPT + d] = h;
        if (WLO) olo[(size_t)row * DGPT + d] = l;
    }
}

// ---------------- tensor-core helpers ----------------
__device__ __forceinline__ void ldm4(uint32_t r[4], const __half* p)
{
    uint32_t a = (uint32_t)__cvta_generic_to_shared(p);
    asm volatile("ldmatrix.sync.aligned.m8n8.x4.shared.b16 {%0,%1,%2,%3}, [%4];\n"
                 : "=r"(r[0]), "=r"(r[1]), "=r"(r[2]), "=r"(r[3]) : "r"(a));
}
__device__ __forceinline__ void mma_f32(float c[4], const uint32_t a[4], const uint32_t b[2])
{
    asm volatile(
        "mma.sync.aligned.m16n8k16.row.col.f32.f16.f16.f32 "
        "{%0,%1,%2,%3}, {%4,%5,%6,%7}, {%8,%9}, {%0,%1,%2,%3};\n"
        : "+f"(c[0]), "+f"(c[1]), "+f"(c[2]), "+f"(c[3])
        : "r"(a[0]), "r"(a[1]), "r"(a[2]), "r"(a[3]), "r"(b[0]), "r"(b[1]));
}

#define BKg 32
#define PK  40
#define SMBUF (128*PK)
#define SMMAT (2*SMBUF)
#define GS1 (2*SMMAT*2)   // 40960 B  (Ah, Bh)
#define GS2 (3*SMMAT*2)   // 61440 B  (Ah, Al, Bh)

// ---------------- GEMM (1-term): C[M,N] = Ahi @ Whi^T ----------------
// MODE: 2 = +bias +res, fp32 out
template<int MODE>
__global__ void __launch_bounds__(256) gemm_tc(
    const __half* __restrict__ Ahi,
    const __half* __restrict__ Whi,
    const float* __restrict__ bias, const float* __restrict__ res,
    float* __restrict__ C,
    int M, int N, int K)
{
    extern __shared__ __align__(16) __half sm[];
    __half* sAh = sm;
    __half* sBh = sm + SMMAT;

    const int tid  = threadIdx.x;
    const int lane = tid & 31;
    const int wid  = tid >> 5;
    const int wm   = wid >> 2;
    const int wn   = wid & 3;
    const int bm   = blockIdx.y * 128;
    const int bn   = blockIdx.x * 128;

    const int lrow = tid >> 1;
    const int lcol = (tid & 1) << 4;
    const __half* gAh = Ahi + (size_t)(bm + lrow) * K + lcol;
    const __half* gBh = Whi + (size_t)(bn + lrow) * K + lcol;

    const int a_r = wm * 64 + (lane & 15);
    const int a_c = (lane >> 4) * 8;
    const int b_r = wn * 32 + (lane >> 4) * 8 + (lane & 7);
    const int b_c = ((lane >> 3) & 1) * 8;

    float acc[4][4][4];
    #pragma unroll
    for (int mi = 0; mi < 4; mi++)
        #pragma unroll
        for (int ni = 0; ni < 4; ni++)
            #pragma unroll
            for (int r = 0; r < 4; r++) acc[mi][ni][r] = 0.f;

    uint4 rAh0, rAh1, rBh0, rBh1;

    const int NS = K / BKg;
    rAh0 = *(const uint4*)(gAh);     rAh1 = *(const uint4*)(gAh + 8);
    rBh0 = *(const uint4*)(gBh);     rBh1 = *(const uint4*)(gBh + 8);
    {
        __half* p = sAh + lrow * PK + lcol;
        *(uint4*)p = rAh0; *(uint4*)(p + 8) = rAh1;
        p = sBh + lrow * PK + lcol;
        *(uint4*)p = rBh0; *(uint4*)(p + 8) = rBh1;
    }
    __syncthreads();

    for (int s = 0; s < NS; s++) {
        if (s + 1 < NS) {
            int k0 = (s + 1) * BKg;
            rAh0 = *(const uint4*)(gAh + k0);  rAh1 = *(const uint4*)(gAh + k0 + 8);
            rBh0 = *(const uint4*)(gBh + k0);  rBh1 = *(const uint4*)(gBh + k0 + 8);
        }

        const int bo = (s & 1) * SMBUF;
        #pragma unroll
        for (int ks = 0; ks < 2; ks++) {
            const int k0 = ks * 16;
            uint32_t afh[4][4];
            #pragma unroll
            for (int mi = 0; mi < 4; mi++)
                ldm4(afh[mi], sAh + bo + (a_r + mi * 16) * PK + k0 + a_c);
            uint32_t bfh[4][2];
            #pragma unroll
            for (int np = 0; np < 2; np++) {
                uint32_t t[4];
                ldm4(t, sBh + bo + (b_r + np * 16) * PK + k0 + b_c);
                bfh[np * 2][0] = t[0]; bfh[np * 2][1] = t[1];
                bfh[np * 2 + 1][0] = t[2]; bfh[np * 2 + 1][1] = t[3];
            }
            #pragma unroll
            for (int mi = 0; mi < 4; mi++)
                #pragma unroll
                for (int ni = 0; ni < 4; ni++)
                    mma_f32(acc[mi][ni], afh[mi], bfh[ni]);
        }

        if (s + 1 < NS) {
            const int bo2 = ((s + 1) & 1) * SMBUF;
            __half* p = sAh + bo2 + lrow * PK + lcol;
            *(uint4*)p = rAh0; *(uint4*)(p + 8) = rAh1;
            p = sBh + bo2 + lrow * PK + lcol;
            *(uint4*)p = rBh0; *(uint4*)(p + 8) = rBh1;
            __syncthreads();
        }
    }

    const int er = bm + wm * 64 + (lane >> 2);
    const int ec = bn + wn * 32 + (lane & 3) * 2;
    #pragma unroll
    for (int mi = 0; mi < 4; mi++) {
        #pragma unroll
        for (int ni = 0; ni < 4; ni++) {
            const int col = ec + ni * 8;
            #pragma unroll
            for (int h = 0; h < 2; h++) {
                const size_t row = (size_t)(er + mi * 16 + h * 8);
                float v0 = acc[mi][ni][h * 2]     + bias[col];
                float v1 = acc[mi][ni][h * 2 + 1] + bias[col + 1];
                if (MODE == 2) {
                    v0 += res[row * N + col];
                    v1 += res[row * N + col + 1];
                }
                float2 o; o.x = v0; o.y = v1;
                *(float2*)(C + row * N + col) = o;
            }
        }
    }
}

// ---------------- fused QKV GEMM: [M,3072] = Ahi @ Wqkv^T, fp16 hi/lo out ----
__global__ void __launch_bounds__(256) gemm_qkv(
    const __half* __restrict__ Ahi,
    const __half* __restrict__ Wf,      // fused [3072, 1024]
    const float* __restrict__ bq, const float* __restrict__ bk,
    const float* __restrict__ bv,
    __half* __restrict__ Chi, __half* __restrict__ Clo)
{
    extern __shared__ __align__(16) __half sm[];
    __half* sAh = sm;
    __half* sBh = sm + SMMAT;

    const int K = DGPT;
    const int tid  = threadIdx.x;
    const int lane = tid & 31;
    const int wid  = tid >> 5;
    const int wm   = wid >> 2;
    const int wn   = wid & 3;
    const int bm   = blockIdx.y * 128;
    const int bn   = blockIdx.x * 128;

    const int tsel = bn >> 10;
    const float* bias = (tsel == 0) ? bq : ((tsel == 1) ? bk : bv);
    const int cb = bn - (tsel << 10);

    const int lrow = tid >> 1;
    const int lcol = (tid & 1) << 4;
    const __half* gAh = Ahi + (size_t)(bm + lrow) * K + lcol;
    const __half* gBh = Wf  + (size_t)(bn + lrow) * K + lcol;

    const int a_r = wm * 64 + (lane & 15);
    const int a_c = (lane >> 4) * 8;
    const int b_r = wn * 32 + (lane >> 4) * 8 + (lane & 7);
    const int b_c = ((lane >> 3) & 1) * 8;

    float acc[4][4][4];
    #pragma unroll
    for (int mi = 0; mi < 4; mi++)
        #pragma unroll
        for (int ni = 0; ni < 4; ni++)
            #pragma unroll
            for (int r = 0; r < 4; r++) acc[mi][ni][r] = 0.f;

    uint4 rAh0, rAh1, rBh0, rBh1;
    const int NS = K / BKg;
    rAh0 = *(const uint4*)(gAh);     rAh1 = *(const uint4*)(gAh + 8);
    rBh0 = *(const uint4*)(gBh);     rBh1 = *(const uint4*)(gBh + 8);
    {
        __half* p = sAh + lrow * PK + lcol;
        *(uint4*)p = rAh0; *(uint4*)(p + 8) = rAh1;
        p = sBh + lrow * PK + lcol;
        *(uint4*)p = rBh0; *(uint4*)(p + 8) = rBh1;
    }
    __syncthreads();

    for (int s = 0; s < NS; s++) {
        if (s + 1 < NS) {
            int k0 = (s + 1) * BKg;
            rAh0 = *(const uint4*)(gAh + k0);  rAh1 = *(const uint4*)(gAh + k0 + 8);
            rBh0 = *(const uint4*)(gBh + k0);  rBh1 = *(const uint4*)(gBh + k0 + 8);
        }
        const int bo = (s & 1) * SMBUF;
        #pragma unroll
        for (int ks = 0; ks < 2; ks++) {
            const int k0 = ks * 16;
            uint32_t afh[4][4];
            #pragma unroll
            for (int mi = 0; mi < 4; mi++)
                ldm4(afh[mi], sAh + bo + (a_r + mi * 16) * PK + k0 + a_c);
            uint32_t bfh[4][2];
            #pragma unroll
            for (int np = 0; np < 2; np++) {
                uint32_t t[4];
                ldm4(t, sBh + bo + (b_r + np * 16) * PK + k0 + b_c);
                bfh[np * 2][0] = t[0]; bfh[np * 2][1] = t[1];
                bfh[np * 2 + 1][0] = t[2]; bfh[np * 2 + 1][1] = t[3];
            }
            #pragma unroll
            for (int mi = 0; mi < 4; mi++)
                #pragma unroll
                for (int ni = 0; ni < 4; ni++)
                    mma_f32(acc[mi][ni], afh[mi], bfh[ni]);
        }
        if (s + 1 < NS) {
            const int bo2 = ((s + 1) & 1) * SMBUF;
            __half* p = sAh + bo2 + lrow * PK + lcol;
            *(uint4*)p = rAh0; *(uint4*)(p + 8) = rAh1;
            p = sBh + bo2 + lrow * PK + lcol;
            *(uint4*)p = rBh0; *(uint4*)(p + 8) = rBh1;
            __syncthreads();
        }
    }

    const int er  = bm + wm * 64 + (lane >> 2);
    const int ecl = cb + wn * 32 + (lane & 3) * 2;   // local col (bias)
    const int ecg = bn + wn * 32 + (lane & 3) * 2;   // fused col (output)
    #pragma unroll
    for (int mi = 0; mi < 4; mi++) {
        #pragma unroll
        for (int ni = 0; ni < 4; ni++) {
            const int coll = ecl + ni * 8;
            const int colg = ecg + ni * 8;
            const float b0 = bias[coll], b1 = bias[coll + 1];
            #pragma unroll
            for (int h = 0; h < 2; h++) {
                const size_t row = (size_t)(er + mi * 16 + h * 8);
                float v0 = acc[mi][ni][h * 2]     + b0;
                float v1 = acc[mi][ni][h * 2 + 1] + b1;
                __half h0, l0, h1, l1;
                split_f16(v0, h0, l0);
                split_f16(v1, h1, l1);
                *(__half2*)(Chi + row * QKVS + colg) = __halves2half2(h0, h1);
                *(__half2*)(Clo + row * QKVS + colg) = __halves2half2(l0, l1);
            }
        }
    }
}

// ---------------- fused heads GEMM: 2-term (Ahi+Alo) @ Whi^T, fp32 out ------
// N covers Wlogit(4096) ‖ Wdev(4096); out split between the two tensors.
__global__ void __launch_bounds__(256) gemm_heads(
    const __half* __restrict__ Ahi, const __half* __restrict__ Alo,
    const __half* __restrict__ Whi,    // [8192, 1024]
    float* __restrict__ out)
{
    extern __shared__ __align__(16) __half sm[];
    __half* sAh = sm;
    __half* sAl = sm + SMMAT;
    __half* sBh = sm + 2 * SMMAT;

    const int K = DGPT;
    const int tid  = threadIdx.x;
    const int lane = tid & 31;
    const int wid  = tid >> 5;
    const int wm   = wid >> 2;
    const int wn   = wid & 3;
    const int bm   = blockIdx.y * 128;
    const int bn   = blockIdx.x * 128;

    const int tsel = bn >> 12;
    float* C = out + (size_t)tsel * MGPT * VGPT;
    const int cb = bn - (tsel << 12);

    const int lrow = tid >> 1;
    const int lcol = (tid & 1) << 4;
    const __half* gAh = Ahi + (size_t)(bm + lrow) * K + lcol;
    const __half* gAl = Alo + (size_t)(bm + lrow) * K + lcol;
    const __half* gBh = Whi + (size_t)(bn + lrow) * K + lcol;

    const int a_r = wm * 64 + (lane & 15);
    const int a_c = (lane >> 4) * 8;
    const int b_r = wn * 32 + (lane >> 4) * 8 + (lane & 7);
    const int b_c = ((lane >> 3) & 1) * 8;

    float acc[4][4][4];
    #pragma unroll
    for (int mi = 0; mi < 4; mi++)
        #pragma unroll
        for (int ni = 0; ni < 4; ni++)
            #pragma unroll
            for (int r = 0; r < 4; r++) acc[mi][ni][r] = 0.f;

    uint4 rAh0, rAh1, rAl0, rAl1, rBh0, rBh1;
    const int NS = K / BKg;
    rAh0 = *(const uint4*)(gAh);  rAh1 = *(const uint4*)(gAh + 8);
    rAl0 = *(const uint4*)(gAl);  rAl1 = *(const uint4*)(gAl + 8);
    rBh0 = *(const uint4*)(gBh);  rBh1 = *(const uint4*)(gBh + 8);
    {
        __half* p = sAh + lrow * PK + lcol;
        *(uint4*)p = rAh0; *(uint4*)(p + 8) = rAh1;
        p = sAl + lrow * PK + lcol;
        *(uint4*)p = rAl0; *(uint4*)(p + 8) = rAl1;
        p = sBh + lrow * PK + lcol;
        *(uint4*)p = rBh0; *(uint4*)(p + 8) = rBh1;
    }
    __syncthreads();

    for (int s = 0; s < NS; s++) {
        if (s + 1 < NS) {
            int k0 = (s + 1) * BKg;
            rAh0 = *(const uint4*)(gAh + k0);  rAh1 = *(const uint4*)(gAh + k0 + 8);
            rAl0 = *(const uint4*)(gAl + k0);  rAl1 = *(const uint4*)(gAl + k0 + 8);
            rBh0 = *(const uint4*)(gBh + k0);  rBh1 = *(const uint4*)(gBh + k0 + 8);
        }
        const int bo = (s & 1) * SMBUF;
        #pragma unroll
        for (int ks = 0; ks < 2; ks++) {
            const int k0 = ks * 16;
            uint32_t bfh[4][2];
            #pragma unroll
            for (int np = 0; np < 2; np++) {
                uint32_t t[4];
                ldm4(t, sBh + bo + (b_r + np * 16) * PK + k0 + b_c);
                bfh[np * 2][0] = t[0]; bfh[np * 2][1] = t[1];
                bfh[np * 2 + 1][0] = t[2]; bfh[np * 2 + 1][1] = t[3];
            }
            uint32_t af[4][4];
            #pragma unroll
            for (int mi = 0; mi < 4; mi++)
                ldm4(af[mi], sAh + bo + (a_r + mi * 16) * PK + k0 + a_c);
            #pragma unroll
            for (int mi = 0; mi < 4; mi++)
                #pragma unroll
                for (int ni = 0; ni < 4; ni++)
                    mma_f32(acc[mi][ni], af[mi], bfh[ni]);
            #pragma unroll
            for (int mi = 0; mi < 4; mi++)
                ldm4(af[mi], sAl + bo + (a_r + mi * 16) * PK + k0 + a_c);
            #pragma unroll
            for (int mi = 0; mi < 4; mi++)
                #pragma unroll
                for (int ni = 0; ni < 4; ni++)
                    mma_f32(acc[mi][ni], af[mi], bfh[ni]);
        }
        if (s + 1 < NS) {
            const int bo2 = ((s + 1) & 1) * SMBUF;
            __half* p = sAh + bo2 + lrow * PK + lcol;
            *(uint4*)p = rAh0; *(uint4*)(p + 8) = rAh1;
            p = sAl + bo2 + lrow * PK + lcol;
            *(uint4*)p = rAl0; *(uint4*)(p + 8) = rAl1;
            p = sBh + bo2 + lrow * PK + lcol;
            *(uint4*)p = rBh0; *(uint4*)(p + 8) = rBh1;
            __syncthreads();
        }
    }

    const int er = bm + wm * 64 + (lane >> 2);
    const int ec = cb + wn * 32 + (lane & 3) * 2;
    #pragma unroll
    for (int mi = 0; mi < 4; mi++) {
        #pragma unroll
        for (int ni = 0; ni < 4; ni++) {
            const int col = ec + ni * 8;
            #pragma unroll
            for (int h = 0; h < 2; h++) {
                const size_t row = (size_t)(er + mi * 16 + h * 8);
                float2 o;
                o.x = acc[mi][ni][h * 2];
                o.y = acc[mi][ni][h * 2 + 1];
                *(float2*)(C + row * VGPT + col) = o;
            }
        }
    }
}

// ---------------- GEMM (BN=256, warp 64x64) for W1: GELU, fp16 hi out ------
#define W1_SA (128*PK)
#define W1_SB (256*PK)
#define W1_STG (W1_SA + W1_SB)
#define GSW (2*W1_STG*2)   // 61440 bytes

__global__ void __launch_bounds__(256) gemm_w1(
    const __half* __restrict__ Ahi, const __half* __restrict__ Whi,
    const float* __restrict__ bias, __half* __restrict__ Chi,
    int M, int N, int K)
{
    extern __shared__ __align__(16) __half sm[];

    const int tid  = threadIdx.x;
    const int lane = tid & 31;
    const int wid  = tid >> 5;
    const int wm   = wid >> 2;
    const int wn   = wid & 3;
    const int bm   = blockIdx.y * 128;
    const int bn   = blockIdx.x * 256;

    const int lrow = tid >> 1;
    const int lcol = (tid & 1) << 4;
    const __half* gA  = Ahi + (size_t)(bm + lrow) * K + lcol;
    const __half* gB0 = Whi + (size_t)(bn + lrow) * K + lcol;
    const __half* gB1 = Whi + (size_t)(bn + 128 + lrow) * K + lcol;

    const int a_r = wm * 64 + (lane & 15);
    const int a_c = (lane >> 4) * 8;
    const int b_r = wn * 64 + (lane >> 4) * 8 + (lane & 7);
    const int b_c = ((lane >> 3) & 1) * 8;

    float acc[4][8][4];
    #pragma unroll
    for (int mi = 0; mi < 4; mi++)
        #pragma unroll
        for (int ni = 0; ni < 8; ni++)
            #pragma unroll
            for (int r = 0; r < 4; r++) acc[mi][ni][r] = 0.f;

    uint4 rA0, rA1, rB00, rB01, rB10, rB11;

    const int NS = K / BKg;
    rA0  = *(const uint4*)(gA);      rA1  = *(const uint4*)(gA + 8);
    rB00 = *(const uint4*)(gB0);     rB01 = *(const uint4*)(gB0 + 8);
    rB10 = *(const uint4*)(gB1);     rB11 = *(const uint4*)(gB1 + 8);
    {
        __half* p = sm + lrow * PK + lcol;
        *(uint4*)p = rA0; *(uint4*)(p + 8) = rA1;
        p = sm + W1_SA + lrow * PK + lcol;
        *(uint4*)p = rB00; *(uint4*)(p + 8) = rB01;
        p = sm + W1_SA + (128 + lrow) * PK + lcol;
        *(uint4*)p = rB10; *(uint4*)(p + 8) = rB11;
    }
    __syncthreads();

    for (int s = 0; s < NS; s++) {
        if (s + 1 < NS) {
            int k0 = (s + 1) * BKg;
            rA0  = *(const uint4*)(gA + k0);   rA1  = *(const uint4*)(gA + k0 + 8);
            rB00 = *(const uint4*)(gB0 + k0);  rB01 = *(const uint4*)(gB0 + k0 + 8);
            rB10 = *(const uint4*)(gB1 + k0);  rB11 = *(const uint4*)(gB1 + k0 + 8);
        }

        const __half* stg = sm + (s & 1) * W1_STG;
        const __half* sA = stg;
        const __half* sB = stg + W1_SA;
        #pragma unroll
        for (int ks = 0; ks < 2; ks++) {
            const int k0 = ks * 16;
            uint32_t af[4][4];
            #pragma unroll
            for (int mi = 0; mi < 4; mi++)
                ldm4(af[mi], sA + (a_r + mi * 16) * PK + k0 + a_c);
            uint32_t bf[8][2];
            #pragma unroll
            for (int nb = 0; nb < 4; nb++) {
                uint32_t t[4];
                ldm4(t, sB + (b_r + nb * 16) * PK + k0 + b_c);
                bf[nb * 2][0] = t[0]; bf[nb * 2][1] = t[1];
                bf[nb * 2 + 1][0] = t[2]; bf[nb * 2 + 1][1] = t[3];
            }
            #pragma unroll
            for (int mi = 0; mi < 4; mi++)
                #pragma unroll
                for (int ni = 0; ni < 8; ni++)
                    mma_f32(acc[mi][ni], af[mi], bf[ni]);
        }

        if (s + 1 < NS) {
            __half* stg2 = sm + ((s + 1) & 1) * W1_STG;
            __half* p = stg2 + lrow * PK + lcol;
            *(uint4*)p = rA0; *(uint4*)(p + 8) = rA1;
            p = stg2 + W1_SA + lrow * PK + lcol;
            *(uint4*)p = rB00; *(uint4*)(p + 8) = rB01;
            p = stg2 + W1_SA + (128 + lrow) * PK + lcol;
            *(uint4*)p = rB10; *(uint4*)(p + 8) = rB11;
            __syncthreads();
        }
    }

    const int er = bm + wm * 64 + (lane >> 2);
    const int ec = bn + wn * 64 + (lane & 3) * 2;
    #pragma unroll
    for (int mi = 0; mi < 4; mi++) {
        #pragma unroll
        for (int ni = 0; ni < 8; ni++) {
            const int col = ec + ni * 8;
            const float b0 = bias[col], b1 = bias[col + 1];
            #pragma unroll
            for (int h = 0; h < 2; h++) {
                const size_t row = (size_t)(er + mi * 16 + h * 8);
                float v0 = acc[mi][ni][h * 2]     + b0;
                float v1 = acc[mi][ni][h * 2 + 1] + b1;
                v0 = 0.5f * v0 * (1.f + erff(v0 * 0.70710678118654752f));
                v1 = 0.5f * v1 * (1.f + erff(v1 * 0.70710678118654752f));
                *(__half2*)(Chi + row * N + col) =
                    __halves2half2(__float2half_rn(v0), __float2half_rn(v1));
            }
        }
    }
}

// ---------------- tensor-core flash attention (fused QKV input) ------------
#define ATS 72
#define ATT_SMEM (6*64*ATS*2)   // 55296 B

__global__ void __launch_bounds__(128) attn_mma(
    const __half* __restrict__ qkvh, const __half* __restrict__ qkvl,
    __half* __restrict__ yhi)
{
    extern __shared__ __align__(16) __half sa[];
    __half* sQh = sa;
    __half* sQl = sa + 64 * ATS;
    __half* sKh = sa + 2 * 64 * ATS;
    __half* sKl = sa + 3 * 64 * ATS;
    __half* sVh = sa + 4 * 64 * ATS;    // transposed: [d][kv]
    __half* sVl = sa + 5 * 64 * ATS;

    const int bh = blockIdx.x;
    const int b  = bh / HGPT;
    const int h  = bh % HGPT;
    const int qb = blockIdx.y;
    const int tid  = threadIdx.x;
    const int w    = tid >> 5;
    const int lane = tid & 31;

    const size_t rowb = (size_t)(b * TGPT);
    const int hoff = h * HDH;

    // Q tile (64x64, hi+lo) from fused buffer (q at col offset 0)
    for (int f = tid; f < 512; f += 128) {
        int r = f >> 3, c8 = (f & 7) * 8;
        size_t g = (rowb + qb * 64 + r) * QKVS + hoff + c8;
        *(uint4*)(sQh + r * ATS + c8) = *(const uint4*)(qkvh + g);
        *(uint4*)(sQl + r * ATS + c8) = *(const uint4*)(qkvl + g);
    }

    float O[8][4];
    #pragma unroll
    for (int t = 0; t < 8; t++)
        #pragma unroll
        for (int r = 0; r < 4; r++) O[t][r] = 0.f;
    float m1 = -1e30f, m2 = -1e30f, l1 = 0.f, l2 = 0.f;

    const int a_row  = w * 16 + (lane & 15);
    const int a_coff = (lane >> 4) * 8;
    const int b_row  = (lane >> 4) * 8 + (lane & 7);
    const int b_coff = ((lane >> 3) & 1) * 8;
    const int rl1 = w * 16 + (lane >> 2);
    const int cl0 = 2 * (lane & 3);

    const int nch = qb + 1;
    for (int ch = 0; ch < nch; ch++) {
        const int j0 = ch * 64;
        __syncthreads();
        for (int f = tid; f < 512; f += 128) {
            int r = f >> 3, c8 = (f & 7) * 8;
            size_t g = (rowb + j0 + r) * QKVS + DGPT + hoff + c8;   // k at +1024
            *(uint4*)(sKh + r * ATS + c8) = *(const uint4*)(qkvh + g);
            *(uint4*)(sKl + r * ATS + c8) = *(const uint4*)(qkvl + g);
        }
        for (int f = tid; f < 1024; f += 128) {
            int r = f >> 4, c4 = (f & 15) * 4;
            size_t g = (rowb + j0 + r) * QKVS + 2 * DGPT + hoff + c4;  // v at +2048
            uint2 hv = *(const uint2*)(qkvh + g);
            uint2 lv = *(const uint2*)(qkvl + g);
            __half2 h01 = *(__half2*)&hv.x, h23 = *(__half2*)&hv.y;
            __half2 l01 = *(__half2*)&lv.x, l23 = *(__half2*)&lv.y;
            sVh[(c4 + 0) * ATS + r] = __low2half(h01);
            sVh[(c4 + 1) * ATS + r] = __high2half(h01);
            sVh[(c4 + 2) * ATS + r] = __low2half(h23);
            sVh[(c4 + 3) * ATS + r] = __high2half(h23);
            sVl[(c4 + 0) * ATS + r] = __low2half(l01);
            sVl[(c4 + 1) * ATS + r] = __high2half(l01);
            sVl[(c4 + 2) * ATS + r] = __low2half(l23);
            sVl[(c4 + 3) * ATS + r] = __high2half(l23);
        }
        __syncthreads();

        float S[8][4];
        #pragma unroll
        for (int t = 0; t < 8; t++)
            #pragma unroll
            for (int r = 0; r < 4; r++) S[t][r] = 0.f;

        #pragma unroll
        for (int ks = 0; ks < 4; ks++) {
            uint32_t aqh[4], aql[4];
            ldm4(aqh, sQh + a_row * ATS + ks * 16 + a_coff);
            ldm4(aql, sQl + a_row * ATS + ks * 16 + a_coff);
            #pragma unroll
            for (int nb = 0; nb < 4; nb++) {
                uint32_t t4[4];
                ldm4(t4, sKh + (nb * 16 + b_row) * ATS + ks * 16 + b_coff);
                uint32_t bh0[2] = { t4[0], t4[1] };
                uint32_t bh1[2] = { t4[2], t4[3] };
                ldm4(t4, sKl + (nb * 16 + b_row) * ATS + ks * 16 + b_coff);
                uint32_t bl0[2] = { t4[0], t4[1] };
                uint32_t bl1[2] = { t4[2], t4[3] };
                mma_f32(S[2 * nb],     aqh, bh0);
                mma_f32(S[2 * nb + 1], aqh, bh1);
                mma_f32(S[2 * nb],     aqh, bl0);
                mma_f32(S[2 * nb + 1], aqh, bl1);
                mma_f32(S[2 * nb],     aql, bh0);
                mma_f32(S[2 * nb + 1], aql, bh1);
            }
        }

        const bool diag = (ch == qb);
        #pragma unroll
        for (int t = 0; t < 8; t++) {
            S[t][0] *= 0.125f; S[t][1] *= 0.125f;
            S[t][2] *= 0.125f; S[t][3] *= 0.125f;
            if (diag) {
                int c0 = t * 8 + cl0, c1 = c0 + 1;
                if (c0 > rl1)     S[t][0] = -1e30f;
                if (c1 > rl1)     S[t][1] = -1e30f;
                if (c0 > rl1 + 8) S[t][2] = -1e30f;
                if (c1 > rl1 + 8) S[t][3] = -1e30f;
            }
        }

        float mx1 = -1e30f, mx2 = -1e30f;
        #pragma unroll
        for (int t = 0; t < 8; t++) {
            mx1 = fmaxf(mx1, fmaxf(S[t][0], S[t][1]));
            mx2 = fmaxf(mx2, fmaxf(S[t][2], S[t][3]));
        }
        mx1 = fmaxf(mx1, __shfl_xor_sync(0xffffffffu, mx1, 1));
        mx1 = fmaxf(mx1, __shfl_xor_sync(0xffffffffu, mx1, 2));
        mx2 = fmaxf(mx2, __shfl_xor_sync(0xffffffffu, mx2, 1));
        mx2 = fmaxf(mx2, __shfl_xor_sync(0xffffffffu, mx2, 2));

        float mn1 = fmaxf(m1, mx1), mn2 = fmaxf(m2, mx2);
        float cr1 = __expf(m1 - mn1), cr2 = __expf(m2 - mn2);
        m1 = mn1; m2 = mn2;

        float s1 = 0.f, s2 = 0.f;
        uint32_t Pf[4][4];
        #pragma unroll
        for (int t = 0; t < 8; t++) {
            float p0 = __expf(S[t][0] - mn1);
            float p1 = __expf(S[t][1] - mn1);
            float p2 = __expf(S[t][2] - mn2);
            float p3 = __expf(S[t][3] - mn2);
            s1 += p0 + p1; s2 += p2 + p3;
            __half2 ph01 = __halves2half2(__float2half_rn(p0), __float2half_rn(p1));
            __half2 ph23 = __halves2half2(__float2half_rn(p2), __float2half_rn(p3));
            const int kt = t >> 1, hf = (t & 1) * 2;
            Pf[kt][hf + 0] = *(uint32_t*)&ph01;
            Pf[kt][hf + 1] = *(uint32_t*)&ph23;
        }
        s1 += __shfl_xor_sync(0xffffffffu, s1, 1);
        s1 += __shfl_xor_sync(0xffffffffu, s1, 2);
        s2 += __shfl_xor_sync(0xffffffffu, s2, 1);
        s2 += __shfl_xor_sync(0xffffffffu, s2, 2);
        l1 = l1 * cr1 + s1;
        l2 = l2 * cr2 + s2;
        #pragma unroll
        for (int t = 0; t < 8; t++) {
            O[t][0] *= cr1; O[t][1] *= cr1;
            O[t][2] *= cr2; O[t][3] *= cr2;
        }

        #pragma unroll
        for (int kt = 0; kt < 4; kt++) {
            #pragma unroll
            for (int nb = 0; nb < 4; nb++) {
                uint32_t t4[4];
                ldm4(t4, sVh + (nb * 16 + b_row) * ATS + kt * 16 + b_coff);
                uint32_t bv0[2] = { t4[0], t4[1] };
                uint32_t bv1[2] = { t4[2], t4[3] };
                mma_f32(O[2 * nb],     Pf[kt], bv0);
                mma_f32(O[2 * nb + 1], Pf[kt], bv1);
                ldm4(t4, sVl + (nb * 16 + b_row) * ATS + kt * 16 + b_coff);
                uint32_t bw0[2] = { t4[0], t4[1] };
                uint32_t bw1[2] = { t4[2], t4[3] };
                mma_f32(O[2 * nb],     Pf[kt], bw0);
                mma_f32(O[2 * nb + 1], Pf[kt], bw1);
            }
        }
    }

    const float inv1 = 1.f / l1, inv2 = 1.f / l2;
    const size_t row1 = (rowb + qb * 64 + rl1) * DGPT + hoff;
    const size_t row2 = (rowb + qb * 64 + rl1 + 8) * DGPT + hoff;
    #pragma unroll
    for (int t = 0; t < 8; t++) {
        const int col = t * 8 + cl0;
        *(__half2*)(yhi + row1 + col) =
            __halves2half2(__float2half_rn(O[t][0] * inv1), __float2half_rn(O[t][1] * inv1));
        *(__half2*)(yhi + row2 + col) =
            __halves2half2(__float2half_rn(O[t][2] * inv2), __float2half_rn(O[t][3] * inv2));
    }
}

// ---------------- launcher ----------------
static inline void convhi(const float* in, __half* hi, size_t n)
{
    size_t n4 = n / 4;
    convhi_kernel<<<(unsigned)((n4 + 255) / 256), 256>>>(in, hi, n4);
}

extern "C" void kernel_launch(void* const* d_in, const int* in_sizes, int n_in,
                              void* d_out, int out_size)
{
    const int*   idx    = (const int*)  d_in[0];
    const float* tok    = (const float*)d_in[1];
    const float* pos    = (const float*)d_in[2];
    const float* ln1_w  = (const float*)d_in[3];
    const float* ln1_b  = (const float*)d_in[4];
    const float* Wq     = (const float*)d_in[5];
    const float* bq     = (const float*)d_in[6];
    const float* Wk     = (const float*)d_in[7];
    const float* bk     = (const float*)d_in[8];
    const float* Wv     = (const float*)d_in[9];
    const float* bv     = (const float*)d_in[10];
    const float* Wproj  = (const float*)d_in[11];
    const float* bproj  = (const float*)d_in[12];
    const float* ln2_w  = (const float*)d_in[13];
    const float* ln2_b  = (const float*)d_in[14];
    const float* W1     = (const float*)d_in[15];
    const float* b1     = (const float*)d_in[16];
    const float* W2     = (const float*)d_in[17];
    const float* b2     = (const float*)d_in[18];
    const float* lnf_w  = (const float*)d_in[19];
    const float* lnf_b  = (const float*)d_in[20];
    const float* Wlogit = (const float*)d_in[21];
    const float* Wdev   = (const float*)d_in[22];
    float* out = (float*)d_out;

    float* xp;
    __half *whi, *ahi, *alo, *fhi, *qkvh, *qkvl;
    cudaGetSymbolAddress((void**)&xp,   g_x);
    cudaGetSymbolAddress((void**)&whi,  g_whi);
    cudaGetSymbolAddress((void**)&ahi,  g_ahi);
    cudaGetSymbolAddress((void**)&alo,  g_alo);
    cudaGetSymbolAddress((void**)&fhi,  g_fhi);
    cudaGetSymbolAddress((void**)&qkvh, g_qkvh);
    cudaGetSymbolAddress((void**)&qkvl, g_qkvl);

    cudaFuncSetAttribute((const void*)gemm_tc<2>, cudaFuncAttributeMaxDynamicSharedMemorySize, GS1);
    cudaFuncSetAttribute((const void*)gemm_qkv,   cudaFuncAttributeMaxDynamicSharedMemorySize, GS1);
    cudaFuncSetAttribute((const void*)gemm_heads, cudaFuncAttributeMaxDynamicSharedMemorySize, GS2);
    cudaFuncSetAttribute((const void*)gemm_w1,    cudaFuncAttributeMaxDynamicSharedMemorySize, GSW);
    cudaFuncSetAttribute((const void*)attn_mma,   cudaFuncAttributeMaxDynamicSharedMemorySize, ATT_SMEM);

    // weight conversion (hi only; qkv scattered into fused layout)
    {
        size_t n4 = (LGPT * DD) / 4;
        unsigned g = (unsigned)((n4 + 255) / 256);
        convqkv_kernel<<<g, 256>>>(Wq, whi + O_QKV, 0, n4);
        convqkv_kernel<<<g, 256>>>(Wk, whi + O_QKV, 1, n4);
        convqkv_kernel<<<g, 256>>>(Wv, whi + O_QKV, 2, n4);
    }
    convhi(Wproj,  whi + O_WP,  LGPT * DD);
    convhi(W1,     whi + O_W1,  (size_t)LGPT * 4 * DD);
    convhi(W2,     whi + O_W2,  (size_t)LGPT * 4 * DD);
    convhi(Wlogit, whi + O_WLG, 4 * DD);
    convhi(Wdev,   whi + O_WDV, 4 * DD);

    dim3 gQ(QKVS / 128, MGPT / 128);   // (24, 32)
    dim3 gD(DGPT / 128, MGPT / 128);   // (8, 32)
    dim3 gW(FGPT / 256, MGPT / 128);   // (16, 32)
    dim3 gH(2 * VGPT / 128, MGPT / 128); // (64, 32)
    dim3 gA(BGPT * HGPT, TGPT / 64);

    embed_kernel<<<(MGPT * DGPT + 255) / 256, 256>>>(idx, tok, pos, xp);

    for (int l = 0; l < LGPT; l++) {
        size_t oQ  = O_QKV + (size_t)l * 3 * DD;
        size_t oP  = O_WP  + (size_t)l * DD;
        size_t o1  = O_W1  + (size_t)l * 4 * DD;
        size_t o2  = O_W2  + (size_t)l * 4 * DD;
        size_t ob  = (size_t)l * DGPT;
        size_t obf = (size_t)l * FGPT;

        ln_kernel<0><<<MGPT, 256>>>(xp, ahi, nullptr, ln1_w + ob, ln1_b + ob);
        gemm_qkv<<<gQ, 256, GS1>>>(ahi, whi + oQ, bq + ob, bk + ob, bv + ob, qkvh, qkvl);
        attn_mma<<<gA, 128, ATT_SMEM>>>(qkvh, qkvl, ahi);
        gemm_tc<2><<<gD, 256, GS1>>>(ahi, whi + oP, bproj + ob, xp, xp, MGPT, DGPT, DGPT);

        ln_kernel<0><<<MGPT, 256>>>(xp, ahi, nullptr, ln2_w + ob, ln2_b + ob);
        gemm_w1<<<gW, 256, GSW>>>(ahi, whi + o1, b1 + obf, fhi, MGPT, FGPT, DGPT);
        gemm_tc<2><<<gD, 256, GS1>>>(fhi, whi + o2, b2 + ob, xp, xp, MGPT, DGPT, FGPT);
    }

    ln_kernel<1><<<MGPT, 256>>>(xp, ahi, alo, lnf_w, lnf_b);
    gemm_heads<<<gH, 256, GS2>>>(ahi, alo, whi + O_WLG, out);
}

// round 14
// speedup vs baseline: 6.0832x; 1.0256x over previous
#include <cuda_runtime.h>
#include <cuda_fp16.h>
#include <math.h>
#include <stdint.h>

// ---------------- problem constants ----------------
#define BGPT 4
#define TGPT 1024
#define DGPT 1024
#define HGPT 16
#define HDH  64
#define LGPT 8
#define VGPT 4096
#define MGPT (BGPT*TGPT)   // 4096 tokens
#define FGPT (4*DGPT)      // 4096 ff dim
#define QKVS (3*DGPT)      // fused qkv row stride (3072)

// weight layout (fp16 hi, element offsets)
#define DD    ((size_t)DGPT*DGPT)
#define O_QKV ((size_t)0)
#define O_WP  ((size_t)LGPT*3*DD)
#define O_W1  (O_WP + (size_t)LGPT*DD)
#define O_W2  (O_W1 + (size_t)LGPT*4*DD)
#define O_WLG (O_W2 + (size_t)LGPT*4*DD)
#define O_WDV (O_WLG + 4*DD)
#define WTOT  (O_WDV + 4*DD)

// ---------------- scratch (device globals; no allocs allowed) ----------------
__device__ float  g_x[MGPT*DGPT];                   // residual stream (fp32)
__device__ __half g_qkvh[(size_t)MGPT*QKVS];        // fused qkv hi
__device__ __half g_qkvl[(size_t)MGPT*QKVS];        // fused qkv lo
__device__ __half g_ahi[(size_t)MGPT*DGPT];         // activation hi
__device__ __half g_alo[(size_t)MGPT*DGPT];         // activation lo (final LN only)
__device__ __half g_fhi[(size_t)MGPT*FGPT];         // ff activation hi
__device__ __half g_whi[WTOT];                      // weights hi

// ---------------- helpers ----------------
__device__ __forceinline__ void split_f16(float v, __half& h, __half& l)
{
    h = __float2half_rn(v);
    l = __float2half_rn(v - __half2float(h));
}

// ---------------- embedding ----------------
__global__ void embed_kernel(const int* __restrict__ idx,
                             const float* __restrict__ tok,
                             const float* __restrict__ pos,
                             float* __restrict__ x)
{
    int i = blockIdx.x * blockDim.x + threadIdx.x;
    if (i >= MGPT * DGPT) return;
    int row = i / DGPT;
    int d   = i - row * DGPT;
    int t   = row & (TGPT - 1);
    x[i] = tok[(size_t)idx[row] * DGPT + d] + pos[(size_t)t * DGPT + d];
}

// ---------------- fp32 -> fp16 hi (8 elems/thread) ----------------
__global__ void __launch_bounds__(256) convhi_kernel(const float* __restrict__ in,
                                                     __half* __restrict__ hi,
                                                     size_t n8)
{
    size_t i = (size_t)blockIdx.x * blockDim.x + threadIdx.x;
    if (i >= n8) return;
    size_t e = i * 8;
    float4 a = *(const float4*)(in + e);
    float4 b = *(const float4*)(in + e + 4);
    __half2 h01 = __halves2half2(__float2half_rn(a.x), __float2half_rn(a.y));
    __half2 h23 = __halves2half2(__float2half_rn(a.z), __float2half_rn(a.w));
    __half2 h45 = __halves2half2(__float2half_rn(b.x), __float2half_rn(b.y));
    __half2 h67 = __halves2half2(__float2half_rn(b.z), __float2half_rn(b.w));
    uint4 ho;
    ho.x = *(uint32_t*)&h01; ho.y = *(uint32_t*)&h23;
    ho.z = *(uint32_t*)&h45; ho.w = *(uint32_t*)&h67;
    *(uint4*)(hi + e) = ho;
}

// ---------------- fp32 -> fp16 hi, scattered into fused QKV layout ----------
__global__ void __launch_bounds__(256) convqkv_kernel(const float* __restrict__ in,
                                                      __half* __restrict__ hi,
                                                      int which, size_t n4)
{
    size_t i = (size_t)blockIdx.x * blockDim.x + threadIdx.x;
    if (i >= n4) return;
    size_t e = i * 4;
    size_t layer = e / DD;
    size_t rem   = e - layer * DD;
    size_t de    = layer * 3 * DD + (size_t)which * DD + rem;
    float4 v = *(const float4*)(in + e);
    __half2 h01 = __halves2half2(__float2half_rn(v.x), __float2half_rn(v.y));
    __half2 h23 = __halves2half2(__float2half_rn(v.z), __float2half_rn(v.w));
    uint2 ho;
    ho.x = *(uint32_t*)&h01; ho.y = *(uint32_t*)&h23;
    *(uint2*)(hi + de) = ho;
}

// ---------------- layernorm (single pass): fp32 in -> fp16 hi (+lo) out -----
template<int WLO>
__global__ void __launch_bounds__(256) ln_kernel(const float* __restrict__ in,
                                                 __half* __restrict__ ohi,
                                                 __half* __restrict__ olo,
                                                 const float* __restrict__ w,
                                                 const float* __restrict__ b)
{
    int row = blockIdx.x;
    int tid = threadIdx.x;
    __shared__ float redS[8], redQ[8];

    float4 v = ((const float4*)(in + (size_t)row * DGPT))[tid];
    float s = v.x + v.y + v.z + v.w;
    float q = v.x * v.x + v.y * v.y + v.z * v.z + v.w * v.w;
    #pragma unroll
    for (int o = 16; o; o >>= 1) {
        s += __shfl_xor_sync(0xffffffffu, s, o);
        q += __shfl_xor_sync(0xffffffffu, q, o);
    }
    if ((tid & 31) == 0) { redS[tid >> 5] = s; redQ[tid >> 5] = q; }
    __syncthreads();
    if (tid < 32) {
        float ts = (tid < 8) ? redS[tid] : 0.f;
        float tq = (tid < 8) ? redQ[tid] : 0.f;
        #pragma unroll
        for (int o = 4; o; o >>= 1) {
            ts += __shfl_xor_sync(0xffffffffu, ts, o);
            tq += __shfl_xor_sync(0xffffffffu, tq, o);
        }
        if (tid == 0) { redS[0] = ts; redQ[0] = tq; }
    }
    __syncthreads();
    float mean = redS[0] * (1.f / DGPT);
    float var  = redQ[0] * (1.f / DGPT) - mean * mean;
    float rstd = rsqrtf(var + 1e-5f);

    float4 wv = ((const float4*)w)[tid];
    float4 bv = ((const float4*)b)[tid];
    float n0 = (v.x - mean) * rstd * wv.x + bv.x;
    float n1 = (v.y - mean) * rstd * wv.y + bv.y;
    float n2 = (v.z - mean) * rstd * wv.z + bv.z;
    float n3 = (v.w - mean) * rstd * wv.w + bv.w;

    __half h0, l0, h1, l1, h2, l2, h3, l3;
    split_f16(n0, h0, l0); split_f16(n1, h1, l1);
    split_f16(n2, h2, l2); split_f16(n3, h3, l3);
    uint2 ho;
    __half2 p01 = __halves2half2(h0, h1), p23 = __halves2half2(h2, h3);
    ho.x = *(uint32_t*)&p01; ho.y = *(uint32_t*)&p23;
    ((uint2*)(ohi + (size_t)row * DGPT))[tid] = ho;
    if (WLO) {
        __half2 q01 = __halves2half2(l0, l1), q23 = __halves2half2(l2, l3);
        uint2 lo2;
        lo2.x = *(uint32_t*)&q01; lo2.y = *(uint32_t*)&q23;
        ((uint2*)(olo + (size_t)row * DGPT))[tid] = lo2;
    }
}

// ---------------- tensor-core helpers ----------------
__device__ __forceinline__ void ldm4(uint32_t r[4], const __half* p)
{
    uint32_t a = (uint32_t)__cvta_generic_to_shared(p);
    asm volatile("ldmatrix.sync.aligned.m8n8.x4.shared.b16 {%0,%1,%2,%3}, [%4];\n"
                 : "=r"(r[0]), "=r"(r[1]), "=r"(r[2]), "=r"(r[3]) : "r"(a));
}
__device__ __forceinline__ void mma_f32(float c[4], const uint32_t a[4], const uint32_t b[2])
{
    asm volatile(
        "mma.sync.aligned.m16n8k16.row.col.f32.f16.f16.f32 "
        "{%0,%1,%2,%3}, {%4,%5,%6,%7}, {%8,%9}, {%0,%1,%2,%3};\n"
        : "+f"(c[0]), "+f"(c[1]), "+f"(c[2]), "+f"(c[3])
        : "r"(a[0]), "r"(a[1]), "r"(a[2]), "r"(a[3]), "r"(b[0]), "r"(b[1]));
}

#define BKg 32
#define PK  40
#define SMBUF (128*PK)
#define SMMAT (2*SMBUF)
#define GS1 (2*SMMAT*2)   // 40960 B
#define GS2 (3*SMMAT*2)   // 61440 B

// ---------------- GEMM (1-term): C = Ahi @ Whi^T, +bias +res fp32 out -------
__global__ void __launch_bounds__(256) gemm_tc(
    const __half* __restrict__ Ahi,
    const __half* __restrict__ Whi,
    const float* __restrict__ bias, const float* __restrict__ res,
    float* __restrict__ C,
    int M, int N, int K)
{
    extern __shared__ __align__(16) __half sm[];
    __half* sAh = sm;
    __half* sBh = sm + SMMAT;

    const int tid  = threadIdx.x;
    const int lane = tid & 31;
    const int wid  = tid >> 5;
    const int wm   = wid >> 2;
    const int wn   = wid & 3;
    const int bm   = blockIdx.y * 128;
    const int bn   = blockIdx.x * 128;

    const int lrow = tid >> 1;
    const int lcol = (tid & 1) << 4;
    const __half* gAh = Ahi + (size_t)(bm + lrow) * K + lcol;
    const __half* gBh = Whi + (size_t)(bn + lrow) * K + lcol;

    const int a_r = wm * 64 + (lane & 15);
    const int a_c = (lane >> 4) * 8;
    const int b_r = wn * 32 + (lane >> 4) * 8 + (lane & 7);
    const int b_c = ((lane >> 3) & 1) * 8;

    float acc[4][4][4];
    #pragma unroll
    for (int mi = 0; mi < 4; mi++)
        #pragma unroll
        for (int ni = 0; ni < 4; ni++)
            #pragma unroll
            for (int r = 0; r < 4; r++) acc[mi][ni][r] = 0.f;

    uint4 rAh0, rAh1, rBh0, rBh1;

    const int NS = K / BKg;
    rAh0 = *(const uint4*)(gAh);     rAh1 = *(const uint4*)(gAh + 8);
    rBh0 = *(const uint4*)(gBh);     rBh1 = *(const uint4*)(gBh + 8);
    {
        __half* p = sAh + lrow * PK + lcol;
        *(uint4*)p = rAh0; *(uint4*)(p + 8) = rAh1;
        p = sBh + lrow * PK + lcol;
        *(uint4*)p = rBh0; *(uint4*)(p + 8) = rBh1;
    }
    __syncthreads();

    for (int s = 0; s < NS; s++) {
        if (s + 1 < NS) {
            int k0 = (s + 1) * BKg;
            rAh0 = *(const uint4*)(gAh + k0);  rAh1 = *(const uint4*)(gAh + k0 + 8);
            rBh0 = *(const uint4*)(gBh + k0);  rBh1 = *(const uint4*)(gBh + k0 + 8);
        }

        const int bo = (s & 1) * SMBUF;
        #pragma unroll
        for (int ks = 0; ks < 2; ks++) {
            const int k0 = ks * 16;
            uint32_t afh[4][4];
            #pragma unroll
            for (int mi = 0; mi < 4; mi++)
                ldm4(afh[mi], sAh + bo + (a_r + mi * 16) * PK + k0 + a_c);
            uint32_t bfh[4][2];
            #pragma unroll
            for (int np = 0; np < 2; np++) {
                uint32_t t[4];
                ldm4(t, sBh + bo + (b_r + np * 16) * PK + k0 + b_c);
                bfh[np * 2][0] = t[0]; bfh[np * 2][1] = t[1];
                bfh[np * 2 + 1][0] = t[2]; bfh[np * 2 + 1][1] = t[3];
            }
            #pragma unroll
            for (int mi = 0; mi < 4; mi++)
                #pragma unroll
                for (int ni = 0; ni < 4; ni++)
                    mma_f32(acc[mi][ni], afh[mi], bfh[ni]);
        }

        if (s + 1 < NS) {
            const int bo2 = ((s + 1) & 1) * SMBUF;
            __half* p = sAh + bo2 + lrow * PK + lcol;
            *(uint4*)p = rAh0; *(uint4*)(p + 8) = rAh1;
            p = sBh + bo2 + lrow * PK + lcol;
            *(uint4*)p = rBh0; *(uint4*)(p + 8) = rBh1;
            __syncthreads();
        }
    }

    const int er = bm + wm * 64 + (lane >> 2);
    const int ec = bn + wn * 32 + (lane & 3) * 2;
    #pragma unroll
    for (int mi = 0; mi < 4; mi++) {
        #pragma unroll
        for (int ni = 0; ni < 4; ni++) {
            const int col = ec + ni * 8;
            #pragma unroll
            for (int h = 0; h < 2; h++) {
                const size_t row = (size_t)(er + mi * 16 + h * 8);
                float v0 = acc[mi][ni][h * 2]     + bias[col];
                float v1 = acc[mi][ni][h * 2 + 1] + bias[col + 1];
                v0 += res[row * N + col];
                v1 += res[row * N + col + 1];
                float2 o; o.x = v0; o.y = v1;
                *(float2*)(C + row * N + col) = o;
            }
        }
    }
}

// ---------------- fused QKV GEMM: [M,3072] = Ahi @ Wqkv^T, fp16 hi/lo out ----
__global__ void __launch_bounds__(256) gemm_qkv(
    const __half* __restrict__ Ahi,
    const __half* __restrict__ Wf,
    const float* __restrict__ bq, const float* __restrict__ bk,
    const float* __restrict__ bv,
    __half* __restrict__ Chi, __half* __restrict__ Clo)
{
    extern __shared__ __align__(16) __half sm[];
    __half* sAh = sm;
    __half* sBh = sm + SMMAT;

    const int K = DGPT;
    const int tid  = threadIdx.x;
    const int lane = tid & 31;
    const int wid  = tid >> 5;
    const int wm   = wid >> 2;
    const int wn   = wid & 3;
    const int bm   = blockIdx.y * 128;
    const int bn   = blockIdx.x * 128;

    const int tsel = bn >> 10;
    const float* bias = (tsel == 0) ? bq : ((tsel == 1) ? bk : bv);
    const int cb = bn - (tsel << 10);

    const int lrow = tid >> 1;
    const int lcol = (tid & 1) << 4;
    const __half* gAh = Ahi + (size_t)(bm + lrow) * K + lcol;
    const __half* gBh = Wf  + (size_t)(bn + lrow) * K + lcol;

    const int a_r = wm * 64 + (lane & 15);
    const int a_c = (lane >> 4) * 8;
    const int b_r = wn * 32 + (lane >> 4) * 8 + (lane & 7);
    const int b_c = ((lane >> 3) & 1) * 8;

    float acc[4][4][4];
    #pragma unroll
    for (int mi = 0; mi < 4; mi++)
        #pragma unroll
        for (int ni = 0; ni < 4; ni++)
            #pragma unroll
            for (int r = 0; r < 4; r++) acc[mi][ni][r] = 0.f;

    uint4 rAh0, rAh1, rBh0, rBh1;
    const int NS = K / BKg;
    rAh0 = *(const uint4*)(gAh);     rAh1 = *(const uint4*)(gAh + 8);
    rBh0 = *(const uint4*)(gBh);     rBh1 = *(const uint4*)(gBh + 8);
    {
        __half* p = sAh + lrow * PK + lcol;
        *(uint4*)p = rAh0; *(uint4*)(p + 8) = rAh1;
        p = sBh + lrow * PK + lcol;
        *(uint4*)p = rBh0; *(uint4*)(p + 8) = rBh1;
    }
    __syncthreads();

    for (int s = 0; s < NS; s++) {
        if (s + 1 < NS) {
            int k0 = (s + 1) * BKg;
            rAh0 = *(const uint4*)(gAh + k0);  rAh1 = *(const uint4*)(gAh + k0 + 8);
            rBh0 = *(const uint4*)(gBh + k0);  rBh1 = *(const uint4*)(gBh + k0 + 8);
        }
        const int bo = (s & 1) * SMBUF;
        #pragma unroll
        for (int ks = 0; ks < 2; ks++) {
            const int k0 = ks * 16;
            uint32_t afh[4][4];
            #pragma unroll
            for (int mi = 0; mi < 4; mi++)
                ldm4(afh[mi], sAh + bo + (a_r + mi * 16) * PK + k0 + a_c);
            uint32_t bfh[4][2];
            #pragma unroll
            for (int np = 0; np < 2; np++) {
                uint32_t t[4];
                ldm4(t, sBh + bo + (b_r + np * 16) * PK + k0 + b_c);
                bfh[np * 2][0] = t[0]; bfh[np * 2][1] = t[1];
                bfh[np * 2 + 1][0] = t[2]; bfh[np * 2 + 1][1] = t[3];
            }
            #pragma unroll
            for (int mi = 0; mi < 4; mi++)
                #pragma unroll
                for (int ni = 0; ni < 4; ni++)
                    mma_f32(acc[mi][ni], afh[mi], bfh[ni]);
        }
        if (s + 1 < NS) {
            const int bo2 = ((s + 1) & 1) * SMBUF;
            __half* p = sAh + bo2 + lrow * PK + lcol;
            *(uint4*)p = rAh0; *(uint4*)(p + 8) = rAh1;
            p = sBh + bo2 + lrow * PK + lcol;
            *(uint4*)p = rBh0; *(uint4*)(p + 8) = rBh1;
            __syncthreads();
        }
    }

    const int er  = bm + wm * 64 + (lane >> 2);
    const int ecl = cb + wn * 32 + (lane & 3) * 2;
    const int ecg = bn + wn * 32 + (lane & 3) * 2;
    #pragma unroll
    for (int mi = 0; mi < 4; mi++) {
        #pragma unroll
        for (int ni = 0; ni < 4; ni++) {
            const int coll = ecl + ni * 8;
            const int colg = ecg + ni * 8;
            const float b0 = bias[coll], b1 = bias[coll + 1];
            #pragma unroll
            for (int h = 0; h < 2; h++) {
                const size_t row = (size_t)(er + mi * 16 + h * 8);
                float v0 = acc[mi][ni][h * 2]     + b0;
                float v1 = acc[mi][ni][h * 2 + 1] + b1;
                __half h0, l0, h1, l1;
                split_f16(v0, h0, l0);
                split_f16(v1, h1, l1);
                *(__half2*)(Chi + row * QKVS + colg) = __halves2half2(h0, h1);
                *(__half2*)(Clo + row * QKVS + colg) = __halves2half2(l0, l1);
            }
        }
    }
}

// ---------------- fused heads GEMM: 2-term (Ahi+Alo) @ Whi^T, fp32 out ------
__global__ void __launch_bounds__(256) gemm_heads(
    const __half* __restrict__ Ahi, const __half* __restrict__ Alo,
    const __half* __restrict__ Whi,
    float* __restrict__ out)
{
    extern __shared__ __align__(16) __half sm[];
    __half* sAh = sm;
    __half* sAl = sm + SMMAT;
    __half* sBh = sm + 2 * SMMAT;

    const int K = DGPT;
    const int tid  = threadIdx.x;
    const int lane = tid & 31;
    const int wid  = tid >> 5;
    const int wm   = wid >> 2;
    const int wn   = wid & 3;
    const int bm   = blockIdx.y * 128;
    const int bn   = blockIdx.x * 128;

    const int tsel = bn >> 12;
    float* C = out + (size_t)tsel * MGPT * VGPT;
    const int cb = bn - (tsel << 12);

    const int lrow = tid >> 1;
    const int lcol = (tid & 1) << 4;
    const __half* gAh = Ahi + (size_t)(bm + lrow) * K + lcol;
    const __half* gAl = Alo + (size_t)(bm + lrow) * K + lcol;
    const __half* gBh = Whi + (size_t)(bn + lrow) * K + lcol;

    const int a_r = wm * 64 + (lane & 15);
    const int a_c = (lane >> 4) * 8;
    const int b_r = wn * 32 + (lane >> 4) * 8 + (lane & 7);
    const int b_c = ((lane >> 3) & 1) * 8;

    float acc[4][4][4];
    #pragma unroll
    for (int mi = 0; mi < 4; mi++)
        #pragma unroll
        for (int ni = 0; ni < 4; ni++)
            #pragma unroll
            for (int r = 0; r < 4; r++) acc[mi][ni][r] = 0.f;

    uint4 rAh0, rAh1, rAl0, rAl1, rBh0, rBh1;
    const int NS = K / BKg;
    rAh0 = *(const uint4*)(gAh);  rAh1 = *(const uint4*)(gAh + 8);
    rAl0 = *(const uint4*)(gAl);  rAl1 = *(const uint4*)(gAl + 8);
    rBh0 = *(const uint4*)(gBh);  rBh1 = *(const uint4*)(gBh + 8);
    {
        __half* p = sAh + lrow * PK + lcol;
        *(uint4*)p = rAh0; *(uint4*)(p + 8) = rAh1;
        p = sAl + lrow * PK + lcol;
        *(uint4*)p = rAl0; *(uint4*)(p + 8) = rAl1;
        p = sBh + lrow * PK + lcol;
        *(uint4*)p = rBh0; *(uint4*)(p + 8) = rBh1;
    }
    __syncthreads();

    for (int s = 0; s < NS; s++) {
        if (s + 1 < NS) {
            int k0 = (s + 1) * BKg;
            rAh0 = *(const uint4*)(gAh + k0);  rAh1 = *(const uint4*)(gAh + k0 + 8);
            rAl0 = *(const uint4*)(gAl + k0);  rAl1 = *(const uint4*)(gAl + k0 + 8);
            rBh0 = *(const uint4*)(gBh + k0);  rBh1 = *(const uint4*)(gBh + k0 + 8);
        }
        const int bo = (s & 1) * SMBUF;
        #pragma unroll
        for (int ks = 0; ks < 2; ks++) {
            const int k0 = ks * 16;
            uint32_t bfh[4][2];
            #pragma unroll
            for (int np = 0; np < 2; np++) {
                uint32_t t[4];
                ldm4(t, sBh + bo + (b_r + np * 16) * PK + k0 + b_c);
                bfh[np * 2][0] = t[0]; bfh[np * 2][1] = t[1];
                bfh[np * 2 + 1][0] = t[2]; bfh[np * 2 + 1][1] = t[3];
            }
            uint32_t af[4][4];
            #pragma unroll
            for (int mi = 0; mi < 4; mi++)
                ldm4(af[mi], sAh + bo + (a_r + mi * 16) * PK + k0 + a_c);
            #pragma unroll
            for (int mi = 0; mi < 4; mi++)
                #pragma unroll
                for (int ni = 0; ni < 4; ni++)
                    mma_f32(acc[mi][ni], af[mi], bfh[ni]);
            #pragma unroll
            for (int mi = 0; mi < 4; mi++)
                ldm4(af[mi], sAl + bo + (a_r + mi * 16) * PK + k0 + a_c);
            #pragma unroll
            for (int mi = 0; mi < 4; mi++)
                #pragma unroll
                for (int ni = 0; ni < 4; ni++)
                    mma_f32(acc[mi][ni], af[mi], bfh[ni]);
        }
        if (s + 1 < NS) {
            const int bo2 = ((s + 1) & 1) * SMBUF;
            __half* p = sAh + bo2 + lrow * PK + lcol;
            *(uint4*)p = rAh0; *(uint4*)(p + 8) = rAh1;
            p = sAl + bo2 + lrow * PK + lcol;
            *(uint4*)p = rAl0; *(uint4*)(p + 8) = rAl1;
            p = sBh + bo2 + lrow * PK + lcol;
            *(uint4*)p = rBh0; *(uint4*)(p + 8) = rBh1;
            __syncthreads();
        }
    }

    const int er = bm + wm * 64 + (lane >> 2);
    const int ec = cb + wn * 32 + (lane & 3) * 2;
    #pragma unroll
    for (int mi = 0; mi < 4; mi++) {
        #pragma unroll
        for (int ni = 0; ni < 4; ni++) {
            const int col = ec + ni * 8;
            #pragma unroll
            for (int h = 0; h < 2; h++) {
                const size_t row = (size_t)(er + mi * 16 + h * 8);
                float2 o;
                o.x = acc[mi][ni][h * 2];
                o.y = acc[mi][ni][h * 2 + 1];
                *(float2*)(C + row * VGPT + col) = o;
            }
        }
    }
}

// ---------------- GEMM (BN=256, warp 64x64) for W1: GELU, fp16 hi out ------
#define W1_SA (128*PK)
#define W1_SB (256*PK)
#define W1_STG (W1_SA + W1_SB)
#define GSW (2*W1_STG*2)

__global__ void __launch_bounds__(256) gemm_w1(
    const __half* __restrict__ Ahi, const __half* __restrict__ Whi,
    const float* __restrict__ bias, __half* __restrict__ Chi,
    int M, int N, int K)
{
    extern __shared__ __align__(16) __half sm[];

    const int tid  = threadIdx.x;
    const int lane = tid & 31;
    const int wid  = tid >> 5;
    const int wm   = wid >> 2;
    const int wn   = wid & 3;
    const int bm   = blockIdx.y * 128;
    const int bn   = blockIdx.x * 256;

    const int lrow = tid >> 1;
    const int lcol = (tid & 1) << 4;
    const __half* gA  = Ahi + (size_t)(bm + lrow) * K + lcol;
    const __half* gB0 = Whi + (size_t)(bn + lrow) * K + lcol;
    const __half* gB1 = Whi + (size_t)(bn + 128 + lrow) * K + lcol;

    const int a_r = wm * 64 + (lane & 15);
    const int a_c = (lane >> 4) * 8;
    const int b_r = wn * 64 + (lane >> 4) * 8 + (lane & 7);
    const int b_c = ((lane >> 3) & 1) * 8;

    float acc[4][8][4];
    #pragma unroll
    for (int mi = 0; mi < 4; mi++)
        #pragma unroll
        for (int ni = 0; ni < 8; ni++)
            #pragma unroll
            for (int r = 0; r < 4; r++) acc[mi][ni][r] = 0.f;

    uint4 rA0, rA1, rB00, rB01, rB10, rB11;

    const int NS = K / BKg;
    rA0  = *(const uint4*)(gA);      rA1  = *(const uint4*)(gA + 8);
    rB00 = *(const uint4*)(gB0);     rB01 = *(const uint4*)(gB0 + 8);
    rB10 = *(const uint4*)(gB1);     rB11 = *(const uint4*)(gB1 + 8);
    {
        __half* p = sm + lrow * PK + lcol;
        *(uint4*)p = rA0; *(uint4*)(p + 8) = rA1;
        p = sm + W1_SA + lrow * PK + lcol;
        *(uint4*)p = rB00; *(uint4*)(p + 8) = rB01;
        p = sm + W1_SA + (128 + lrow) * PK + lcol;
        *(uint4*)p = rB10; *(uint4*)(p + 8) = rB11;
    }
    __syncthreads();

    for (int s = 0; s < NS; s++) {
        if (s + 1 < NS) {
            int k0 = (s + 1) * BKg;
            rA0  = *(const uint4*)(gA + k0);   rA1  = *(const uint4*)(gA + k0 + 8);
            rB00 = *(const uint4*)(gB0 + k0);  rB01 = *(const uint4*)(gB0 + k0 + 8);
            rB10 = *(const uint4*)(gB1 + k0);  rB11 = *(const uint4*)(gB1 + k0 + 8);
        }

        const __half* stg = sm + (s & 1) * W1_STG;
        const __half* sA = stg;
        const __half* sB = stg + W1_SA;
        #pragma unroll
        for (int ks = 0; ks < 2; ks++) {
            const int k0 = ks * 16;
            uint32_t af[4][4];
            #pragma unroll
            for (int mi = 0; mi < 4; mi++)
                ldm4(af[mi], sA + (a_r + mi * 16) * PK + k0 + a_c);
            uint32_t bf[8][2];
            #pragma unroll
            for (int nb = 0; nb < 4; nb++) {
                uint32_t t[4];
                ldm4(t, sB + (b_r + nb * 16) * PK + k0 + b_c);
                bf[nb * 2][0] = t[0]; bf[nb * 2][1] = t[1];
                bf[nb * 2 + 1][0] = t[2]; bf[nb * 2 + 1][1] = t[3];
            }
            #pragma unroll
            for (int mi = 0; mi < 4; mi++)
                #pragma unroll
                for (int ni = 0; ni < 8; ni++)
                    mma_f32(acc[mi][ni], af[mi], bf[ni]);
        }

        if (s + 1 < NS) {
            __half* stg2 = sm + ((s + 1) & 1) * W1_STG;
            __half* p = stg2 + lrow * PK + lcol;
            *(uint4*)p = rA0; *(uint4*)(p + 8) = rA1;
            p = stg2 + W1_SA + lrow * PK + lcol;
            *(uint4*)p = rB00; *(uint4*)(p + 8) = rB01;
            p = stg2 + W1_SA + (128 + lrow) * PK + lcol;
            *(uint4*)p = rB10; *(uint4*)(p + 8) = rB11;
            __syncthreads();
        }
    }

    const int er = bm + wm * 64 + (lane >> 2);
    const int ec = bn + wn * 64 + (lane & 3) * 2;
    #pragma unroll
    for (int mi = 0; mi < 4; mi++) {
        #pragma unroll
        for (int ni = 0; ni < 8; ni++) {
            const int col = ec + ni * 8;
            const float b0 = bias[col], b1 = bias[col + 1];
            #pragma unroll
            for (int h = 0; h < 2; h++) {
                const size_t row = (size_t)(er + mi * 16 + h * 8);
                float v0 = acc[mi][ni][h * 2]     + b0;
                float v1 = acc[mi][ni][h * 2 + 1] + b1;
                v0 = 0.5f * v0 * (1.f + erff(v0 * 0.70710678118654752f));
                v1 = 0.5f * v1 * (1.f + erff(v1 * 0.70710678118654752f));
                *(__half2*)(Chi + row * N + col) =
                    __halves2half2(__float2half_rn(v0), __float2half_rn(v1));
            }
        }
    }
}

// ---------------- tensor-core flash attention (fused QKV input) ------------
// S = Qhi*(Khi+Klo) (fp32); O += P16 * (Vhi + Vlo).
#define ATS 72
#define ATT_SMEM (5*64*ATS*2)   // 46080 B

__global__ void __launch_bounds__(128) attn_mma(
    const __half* __restrict__ qkvh, const __half* __restrict__ qkvl,
    __half* __restrict__ yhi)
{
    extern __shared__ __align__(16) __half sa[];
    __half* sQh = sa;
    __half* sKh = sa + 64 * ATS;
    __half* sKl = sa + 2 * 64 * ATS;
    __half* sVh = sa + 3 * 64 * ATS;    // transposed: [d][kv]
    __half* sVl = sa + 4 * 64 * ATS;

    const int bh = blockIdx.x;
    const int b  = bh / HGPT;
    const int h  = bh % HGPT;
    const int qb = blockIdx.y;
    const int tid  = threadIdx.x;
    const int w    = tid >> 5;
    const int lane = tid & 31;

    const size_t rowb = (size_t)(b * TGPT);
    const int hoff = h * HDH;

    // Q tile (64x64, hi only)
    for (int f = tid; f < 512; f += 128) {
        int r = f >> 3, c8 = (f & 7) * 8;
        size_t g = (rowb + qb * 64 + r) * QKVS + hoff + c8;
        *(uint4*)(sQh + r * ATS + c8) = *(const uint4*)(qkvh + g);
    }

    float O[8][4];
    #pragma unroll
    for (int t = 0; t < 8; t++)
        #pragma unroll
        for (int r = 0; r < 4; r++) O[t][r] = 0.f;
    float m1 = -1e30f, m2 = -1e30f, l1 = 0.f, l2 = 0.f;

    const int a_row  = w * 16 + (lane & 15);
    const int a_coff = (lane >> 4) * 8;
    const int b_row  = (lane >> 4) * 8 + (lane & 7);
    const int b_coff = ((lane >> 3) & 1) * 8;
    const int rl1 = w * 16 + (lane >> 2);
    const int cl0 = 2 * (lane & 3);

    const int nch = qb + 1;
    for (int ch = 0; ch < nch; ch++) {
        const int j0 = ch * 64;
        __syncthreads();
        for (int f = tid; f < 512; f += 128) {
            int r = f >> 3, c8 = (f & 7) * 8;
            size_t g = (rowb + j0 + r) * QKVS + DGPT + hoff + c8;
            *(uint4*)(sKh + r * ATS + c8) = *(const uint4*)(qkvh + g);
            *(uint4*)(sKl + r * ATS + c8) = *(const uint4*)(qkvl + g);
        }
        for (int f = tid; f < 1024; f += 128) {
            int r = f >> 4, c4 = (f & 15) * 4;
            size_t g = (rowb + j0 + r) * QKVS + 2 * DGPT + hoff + c4;
            uint2 hv = *(const uint2*)(qkvh + g);
            uint2 lv = *(const uint2*)(qkvl + g);
            __half2 h01 = *(__half2*)&hv.x, h23 = *(__half2*)&hv.y;
            __half2 l01 = *(__half2*)&lv.x, l23 = *(__half2*)&lv.y;
            sVh[(c4 + 0) * ATS + r] = __low2half(h01);
            sVh[(c4 + 1) * ATS + r] = __high2half(h01);
            sVh[(c4 + 2) * ATS + r] = __low2half(h23);
            sVh[(c4 + 3) * ATS + r] = __high2half(h23);
            sVl[(c4 + 0) * ATS + r] = __low2half(l01);
            sVl[(c4 + 1) * ATS + r] = __high2half(l01);
            sVl[(c4 + 2) * ATS + r] = __low2half(l23);
            sVl[(c4 + 3) * ATS + r] = __high2half(l23);
        }
        __syncthreads();

        float S[8][4];
        #pragma unroll
        for (int t = 0; t < 8; t++)
            #pragma unroll
            for (int r = 0; r < 4; r++) S[t][r] = 0.f;

        #pragma unroll
        for (int ks = 0; ks < 4; ks++) {
            uint32_t aqh[4];
            ldm4(aqh, sQh + a_row * ATS + ks * 16 + a_coff);
            #pragma unroll
            for (int nb = 0; nb < 4; nb++) {
                uint32_t t4[4];
                ldm4(t4, sKh + (nb * 16 + b_row) * ATS + ks * 16 + b_coff);
                uint32_t bh0[2] = { t4[0], t4[1] };
                uint32_t bh1[2] = { t4[2], t4[3] };
                ldm4(t4, sKl + (nb * 16 + b_row) * ATS + ks * 16 + b_coff);
                uint32_t bl0[2] = { t4[0], t4[1] };
                uint32_t bl1[2] = { t4[2], t4[3] };
                mma_f32(S[2 * nb],     aqh, bh0);
                mma_f32(S[2 * nb + 1], aqh, bh1);
                mma_f32(S[2 * nb],     aqh, bl0);
                mma_f32(S[2 * nb + 1], aqh, bl1);
            }
        }

        const bool diag = (ch == qb);
        #pragma unroll
        for (int t = 0; t < 8; t++) {
            S[t][0] *= 0.125f; S[t][1] *= 0.125f;
            S[t][2] *= 0.125f; S[t][3] *= 0.125f;
            if (diag) {
                int c0 = t * 8 + cl0, c1 = c0 + 1;
                if (c0 > rl1)     S[t][0] = -1e30f;
                if (c1 > rl1)     S[t][1] = -1e30f;
                if (c0 > rl1 + 8) S[t][2] = -1e30f;
                if (c1 > rl1 + 8) S[t][3] = -1e30f;
            }
        }

        float mx1 = -1e30f, mx2 = -1e30f;
        #pragma unroll
        for (int t = 0; t < 8; t++) {
            mx1 = fmaxf(mx1, fmaxf(S[t][0], S[t][1]));
            mx2 = fmaxf(mx2, fmaxf(S[t][2], S[t][3]));
        }
        mx1 = fmaxf(mx1, __shfl_xor_sync(0xffffffffu, mx1, 1));
        mx1 = fmaxf(mx1, __shfl_xor_sync(0xffffffffu, mx1, 2));
        mx2 = fmaxf(mx2, __shfl_xor_sync(0xffffffffu, mx2, 1));
        mx2 = fmaxf(mx2, __shfl_xor_sync(0xffffffffu, mx2, 2));

        float mn1 = fmaxf(m1, mx1), mn2 = fmaxf(m2, mx2);
        float cr1 = __expf(m1 - mn1), cr2 = __expf(m2 - mn2);
        m1 = mn1; m2 = mn2;

        float s1 = 0.f, s2 = 0.f;
        uint32_t Pf[4][4];
        #pragma unroll
        for (int t = 0; t < 8; t++) {
            float p0 = __expf(S[t][0] - mn1);
            float p1 = __expf(S[t][1] - mn1);
            float p2 = __expf(S[t][2] - mn2);
            float p3 = __expf(S[t][3] - mn2);
            s1 += p0 + p1; s2 += p2 + p3;
            __half2 ph01 = __halves2half2(__float2half_rn(p0), __float2half_rn(p1));
            __half2 ph23 = __halves2half2(__float2half_rn(p2), __float2half_rn(p3));
            const int kt = t >> 1, hf = (t & 1) * 2;
            Pf[kt][hf + 0] = *(uint32_t*)&ph01;
            Pf[kt][hf + 1] = *(uint32_t*)&ph23;
        }
        s1 += __shfl_xor_sync(0xffffffffu, s1, 1);
        s1 += __shfl_xor_sync(0xffffffffu, s1, 2);
        s2 += __shfl_xor_sync(0xffffffffu, s2, 1);
        s2 += __shfl_xor_sync(0xffffffffu, s2, 2);
        l1 = l1 * cr1 + s1;
        l2 = l2 * cr2 + s2;
        #pragma unroll
        for (int t = 0; t < 8; t++) {
            O[t][0] *= cr1; O[t][1] *= cr1;
            O[t][2] *= cr2; O[t][3] *= cr2;
        }

        #pragma unroll
        for (int kt = 0; kt < 4; kt++) {
            #pragma unroll
            for (int nb = 0; nb < 4; nb++) {
                uint32_t t4[4];
                ldm4(t4, sVh + (nb * 16 + b_row) * ATS + kt * 16 + b_coff);
                uint32_t bv0[2] = { t4[0], t4[1] };
                uint32_t bv1[2] = { t4[2], t4[3] };
                mma_f32(O[2 * nb],     Pf[kt], bv0);
                mma_f32(O[2 * nb + 1], Pf[kt], bv1);
                ldm4(t4, sVl + (nb * 16 + b_row) * ATS + kt * 16 + b_coff);
                uint32_t bw0[2] = { t4[0], t4[1] };
                uint32_t bw1[2] = { t4[2], t4[3] };
                mma_f32(O[2 * nb],     Pf[kt], bw0);
                mma_f32(O[2 * nb + 1], Pf[kt], bw1);
            }
        }
    }

    const float inv1 = 1.f / l1, inv2 = 1.f / l2;
    const size_t row1 = (rowb + qb * 64 + rl1) * DGPT + hoff;
    const size_t row2 = (rowb + qb * 64 + rl1 + 8) * DGPT + hoff;
    #pragma unroll
    for (int t = 0; t < 8; t++) {
        const int col = t * 8 + cl0;
        *(__half2*)(yhi + row1 + col) =
            __halves2half2(__float2half_rn(O[t][0] * inv1), __float2half_rn(O[t][1] * inv1));
        *(__half2*)(yhi + row2 + col) =
            __halves2half2(__float2half_rn(O[t][2] * inv2), __float2half_rn(O[t][3] * inv2));
    }
}

// ---------------- launcher ----------------
static inline void convhi(const float* in, __half* hi, size_t n)
{
    size_t n8 = n / 8;
    convhi_kernel<<<(unsigned)((n8 + 255) / 256), 256>>>(in, hi, n8);
}

extern "C" void kernel_launch(void* const* d_in, const int* in_sizes, int n_in,
                              void* d_out, int out_size)
{
    const int*   idx    = (const int*)  d_in[0];
    const float* tok    = (const float*)d_in[1];
    const float* pos    = (const float*)d_in[2];
    const float* ln1_w  = (const float*)d_in[3];
    const float* ln1_b  = (const float*)d_in[4];
    const float* Wq     = (const float*)d_in[5];
    const float* bq     = (const float*)d_in[6];
    const float* Wk     = (const float*)d_in[7];
    const float* bk     = (const float*)d_in[8];
    const float* Wv     = (const float*)d_in[9];
    const float* bv     = (const float*)d_in[10];
    const float* Wproj  = (const float*)d_in[11];
    const float* bproj  = (const float*)d_in[12];
    const float* ln2_w  = (const float*)d_in[13];
    const float* ln2_b  = (const float*)d_in[14];
    const float* W1     = (const float*)d_in[15];
    const float* b1     = (const float*)d_in[16];
    const float* W2     = (const float*)d_in[17];
    const float* b2     = (const float*)d_in[18];
    const float* lnf_w  = (const float*)d_in[19];
    const float* lnf_b  = (const float*)d_in[20];
    const float* Wlogit = (const float*)d_in[21];
    const float* Wdev   = (const float*)d_in[22];
    float* out = (float*)d_out;

    float* xp;
    __half *whi, *ahi, *alo, *fhi, *qkvh, *qkvl;
    cudaGetSymbolAddress((void**)&xp,   g_x);
    cudaGetSymbolAddress((void**)&whi,  g_whi);
    cudaGetSymbolAddress((void**)&ahi,  g_ahi);
    cudaGetSymbolAddress((void**)&alo,  g_alo);
    cudaGetSymbolAddress((void**)&fhi,  g_fhi);
    cudaGetSymbolAddress((void**)&qkvh, g_qkvh);
    cudaGetSymbolAddress((void**)&qkvl, g_qkvl);

    cudaFuncSetAttribute((const void*)gemm_tc,    cudaFuncAttributeMaxDynamicSharedMemorySize, GS1);
    cudaFuncSetAttribute((const void*)gemm_qkv,   cudaFuncAttributeMaxDynamicSharedMemorySize, GS1);
    cudaFuncSetAttribute((const void*)gemm_heads, cudaFuncAttributeMaxDynamicSharedMemorySize, GS2);
    cudaFuncSetAttribute((const void*)gemm_w1,    cudaFuncAttributeMaxDynamicSharedMemorySize, GSW);
    cudaFuncSetAttribute((const void*)attn_mma,   cudaFuncAttributeMaxDynamicSharedMemorySize, ATT_SMEM);

    {
        size_t n4 = (LGPT * DD) / 4;
        unsigned g = (unsigned)((n4 + 255) / 256);
        convqkv_kernel<<<g, 256>>>(Wq, whi + O_QKV, 0, n4);
        convqkv_kernel<<<g, 256>>>(Wk, whi + O_QKV, 1, n4);
        convqkv_kernel<<<g, 256>>>(Wv, whi + O_QKV, 2, n4);
    }
    convhi(Wproj,  whi + O_WP,  LGPT * DD);
    convhi(W1,     whi + O_W1,  (size_t)LGPT * 4 * DD);
    convhi(W2,     whi + O_W2,  (size_t)LGPT * 4 * DD);
    convhi(Wlogit, whi + O_WLG, 4 * DD);
    convhi(Wdev,   whi + O_WDV, 4 * DD);

    dim3 gQ(QKVS / 128, MGPT / 128);
    dim3 gD(DGPT / 128, MGPT / 128);
    dim3 gW(FGPT / 256, MGPT / 128);
    dim3 gH(2 * VGPT / 128, MGPT / 128);
    dim3 gA(BGPT * HGPT, TGPT / 64);

    embed_kernel<<<(MGPT * DGPT + 255) / 256, 256>>>(idx, tok, pos, xp);

    for (int l = 0; l < LGPT; l++) {
        size_t oQ  = O_QKV + (size_t)l * 3 * DD;
        size_t oP  = O_WP  + (size_t)l * DD;
        size_t o1  = O_W1  + (size_t)l * 4 * DD;
        size_t o2  = O_W2  + (size_t)l * 4 * DD;
        size_t ob  = (size_t)l * DGPT;
        size_t obf = (size_t)l * FGPT;

        ln_kernel<0><<<MGPT, 256>>>(xp, ahi, nullptr, ln1_w + ob, ln1_b + ob);
        gemm_qkv<<<gQ, 256, GS1>>>(ahi, whi + oQ, bq + ob, bk + ob, bv + ob, qkvh, qkvl);
        attn_mma<<<gA, 128, ATT_SMEM>>>(qkvh, qkvl, ahi);
        gemm_tc<<<gD, 256, GS1>>>(ahi, whi + oP, bproj + ob, xp, xp, MGPT, DGPT, DGPT);

        ln_kernel<0><<<MGPT, 256>>>(xp, ahi, nullptr, ln2_w + ob, ln2_b + ob);
        gemm_w1<<<gW, 256, GSW>>>(ahi, whi + o1, b1 + obf, fhi, MGPT, FGPT, DGPT);
        gemm_tc<<<gD, 256, GS1>>>(fhi, whi + o2, b2 + ob, xp, xp, MGPT, DGPT, FGPT);
    }

    ln_kernel<1><<<MGPT, 256>>>(xp, ahi, alo, lnf_w, lnf_b);
    gemm_heads<<<gH, 256, GS2>>>(ahi, alo, whi + O_WLG, out);
}

// round 15
// speedup vs baseline: 6.5285x; 1.0732x over previous
#include <cuda_runtime.h>
#include <cuda_fp16.h>
#include <math.h>
#include <stdint.h>

// ---------------- problem constants ----------------
#define BGPT 4
#define TGPT 1024
#define DGPT 1024
#define HGPT 16
#define HDH  64
#define LGPT 8
#define VGPT 4096
#define MGPT (BGPT*TGPT)   // 4096 tokens
#define FGPT (4*DGPT)      // 4096 ff dim
#define QKVS (3*DGPT)      // fused qkv row stride (3072)

// weight layout (fp16 hi, element offsets)
#define DD    ((size_t)DGPT*DGPT)
#define O_QKV ((size_t)0)
#define O_WP  ((size_t)LGPT*3*DD)
#define O_W1  (O_WP + (size_t)LGPT*DD)
#define O_W2  (O_W1 + (size_t)LGPT*4*DD)
#define O_WLG (O_W2 + (size_t)LGPT*4*DD)
#define O_WDV (O_WLG + 4*DD)
#define WTOT  (O_WDV + 4*DD)

// ---------------- scratch (device globals; no allocs allowed) ----------------
__device__ float  g_x[MGPT*DGPT];                   // residual stream (fp32)
__device__ __half g_qkvh[(size_t)MGPT*QKVS];        // fused qkv hi
__device__ __half g_qkvl[(size_t)MGPT*QKVS];        // fused qkv lo
__device__ __half g_ahi[(size_t)MGPT*DGPT];         // activation hi
__device__ __half g_alo[(size_t)MGPT*DGPT];         // activation lo (final LN only)
__device__ __half g_fhi[(size_t)MGPT*FGPT];         // ff activation hi
__device__ __half g_whi[WTOT];                      // weights hi

// ---------------- helpers ----------------
__device__ __forceinline__ void split_f16(float v, __half& h, __half& l)
{
    h = __float2half_rn(v);
    l = __float2half_rn(v - __half2float(h));
}

// ---------------- embedding ----------------
__global__ void embed_kernel(const int* __restrict__ idx,
                             const float* __restrict__ tok,
                             const float* __restrict__ pos,
                             float* __restrict__ x)
{
    int i = blockIdx.x * blockDim.x + threadIdx.x;
    if (i >= MGPT * DGPT) return;
    int row = i / DGPT;
    int d   = i - row * DGPT;
    int t   = row & (TGPT - 1);
    x[i] = tok[(size_t)idx[row] * DGPT + d] + pos[(size_t)t * DGPT + d];
}

// ---------------- fp32 -> fp16 hi (8 elems/thread) ----------------
__global__ void __launch_bounds__(256) convhi_kernel(const float* __restrict__ in,
                                                     __half* __restrict__ hi,
                                                     size_t n8)
{
    size_t i = (size_t)blockIdx.x * blockDim.x + threadIdx.x;
    if (i >= n8) return;
    size_t e = i * 8;
    float4 a = *(const float4*)(in + e);
    float4 b = *(const float4*)(in + e + 4);
    __half2 h01 = __halves2half2(__float2half_rn(a.x), __float2half_rn(a.y));
    __half2 h23 = __halves2half2(__float2half_rn(a.z), __float2half_rn(a.w));
    __half2 h45 = __halves2half2(__float2half_rn(b.x), __float2half_rn(b.y));
    __half2 h67 = __halves2half2(__float2half_rn(b.z), __float2half_rn(b.w));
    uint4 ho;
    ho.x = *(uint32_t*)&h01; ho.y = *(uint32_t*)&h23;
    ho.z = *(uint32_t*)&h45; ho.w = *(uint32_t*)&h67;
    *(uint4*)(hi + e) = ho;
}

// ---------------- fp32 -> fp16 hi, scattered into fused QKV layout ----------
__global__ void __launch_bounds__(256) convqkv_kernel(const float* __restrict__ in,
                                                      __half* __restrict__ hi,
                                                      int which, size_t n4)
{
    size_t i = (size_t)blockIdx.x * blockDim.x + threadIdx.x;
    if (i >= n4) return;
    size_t e = i * 4;
    size_t layer = e / DD;
    size_t rem   = e - layer * DD;
    size_t de    = layer * 3 * DD + (size_t)which * DD + rem;
    float4 v = *(const float4*)(in + e);
    __half2 h01 = __halves2half2(__float2half_rn(v.x), __float2half_rn(v.y));
    __half2 h23 = __halves2half2(__float2half_rn(v.z), __float2half_rn(v.w));
    uint2 ho;
    ho.x = *(uint32_t*)&h01; ho.y = *(uint32_t*)&h23;
    *(uint2*)(hi + de) = ho;
}

// ---------------- layernorm (single pass): fp32 in -> fp16 hi (+lo) out -----
template<int WLO>
__global__ void __launch_bounds__(256) ln_kernel(const float* __restrict__ in,
                                                 __half* __restrict__ ohi,
                                                 __half* __restrict__ olo,
                                                 const float* __restrict__ w,
                                                 const float* __restrict__ b)
{
    int row = blockIdx.x;
    int tid = threadIdx.x;
    __shared__ float redS[8], redQ[8];

    float4 v = ((const float4*)(in + (size_t)row * DGPT))[tid];
    float s = v.x + v.y + v.z + v.w;
    float q = v.x * v.x + v.y * v.y + v.z * v.z + v.w * v.w;
    #pragma unroll
    for (int o = 16; o; o >>= 1) {
        s += __shfl_xor_sync(0xffffffffu, s, o);
        q += __shfl_xor_sync(0xffffffffu, q, o);
    }
    if ((tid & 31) == 0) { redS[tid >> 5] = s; redQ[tid >> 5] = q; }
    __syncthreads();
    if (tid < 32) {
        float ts = (tid < 8) ? redS[tid] : 0.f;
        float tq = (tid < 8) ? redQ[tid] : 0.f;
        #pragma unroll
        for (int o = 4; o; o >>= 1) {
            ts += __shfl_xor_sync(0xffffffffu, ts, o);
            tq += __shfl_xor_sync(0xffffffffu, tq, o);
        }
        if (tid == 0) { redS[0] = ts; redQ[0] = tq; }
    }
    __syncthreads();
    float mean = redS[0] * (1.f / DGPT);
    float var  = redQ[0] * (1.f / DGPT) - mean * mean;
    float rstd = rsqrtf(var + 1e-5f);

    float4 wv = ((const float4*)w)[tid];
    float4 bv = ((const float4*)b)[tid];
    float n0 = (v.x - mean) * rstd * wv.x + bv.x;
    float n1 = (v.y - mean) * rstd * wv.y + bv.y;
    float n2 = (v.z - mean) * rstd * wv.z + bv.z;
    float n3 = (v.w - mean) * rstd * wv.w + bv.w;

    __half h0, l0, h1, l1, h2, l2, h3, l3;
    split_f16(n0, h0, l0); split_f16(n1, h1, l1);
    split_f16(n2, h2, l2); split_f16(n3, h3, l3);
    uint2 ho;
    __half2 p01 = __halves2half2(h0, h1), p23 = __halves2half2(h2, h3);
    ho.x = *(uint32_t*)&p01; ho.y = *(uint32_t*)&p23;
    ((uint2*)(ohi + (size_t)row * DGPT))[tid] = ho;
    if (WLO) {
        __half2 q01 = __halves2half2(l0, l1), q23 = __halves2half2(l2, l3);
        uint2 lo2;
        lo2.x = *(uint32_t*)&q01; lo2.y = *(uint32_t*)&q23;
        ((uint2*)(olo + (size_t)row * DGPT))[tid] = lo2;
    }
}

// ---------------- tensor-core helpers ----------------
__device__ __forceinline__ void ldm4(uint32_t r[4], const __half* p)
{
    uint32_t a = (uint32_t)__cvta_generic_to_shared(p);
    asm volatile("ldmatrix.sync.aligned.m8n8.x4.shared.b16 {%0,%1,%2,%3}, [%4];\n"
                 : "=r"(r[0]), "=r"(r[1]), "=r"(r[2]), "=r"(r[3]) : "r"(a));
}
__device__ __forceinline__ void mma_f32(float c[4], const uint32_t a[4], const uint32_t b[2])
{
    asm volatile(
        "mma.sync.aligned.m16n8k16.row.col.f32.f16.f16.f32 "
        "{%0,%1,%2,%3}, {%4,%5,%6,%7}, {%8,%9}, {%0,%1,%2,%3};\n"
        : "+f"(c[0]), "+f"(c[1]), "+f"(c[2]), "+f"(c[3])
        : "r"(a[0]), "r"(a[1]), "r"(a[2]), "r"(a[3]), "r"(b[0]), "r"(b[1]));
}

#define BKg 32
#define PK  40
#define SMBUF (128*PK)
#define SMMAT (2*SMBUF)
#define GS1 (2*SMMAT*2)   // 40960 B
#define GS2 (3*SMMAT*2)   // 61440 B

// ---------------- GEMM (1-term): C = Ahi @ Whi^T, +bias +res fp32 out -------
__global__ void __launch_bounds__(256) gemm_tc(
    const __half* __restrict__ Ahi,
    const __half* __restrict__ Whi,
    const float* __restrict__ bias, const float* __restrict__ res,
    float* __restrict__ C,
    int M, int N, int K)
{
    extern __shared__ __align__(16) __half sm[];
    __half* sAh = sm;
    __half* sBh = sm + SMMAT;

    const int tid  = threadIdx.x;
    const int lane = tid & 31;
    const int wid  = tid >> 5;
    const int wm   = wid >> 2;
    const int wn   = wid & 3;
    const int bm   = blockIdx.y * 128;
    const int bn   = blockIdx.x * 128;

    const int lrow = tid >> 1;
    const int lcol = (tid & 1) << 4;
    const __half* gAh = Ahi + (size_t)(bm + lrow) * K + lcol;
    const __half* gBh = Whi + (size_t)(bn + lrow) * K + lcol;

    const int a_r = wm * 64 + (lane & 15);
    const int a_c = (lane >> 4) * 8;
    const int b_r = wn * 32 + (lane >> 4) * 8 + (lane & 7);
    const int b_c = ((lane >> 3) & 1) * 8;

    float acc[4][4][4];
    #pragma unroll
    for (int mi = 0; mi < 4; mi++)
        #pragma unroll
        for (int ni = 0; ni < 4; ni++)
            #pragma unroll
            for (int r = 0; r < 4; r++) acc[mi][ni][r] = 0.f;

    uint4 rAh0, rAh1, rBh0, rBh1;

    const int NS = K / BKg;
    rAh0 = *(const uint4*)(gAh);     rAh1 = *(const uint4*)(gAh + 8);
    rBh0 = *(const uint4*)(gBh);     rBh1 = *(const uint4*)(gBh + 8);
    {
        __half* p = sAh + lrow * PK + lcol;
        *(uint4*)p = rAh0; *(uint4*)(p + 8) = rAh1;
        p = sBh + lrow * PK + lcol;
        *(uint4*)p = rBh0; *(uint4*)(p + 8) = rBh1;
    }
    __syncthreads();

    for (int s = 0; s < NS; s++) {
        if (s + 1 < NS) {
            int k0 = (s + 1) * BKg;
            rAh0 = *(const uint4*)(gAh + k0);  rAh1 = *(const uint4*)(gAh + k0 + 8);
            rBh0 = *(const uint4*)(gBh + k0);  rBh1 = *(const uint4*)(gBh + k0 + 8);
        }

        const int bo = (s & 1) * SMBUF;
        #pragma unroll
        for (int ks = 0; ks < 2; ks++) {
            const int k0 = ks * 16;
            uint32_t afh[4][4];
            #pragma unroll
            for (int mi = 0; mi < 4; mi++)
                ldm4(afh[mi], sAh + bo + (a_r + mi * 16) * PK + k0 + a_c);
            uint32_t bfh[4][2];
            #pragma unroll
            for (int np = 0; np < 2; np++) {
                uint32_t t[4];
                ldm4(t, sBh + bo + (b_r + np * 16) * PK + k0 + b_c);
                bfh[np * 2][0] = t[0]; bfh[np * 2][1] = t[1];
                bfh[np * 2 + 1][0] = t[2]; bfh[np * 2 + 1][1] = t[3];
            }
            #pragma unroll
            for (int mi = 0; mi < 4; mi++)
                #pragma unroll
                for (int ni = 0; ni < 4; ni++)
                    mma_f32(acc[mi][ni], afh[mi], bfh[ni]);
        }

        if (s + 1 < NS) {
            const int bo2 = ((s + 1) & 1) * SMBUF;
            __half* p = sAh + bo2 + lrow * PK + lcol;
            *(uint4*)p = rAh0; *(uint4*)(p + 8) = rAh1;
            p = sBh + bo2 + lrow * PK + lcol;
            *(uint4*)p = rBh0; *(uint4*)(p + 8) = rBh1;
            __syncthreads();
        }
    }

    const int er = bm + wm * 64 + (lane >> 2);
    const int ec = bn + wn * 32 + (lane & 3) * 2;
    #pragma unroll
    for (int mi = 0; mi < 4; mi++) {
        #pragma unroll
        for (int ni = 0; ni < 4; ni++) {
            const int col = ec + ni * 8;
            #pragma unroll
            for (int h = 0; h < 2; h++) {
                const size_t row = (size_t)(er + mi * 16 + h * 8);
                float v0 = acc[mi][ni][h * 2]     + bias[col];
                float v1 = acc[mi][ni][h * 2 + 1] + bias[col + 1];
                v0 += res[row * N + col];
                v1 += res[row * N + col + 1];
                float2 o; o.x = v0; o.y = v1;
                *(float2*)(C + row * N + col) = o;
            }
        }
    }
}

// ---------------- fused QKV GEMM: [M,3072] = Ahi @ Wqkv^T, fp16 hi/lo out ----
__global__ void __launch_bounds__(256) gemm_qkv(
    const __half* __restrict__ Ahi,
    const __half* __restrict__ Wf,
    const float* __restrict__ bq, const float* __restrict__ bk,
    const float* __restrict__ bv,
    __half* __restrict__ Chi, __half* __restrict__ Clo)
{
    extern __shared__ __align__(16) __half sm[];
    __half* sAh = sm;
    __half* sBh = sm + SMMAT;

    const int K = DGPT;
    const int tid  = threadIdx.x;
    const int lane = tid & 31;
    const int wid  = tid >> 5;
    const int wm   = wid >> 2;
    const int wn   = wid & 3;
    const int bm   = blockIdx.y * 128;
    const int bn   = blockIdx.x * 128;

    const int tsel = bn >> 10;
    const float* bias = (tsel == 0) ? bq : ((tsel == 1) ? bk : bv);
    const int cb = bn - (tsel << 10);

    const int lrow = tid >> 1;
    const int lcol = (tid & 1) << 4;
    const __half* gAh = Ahi + (size_t)(bm + lrow) * K + lcol;
    const __half* gBh = Wf  + (size_t)(bn + lrow) * K + lcol;

    const int a_r = wm * 64 + (lane & 15);
    const int a_c = (lane >> 4) * 8;
    const int b_r = wn * 32 + (lane >> 4) * 8 + (lane & 7);
    const int b_c = ((lane >> 3) & 1) * 8;

    float acc[4][4][4];
    #pragma unroll
    for (int mi = 0; mi < 4; mi++)
        #pragma unroll
        for (int ni = 0; ni < 4; ni++)
            #pragma unroll
            for (int r = 0; r < 4; r++) acc[mi][ni][r] = 0.f;

    uint4 rAh0, rAh1, rBh0, rBh1;
    const int NS = K / BKg;
    rAh0 = *(const uint4*)(gAh);     rAh1 = *(const uint4*)(gAh + 8);
    rBh0 = *(const uint4*)(gBh);     rBh1 = *(const uint4*)(gBh + 8);
    {
        __half* p = sAh + lrow * PK + lcol;
        *(uint4*)p = rAh0; *(uint4*)(p + 8) = rAh1;
        p = sBh + lrow * PK + lcol;
        *(uint4*)p = rBh0; *(uint4*)(p + 8) = rBh1;
    }
    __syncthreads();

    for (int s = 0; s < NS; s++) {
        if (s + 1 < NS) {
            int k0 = (s + 1) * BKg;
            rAh0 = *(const uint4*)(gAh + k0);  rAh1 = *(const uint4*)(gAh + k0 + 8);
            rBh0 = *(const uint4*)(gBh + k0);  rBh1 = *(const uint4*)(gBh + k0 + 8);
        }
        const int bo = (s & 1) * SMBUF;
        #pragma unroll
        for (int ks = 0; ks < 2; ks++) {
            const int k0 = ks * 16;
            uint32_t afh[4][4];
            #pragma unroll
            for (int mi = 0; mi < 4; mi++)
                ldm4(afh[mi], sAh + bo + (a_r + mi * 16) * PK + k0 + a_c);
            uint32_t bfh[4][2];
            #pragma unroll
            for (int np = 0; np < 2; np++) {
                uint32_t t[4];
                ldm4(t, sBh + bo + (b_r + np * 16) * PK + k0 + b_c);
                bfh[np * 2][0] = t[0]; bfh[np * 2][1] = t[1];
                bfh[np * 2 + 1][0] = t[2]; bfh[np * 2 + 1][1] = t[3];
            }
            #pragma unroll
            for (int mi = 0; mi < 4; mi++)
                #pragma unroll
                for (int ni = 0; ni < 4; ni++)
                    mma_f32(acc[mi][ni], afh[mi], bfh[ni]);
        }
        if (s + 1 < NS) {
            const int bo2 = ((s + 1) & 1) * SMBUF;
            __half* p = sAh + bo2 + lrow * PK + lcol;
            *(uint4*)p = rAh0; *(uint4*)(p + 8) = rAh1;
            p = sBh + bo2 + lrow * PK + lcol;
            *(uint4*)p = rBh0; *(uint4*)(p + 8) = rBh1;
            __syncthreads();
        }
    }

    const int er  = bm + wm * 64 + (lane >> 2);
    const int ecl = cb + wn * 32 + (lane & 3) * 2;
    const int ecg = bn + wn * 32 + (lane & 3) * 2;
    #pragma unroll
    for (int mi = 0; mi < 4; mi++) {
        #pragma unroll
        for (int ni = 0; ni < 4; ni++) {
            const int coll = ecl + ni * 8;
            const int colg = ecg + ni * 8;
            const float b0 = bias[coll], b1 = bias[coll + 1];
            #pragma unroll
            for (int h = 0; h < 2; h++) {
                const size_t row = (size_t)(er + mi * 16 + h * 8);
                float v0 = acc[mi][ni][h * 2]     + b0;
                float v1 = acc[mi][ni][h * 2 + 1] + b1;
                __half h0, l0, h1, l1;
                split_f16(v0, h0, l0);
                split_f16(v1, h1, l1);
                *(__half2*)(Chi + row * QKVS + colg) = __halves2half2(h0, h1);
                *(__half2*)(Clo + row * QKVS + colg) = __halves2half2(l0, l1);
            }
        }
    }
}

// ---------------- fused heads GEMM: 2-term (Ahi+Alo) @ Whi^T, fp32 out ------
__global__ void __launch_bounds__(256) gemm_heads(
    const __half* __restrict__ Ahi, const __half* __restrict__ Alo,
    const __half* __restrict__ Whi,
    float* __restrict__ out)
{
    extern __shared__ __align__(16) __half sm[];
    __half* sAh = sm;
    __half* sAl = sm + SMMAT;
    __half* sBh = sm + 2 * SMMAT;

    const int K = DGPT;
    const int tid  = threadIdx.x;
    const int lane = tid & 31;
    const int wid  = tid >> 5;
    const int wm   = wid >> 2;
    const int wn   = wid & 3;
    const int bm   = blockIdx.y * 128;
    const int bn   = blockIdx.x * 128;

    const int tsel = bn >> 12;
    float* C = out + (size_t)tsel * MGPT * VGPT;
    const int cb = bn - (tsel << 12);

    const int lrow = tid >> 1;
    const int lcol = (tid & 1) << 4;
    const __half* gAh = Ahi + (size_t)(bm + lrow) * K + lcol;
    const __half* gAl = Alo + (size_t)(bm + lrow) * K + lcol;
    const __half* gBh = Whi + (size_t)(bn + lrow) * K + lcol;

    const int a_r = wm * 64 + (lane & 15);
    const int a_c = (lane >> 4) * 8;
    const int b_r = wn * 32 + (lane >> 4) * 8 + (lane & 7);
    const int b_c = ((lane >> 3) & 1) * 8;

    float acc[4][4][4];
    #pragma unroll
    for (int mi = 0; mi < 4; mi++)
        #pragma unroll
        for (int ni = 0; ni < 4; ni++)
            #pragma unroll
            for (int r = 0; r < 4; r++) acc[mi][ni][r] = 0.f;

    uint4 rAh0, rAh1, rAl0, rAl1, rBh0, rBh1;
    const int NS = K / BKg;
    rAh0 = *(const uint4*)(gAh);  rAh1 = *(const uint4*)(gAh + 8);
    rAl0 = *(const uint4*)(gAl);  rAl1 = *(const uint4*)(gAl + 8);
    rBh0 = *(const uint4*)(gBh);  rBh1 = *(const uint4*)(gBh + 8);
    {
        __half* p = sAh + lrow * PK + lcol;
        *(uint4*)p = rAh0; *(uint4*)(p + 8) = rAh1;
        p = sAl + lrow * PK + lcol;
        *(uint4*)p = rAl0; *(uint4*)(p + 8) = rAl1;
        p = sBh + lrow * PK + lcol;
        *(uint4*)p = rBh0; *(uint4*)(p + 8) = rBh1;
    }
    __syncthreads();

    for (int s = 0; s < NS; s++) {
        if (s + 1 < NS) {
            int k0 = (s + 1) * BKg;
            rAh0 = *(const uint4*)(gAh + k0);  rAh1 = *(const uint4*)(gAh + k0 + 8);
            rAl0 = *(const uint4*)(gAl + k0);  rAl1 = *(const uint4*)(gAl + k0 + 8);
            rBh0 = *(const uint4*)(gBh + k0);  rBh1 = *(const uint4*)(gBh + k0 + 8);
        }
        const int bo = (s & 1) * SMBUF;
        #pragma unroll
        for (int ks = 0; ks < 2; ks++) {
            const int k0 = ks * 16;
            uint32_t bfh[4][2];
            #pragma unroll
            for (int np = 0; np < 2; np++) {
                uint32_t t[4];
                ldm4(t, sBh + bo + (b_r + np * 16) * PK + k0 + b_c);
                bfh[np * 2][0] = t[0]; bfh[np * 2][1] = t[1];
                bfh[np * 2 + 1][0] = t[2]; bfh[np * 2 + 1][1] = t[3];
            }
            uint32_t af[4][4];
            #pragma unroll
            for (int mi = 0; mi < 4; mi++)
                ldm4(af[mi], sAh + bo + (a_r + mi * 16) * PK + k0 + a_c);
            #pragma unroll
            for (int mi = 0; mi < 4; mi++)
                #pragma unroll
                for (int ni = 0; ni < 4; ni++)
                    mma_f32(acc[mi][ni], af[mi], bfh[ni]);
            #pragma unroll
            for (int mi = 0; mi < 4; mi++)
                ldm4(af[mi], sAl + bo + (a_r + mi * 16) * PK + k0 + a_c);
            #pragma unroll
            for (int mi = 0; mi < 4; mi++)
                #pragma unroll
                for (int ni = 0; ni < 4; ni++)
                    mma_f32(acc[mi][ni], af[mi], bfh[ni]);
        }
        if (s + 1 < NS) {
            const int bo2 = ((s + 1) & 1) * SMBUF;
            __half* p = sAh + bo2 + lrow * PK + lcol;
            *(uint4*)p = rAh0; *(uint4*)(p + 8) = rAh1;
            p = sAl + bo2 + lrow * PK + lcol;
            *(uint4*)p = rAl0; *(uint4*)(p + 8) = rAl1;
            p = sBh + bo2 + lrow * PK + lcol;
            *(uint4*)p = rBh0; *(uint4*)(p + 8) = rBh1;
            __syncthreads();
        }
    }

    const int er = bm + wm * 64 + (lane >> 2);
    const int ec = cb + wn * 32 + (lane & 3) * 2;
    #pragma unroll
    for (int mi = 0; mi < 4; mi++) {
        #pragma unroll
        for (int ni = 0; ni < 4; ni++) {
            const int col = ec + ni * 8;
            #pragma unroll
            for (int h = 0; h < 2; h++) {
                const size_t row = (size_t)(er + mi * 16 + h * 8);
                float2 o;
                o.x = acc[mi][ni][h * 2];
                o.y = acc[mi][ni][h * 2 + 1];
                *(float2*)(C + row * VGPT + col) = o;
            }
        }
    }
}

// ---------------- GEMM (BN=256, warp 64x64) for W1: GELU, fp16 hi out ------
#define W1_SA (128*PK)
#define W1_SB (256*PK)
#define W1_STG (W1_SA + W1_SB)
#define GSW (2*W1_STG*2)

__global__ void __launch_bounds__(256) gemm_w1(
    const __half* __restrict__ Ahi, const __half* __restrict__ Whi,
    const float* __restrict__ bias, __half* __restrict__ Chi,
    int M, int N, int K)
{
    extern __shared__ __align__(16) __half sm[];

    const int tid  = threadIdx.x;
    const int lane = tid & 31;
    const int wid  = tid >> 5;
    const int wm   = wid >> 2;
    const int wn   = wid & 3;
    const int bm   = blockIdx.y * 128;
    const int bn   = blockIdx.x * 256;

    const int lrow = tid >> 1;
    const int lcol = (tid & 1) << 4;
    const __half* gA  = Ahi + (size_t)(bm + lrow) * K + lcol;
    const __half* gB0 = Whi + (size_t)(bn + lrow) * K + lcol;
    const __half* gB1 = Whi + (size_t)(bn + 128 + lrow) * K + lcol;

    const int a_r = wm * 64 + (lane & 15);
    const int a_c = (lane >> 4) * 8;
    const int b_r = wn * 64 + (lane >> 4) * 8 + (lane & 7);
    const int b_c = ((lane >> 3) & 1) * 8;

    float acc[4][8][4];
    #pragma unroll
    for (int mi = 0; mi < 4; mi++)
        #pragma unroll
        for (int ni = 0; ni < 8; ni++)
            #pragma unroll
            for (int r = 0; r < 4; r++) acc[mi][ni][r] = 0.f;

    uint4 rA0, rA1, rB00, rB01, rB10, rB11;

    const int NS = K / BKg;
    rA0  = *(const uint4*)(gA);      rA1  = *(const uint4*)(gA + 8);
    rB00 = *(const uint4*)(gB0);     rB01 = *(const uint4*)(gB0 + 8);
    rB10 = *(const uint4*)(gB1);     rB11 = *(const uint4*)(gB1 + 8);
    {
        __half* p = sm + lrow * PK + lcol;
        *(uint4*)p = rA0; *(uint4*)(p + 8) = rA1;
        p = sm + W1_SA + lrow * PK + lcol;
        *(uint4*)p = rB00; *(uint4*)(p + 8) = rB01;
        p = sm + W1_SA + (128 + lrow) * PK + lcol;
        *(uint4*)p = rB10; *(uint4*)(p + 8) = rB11;
    }
    __syncthreads();

    for (int s = 0; s < NS; s++) {
        if (s + 1 < NS) {
            int k0 = (s + 1) * BKg;
            rA0  = *(const uint4*)(gA + k0);   rA1  = *(const uint4*)(gA + k0 + 8);
            rB00 = *(const uint4*)(gB0 + k0);  rB01 = *(const uint4*)(gB0 + k0 + 8);
            rB10 = *(const uint4*)(gB1 + k0);  rB11 = *(const uint4*)(gB1 + k0 + 8);
        }

        const __half* stg = sm + (s & 1) * W1_STG;
        const __half* sA = stg;
        const __half* sB = stg + W1_SA;
        #pragma unroll
        for (int ks = 0; ks < 2; ks++) {
            const int k0 = ks * 16;
            uint32_t af[4][4];
            #pragma unroll
            for (int mi = 0; mi < 4; mi++)
                ldm4(af[mi], sA + (a_r + mi * 16) * PK + k0 + a_c);
            uint32_t bf[8][2];
            #pragma unroll
            for (int nb = 0; nb < 4; nb++) {
                uint32_t t[4];
                ldm4(t, sB + (b_r + nb * 16) * PK + k0 + b_c);
                bf[nb * 2][0] = t[0]; bf[nb * 2][1] = t[1];
                bf[nb * 2 + 1][0] = t[2]; bf[nb * 2 + 1][1] = t[3];
            }
            #pragma unroll
            for (int mi = 0; mi < 4; mi++)
                #pragma unroll
                for (int ni = 0; ni < 8; ni++)
                    mma_f32(acc[mi][ni], af[mi], bf[ni]);
        }

        if (s + 1 < NS) {
            __half* stg2 = sm + ((s + 1) & 1) * W1_STG;
            __half* p = stg2 + lrow * PK + lcol;
            *(uint4*)p = rA0; *(uint4*)(p + 8) = rA1;
            p = stg2 + W1_SA + lrow * PK + lcol;
            *(uint4*)p = rB00; *(uint4*)(p + 8) = rB01;
            p = stg2 + W1_SA + (128 + lrow) * PK + lcol;
            *(uint4*)p = rB10; *(uint4*)(p + 8) = rB11;
            __syncthreads();
        }
    }

    const int er = bm + wm * 64 + (lane >> 2);
    const int ec = bn + wn * 64 + (lane & 3) * 2;
    #pragma unroll
    for (int mi = 0; mi < 4; mi++) {
        #pragma unroll
        for (int ni = 0; ni < 8; ni++) {
            const int col = ec + ni * 8;
            const float b0 = bias[col], b1 = bias[col + 1];
            #pragma unroll
            for (int h = 0; h < 2; h++) {
                const size_t row = (size_t)(er + mi * 16 + h * 8);
                float v0 = acc[mi][ni][h * 2]     + b0;
                float v1 = acc[mi][ni][h * 2 + 1] + b1;
                v0 = 0.5f * v0 * (1.f + erff(v0 * 0.70710678118654752f));
                v1 = 0.5f * v1 * (1.f + erff(v1 * 0.70710678118654752f));
                *(__half2*)(Chi + row * N + col) =
                    __halves2half2(__float2half_rn(v0), __float2half_rn(v1));
            }
        }
    }
}

// ---------------- tensor-core flash attention ----------------
// Q-block 128 rows, 8 warps. S = Qhi*(Khi+Klo); O += P16 * Vhi.
#define ATS 72
#define ATT_SMEM ((128 + 3*64)*ATS*2)   // 46080 B

__global__ void __launch_bounds__(256) attn_mma(
    const __half* __restrict__ qkvh, const __half* __restrict__ qkvl,
    __half* __restrict__ yhi)
{
    extern __shared__ __align__(16) __half sa[];
    __half* sQh = sa;                     // 128 x ATS
    __half* sKh = sa + 128 * ATS;         // 64 x ATS
    __half* sKl = sa + 192 * ATS;         // 64 x ATS
    __half* sVh = sa + 256 * ATS;         // transposed: [d][kv] 64 x ATS

    const int bh = blockIdx.x;
    const int b  = bh / HGPT;
    const int h  = bh % HGPT;
    const int qb = blockIdx.y;            // 128-row q block
    const int tid  = threadIdx.x;
    const int w    = tid >> 5;
    const int lane = tid & 31;

    const size_t rowb = (size_t)(b * TGPT);
    const int hoff = h * HDH;

    // Q tile (128x64, hi only)
    for (int f = tid; f < 1024; f += 256) {
        int r = f >> 3, c8 = (f & 7) * 8;
        size_t g = (rowb + qb * 128 + r) * QKVS + hoff + c8;
        *(uint4*)(sQh + r * ATS + c8) = *(const uint4*)(qkvh + g);
    }

    float O[8][4];
    #pragma unroll
    for (int t = 0; t < 8; t++)
        #pragma unroll
        for (int r = 0; r < 4; r++) O[t][r] = 0.f;
    float m1 = -1e30f, m2 = -1e30f, l1 = 0.f, l2 = 0.f;

    const int a_row  = w * 16 + (lane & 15);
    const int a_coff = (lane >> 4) * 8;
    const int b_row  = (lane >> 4) * 8 + (lane & 7);
    const int b_coff = ((lane >> 3) & 1) * 8;
    const int rl1 = w * 16 + (lane >> 2);       // local q row within 128-block
    const int cl0 = 2 * (lane & 3);
    const int grow1 = qb * 128 + rl1;

    const int nch = 2 * qb + 2;
    for (int ch = 0; ch < nch; ch++) {
        const int j0 = ch * 64;
        __syncthreads();
        for (int f = tid; f < 512; f += 256) {
            int r = f >> 3, c8 = (f & 7) * 8;
            size_t g = (rowb + j0 + r) * QKVS + DGPT + hoff + c8;
            *(uint4*)(sKh + r * ATS + c8) = *(const uint4*)(qkvh + g);
            *(uint4*)(sKl + r * ATS + c8) = *(const uint4*)(qkvl + g);
        }
        for (int f = tid; f < 1024; f += 256) {     // V hi transposed
            int r = f >> 4, c4 = (f & 15) * 4;
            size_t g = (rowb + j0 + r) * QKVS + 2 * DGPT + hoff + c4;
            uint2 hv = *(const uint2*)(qkvh + g);
            __half2 h01 = *(__half2*)&hv.x, h23 = *(__half2*)&hv.y;
            sVh[(c4 + 0) * ATS + r] = __low2half(h01);
            sVh[(c4 + 1) * ATS + r] = __high2half(h01);
            sVh[(c4 + 2) * ATS + r] = __low2half(h23);
            sVh[(c4 + 3) * ATS + r] = __high2half(h23);
        }
        __syncthreads();

        float S[8][4];
        #pragma unroll
        for (int t = 0; t < 8; t++)
            #pragma unroll
            for (int r = 0; r < 4; r++) S[t][r] = 0.f;

        #pragma unroll
        for (int ks = 0; ks < 4; ks++) {
            uint32_t aqh[4];
            ldm4(aqh, sQh + a_row * ATS + ks * 16 + a_coff);
            #pragma unroll
            for (int nb = 0; nb < 4; nb++) {
                uint32_t t4[4];
                ldm4(t4, sKh + (nb * 16 + b_row) * ATS + ks * 16 + b_coff);
                uint32_t bh0[2] = { t4[0], t4[1] };
                uint32_t bh1[2] = { t4[2], t4[3] };
                ldm4(t4, sKl + (nb * 16 + b_row) * ATS + ks * 16 + b_coff);
                uint32_t bl0[2] = { t4[0], t4[1] };
                uint32_t bl1[2] = { t4[2], t4[3] };
                mma_f32(S[2 * nb],     aqh, bh0);
                mma_f32(S[2 * nb + 1], aqh, bh1);
                mma_f32(S[2 * nb],     aqh, bl0);
                mma_f32(S[2 * nb + 1], aqh, bl1);
            }
        }

        const bool diag = (ch >= 2 * qb);
        #pragma unroll
        for (int t = 0; t < 8; t++) {
            S[t][0] *= 0.125f; S[t][1] *= 0.125f;
            S[t][2] *= 0.125f; S[t][3] *= 0.125f;
            if (diag) {
                int c0 = j0 + t * 8 + cl0, c1 = c0 + 1;
                if (c0 > grow1)     S[t][0] = -1e30f;
                if (c1 > grow1)     S[t][1] = -1e30f;
                if (c0 > grow1 + 8) S[t][2] = -1e30f;
                if (c1 > grow1 + 8) S[t][3] = -1e30f;
            }
        }

        float mx1 = -1e30f, mx2 = -1e30f;
        #pragma unroll
        for (int t = 0; t < 8; t++) {
            mx1 = fmaxf(mx1, fmaxf(S[t][0], S[t][1]));
            mx2 = fmaxf(mx2, fmaxf(S[t][2], S[t][3]));
        }
        mx1 = fmaxf(mx1, __shfl_xor_sync(0xffffffffu, mx1, 1));
        mx1 = fmaxf(mx1, __shfl_xor_sync(0xffffffffu, mx1, 2));
        mx2 = fmaxf(mx2, __shfl_xor_sync(0xffffffffu, mx2, 1));
        mx2 = fmaxf(mx2, __shfl_xor_sync(0xffffffffu, mx2, 2));

        float mn1 = fmaxf(m1, mx1), mn2 = fmaxf(m2, mx2);
        float cr1 = __expf(m1 - mn1), cr2 = __expf(m2 - mn2);
        m1 = mn1; m2 = mn2;

        float s1 = 0.f, s2 = 0.f;
        uint32_t Pf[4][4];
        #pragma unroll
        for (int t = 0; t < 8; t++) {
            float p0 = __expf(S[t][0] - mn1);
            float p1 = __expf(S[t][1] - mn1);
            float p2 = __expf(S[t][2] - mn2);
            float p3 = __expf(S[t][3] - mn2);
            s1 += p0 + p1; s2 += p2 + p3;
            __half2 ph01 = __halves2half2(__float2half_rn(p0), __float2half_rn(p1));
            __half2 ph23 = __halves2half2(__float2half_rn(p2), __float2half_rn(p3));
            const int kt = t >> 1, hf = (t & 1) * 2;
            Pf[kt][hf + 0] = *(uint32_t*)&ph01;
            Pf[kt][hf + 1] = *(uint32_t*)&ph23;
        }
        s1 += __shfl_xor_sync(0xffffffffu, s1, 1);
        s1 += __shfl_xor_sync(0xffffffffu, s1, 2);
        s2 += __shfl_xor_sync(0xffffffffu, s2, 1);
        s2 += __shfl_xor_sync(0xffffffffu, s2, 2);
        l1 = l1 * cr1 + s1;
        l2 = l2 * cr2 + s2;
        #pragma unroll
        for (int t = 0; t < 8; t++) {
            O[t][0] *= cr1; O[t][1] *= cr1;
            O[t][2] *= cr2; O[t][3] *= cr2;
        }

        #pragma unroll
        for (int kt = 0; kt < 4; kt++) {
            #pragma unroll
            for (int nb = 0; nb < 4; nb++) {
                uint32_t t4[4];
                ldm4(t4, sVh + (nb * 16 + b_row) * ATS + kt * 16 + b_coff);
                uint32_t bv0[2] = { t4[0], t4[1] };
                uint32_t bv1[2] = { t4[2], t4[3] };
                mma_f32(O[2 * nb],     Pf[kt], bv0);
                mma_f32(O[2 * nb + 1], Pf[kt], bv1);
            }
        }
    }

    const float inv1 = 1.f / l1, inv2 = 1.f / l2;
    const size_t row1 = (rowb + qb * 128 + rl1) * DGPT + hoff;
    const size_t row2 = (rowb + qb * 128 + rl1 + 8) * DGPT + hoff;
    #pragma unroll
    for (int t = 0; t < 8; t++) {
        const int col = t * 8 + cl0;
        *(__half2*)(yhi + row1 + col) =
            __halves2half2(__float2half_rn(O[t][0] * inv1), __float2half_rn(O[t][1] * inv1));
        *(__half2*)(yhi + row2 + col) =
            __halves2half2(__float2half_rn(O[t][2] * inv2), __float2half_rn(O[t][3] * inv2));
    }
}

// ---------------- launcher ----------------
static inline void convhi(const float* in, __half* hi, size_t n)
{
    size_t n8 = n / 8;
    convhi_kernel<<<(unsigned)((n8 + 255) / 256), 256>>>(in, hi, n8);
}

extern "C" void kernel_launch(void* const* d_in, const int* in_sizes, int n_in,
                              void* d_out, int out_size)
{
    const int*   idx    = (const int*)  d_in[0];
    const float* tok    = (const float*)d_in[1];
    const float* pos    = (const float*)d_in[2];
    const float* ln1_w  = (const float*)d_in[3];
    const float* ln1_b  = (const float*)d_in[4];
    const float* Wq     = (const float*)d_in[5];
    const float* bq     = (const float*)d_in[6];
    const float* Wk     = (const float*)d_in[7];
    const float* bk     = (const float*)d_in[8];
    const float* Wv     = (const float*)d_in[9];
    const float* bv     = (const float*)d_in[10];
    const float* Wproj  = (const float*)d_in[11];
    const float* bproj  = (const float*)d_in[12];
    const float* ln2_w  = (const float*)d_in[13];
    const float* ln2_b  = (const float*)d_in[14];
    const float* W1     = (const float*)d_in[15];
    const float* b1     = (const float*)d_in[16];
    const float* W2     = (const float*)d_in[17];
    const float* b2     = (const float*)d_in[18];
    const float* lnf_w  = (const float*)d_in[19];
    const float* lnf_b  = (const float*)d_in[20];
    const float* Wlogit = (const float*)d_in[21];
    const float* Wdev   = (const float*)d_in[22];
    float* out = (float*)d_out;

    float* xp;
    __half *whi, *ahi, *alo, *fhi, *qkvh, *qkvl;
    cudaGetSymbolAddress((void**)&xp,   g_x);
    cudaGetSymbolAddress((void**)&whi,  g_whi);
    cudaGetSymbolAddress((void**)&ahi,  g_ahi);
    cudaGetSymbolAddress((void**)&alo,  g_alo);
    cudaGetSymbolAddress((void**)&fhi,  g_fhi);
    cudaGetSymbolAddress((void**)&qkvh, g_qkvh);
    cudaGetSymbolAddress((void**)&qkvl, g_qkvl);

    cudaFuncSetAttribute((const void*)gemm_tc,    cudaFuncAttributeMaxDynamicSharedMemorySize, GS1);
    cudaFuncSetAttribute((const void*)gemm_qkv,   cudaFuncAttributeMaxDynamicSharedMemorySize, GS1);
    cudaFuncSetAttribute((const void*)gemm_heads, cudaFuncAttributeMaxDynamicSharedMemorySize, GS2);
    cudaFuncSetAttribute((const void*)gemm_w1,    cudaFuncAttributeMaxDynamicSharedMemorySize, GSW);
    cudaFuncSetAttribute((const void*)attn_mma,   cudaFuncAttributeMaxDynamicSharedMemorySize, ATT_SMEM);

    {
        size_t n4 = (LGPT * DD) / 4;
        unsigned g = (unsigned)((n4 + 255) / 256);
        convqkv_kernel<<<g, 256>>>(Wq, whi + O_QKV, 0, n4);
        convqkv_kernel<<<g, 256>>>(Wk, whi + O_QKV, 1, n4);
        convqkv_kernel<<<g, 256>>>(Wv, whi + O_QKV, 2, n4);
    }
    convhi(Wproj,  whi + O_WP,  LGPT * DD);
    convhi(W1,     whi + O_W1,  (size_t)LGPT * 4 * DD);
    convhi(W2,     whi + O_W2,  (size_t)LGPT * 4 * DD);
    convhi(Wlogit, whi + O_WLG, 4 * DD);
    convhi(Wdev,   whi + O_WDV, 4 * DD);

    dim3 gQ(QKVS / 128, MGPT / 128);
    dim3 gD(DGPT / 128, MGPT / 128);
    dim3 gW(FGPT / 256, MGPT / 128);
    dim3 gH(2 * VGPT / 128, MGPT / 128);
    dim3 gA(BGPT * HGPT, TGPT / 128);

    embed_kernel<<<(MGPT * DGPT + 255) / 256, 256>>>(idx, tok, pos, xp);

    for (int l = 0; l < LGPT; l++) {
        size_t oQ  = O_QKV + (size_t)l * 3 * DD;
        size_t oP  = O_WP  + (size_t)l * DD;
        size_t o1  = O_W1  + (size_t)l * 4 * DD;
        size_t o2  = O_W2  + (size_t)l * 4 * DD;
        size_t ob  = (size_t)l * DGPT;
        size_t obf = (size_t)l * FGPT;

        ln_kernel<0><<<MGPT, 256>>>(xp, ahi, nullptr, ln1_w + ob, ln1_b + ob);
        gemm_qkv<<<gQ, 256, GS1>>>(ahi, whi + oQ, bq + ob, bk + ob, bv + ob, qkvh, qkvl);
        attn_mma<<<gA, 256, ATT_SMEM>>>(qkvh, qkvl, ahi);
        gemm_tc<<<gD, 256, GS1>>>(ahi, whi + oP, bproj + ob, xp, xp, MGPT, DGPT, DGPT);

        ln_kernel<0><<<MGPT, 256>>>(xp, ahi, nullptr, ln2_w + ob, ln2_b + ob);
        gemm_w1<<<gW, 256, GSW>>>(ahi, whi + o1, b1 + obf, fhi, MGPT, FGPT, DGPT);
        gemm_tc<<<gD, 256, GS1>>>(fhi, whi + o2, b2 + ob, xp, xp, MGPT, DGPT, FGPT);
    }

    ln_kernel<1><<<MGPT, 256>>>(xp, ahi, alo, lnf_w, lnf_b);
    gemm_heads<<<gH, 256, GS2>>>(ahi, alo, whi + O_WLG, out);
}

// round 16
// speedup vs baseline: 6.7539x; 1.0345x over previous
#include <cuda_runtime.h>
#include <cuda_fp16.h>
#include <math.h>
#include <stdint.h>

// ---------------- problem constants ----------------
#define BGPT 4
#define TGPT 1024
#define DGPT 1024
#define HGPT 16
#define HDH  64
#define LGPT 8
#define VGPT 4096
#define MGPT (BGPT*TGPT)   // 4096 tokens
#define FGPT (4*DGPT)      // 4096 ff dim
#define QKVS (3*DGPT)      // fused qkv row stride (3072)

// weight layout (fp16 hi, element offsets)
#define DD    ((size_t)DGPT*DGPT)
#define O_QKV ((size_t)0)
#define O_WP  ((size_t)LGPT*3*DD)
#define O_W1  (O_WP + (size_t)LGPT*DD)
#define O_W2  (O_W1 + (size_t)LGPT*4*DD)
#define O_WLG (O_W2 + (size_t)LGPT*4*DD)
#define O_WDV (O_WLG + 4*DD)
#define WTOT  (O_WDV + 4*DD)

// ---------------- scratch (device globals; no allocs allowed) ----------------
__device__ float  g_x[MGPT*DGPT];                   // residual stream (fp32)
__device__ __half g_qkvh[(size_t)MGPT*QKVS];        // fused qkv hi
__device__ __half g_ahi[(size_t)MGPT*DGPT];         // activation hi
__device__ __half g_alo[(size_t)MGPT*DGPT];         // activation lo (final LN only)
__device__ __half g_fhi[(size_t)MGPT*FGPT];         // ff activation hi
__device__ __half g_whi[WTOT];                      // weights hi

// ---------------- helpers ----------------
__device__ __forceinline__ void split_f16(float v, __half& h, __half& l)
{
    h = __float2half_rn(v);
    l = __float2half_rn(v - __half2float(h));
}

// ---------------- embedding ----------------
__global__ void embed_kernel(const int* __restrict__ idx,
                             const float* __restrict__ tok,
                             const float* __restrict__ pos,
                             float* __restrict__ x)
{
    int i = blockIdx.x * blockDim.x + threadIdx.x;
    if (i >= MGPT * DGPT) return;
    int row = i / DGPT;
    int d   = i - row * DGPT;
    int t   = row & (TGPT - 1);
    x[i] = tok[(size_t)idx[row] * DGPT + d] + pos[(size_t)t * DGPT + d];
}

// ---------------- fp32 -> fp16 hi (8 elems/thread) ----------------
__global__ void __launch_bounds__(256) convhi_kernel(const float* __restrict__ in,
                                                     __half* __restrict__ hi,
                                                     size_t n8)
{
    size_t i = (size_t)blockIdx.x * blockDim.x + threadIdx.x;
    if (i >= n8) return;
    size_t e = i * 8;
    float4 a = *(const float4*)(in + e);
    float4 b = *(const float4*)(in + e + 4);
    __half2 h01 = __halves2half2(__float2half_rn(a.x), __float2half_rn(a.y));
    __half2 h23 = __halves2half2(__float2half_rn(a.z), __float2half_rn(a.w));
    __half2 h45 = __halves2half2(__float2half_rn(b.x), __float2half_rn(b.y));
    __half2 h67 = __halves2half2(__float2half_rn(b.z), __float2half_rn(b.w));
    uint4 ho;
    ho.x = *(uint32_t*)&h01; ho.y = *(uint32_t*)&h23;
    ho.z = *(uint32_t*)&h45; ho.w = *(uint32_t*)&h67;
    *(uint4*)(hi + e) = ho;
}

// ---------------- fp32 -> fp16 hi, scattered into fused QKV layout ----------
__global__ void __launch_bounds__(256) convqkv_kernel(const float* __restrict__ in,
                                                      __half* __restrict__ hi,
                                                      int which, size_t n4)
{
    size_t i = (size_t)blockIdx.x * blockDim.x + threadIdx.x;
    if (i >= n4) return;
    size_t e = i * 4;
    size_t layer = e / DD;
    size_t rem   = e - layer * DD;
    size_t de    = layer * 3 * DD + (size_t)which * DD + rem;
    float4 v = *(const float4*)(in + e);
    __half2 h01 = __halves2half2(__float2half_rn(v.x), __float2half_rn(v.y));
    __half2 h23 = __halves2half2(__float2half_rn(v.z), __float2half_rn(v.w));
    uint2 ho;
    ho.x = *(uint32_t*)&h01; ho.y = *(uint32_t*)&h23;
    *(uint2*)(hi + de) = ho;
}

// ---------------- layernorm (single pass): fp32 in -> fp16 hi (+lo) out -----
template<int WLO>
__global__ void __launch_bounds__(256) ln_kernel(const float* __restrict__ in,
                                                 __half* __restrict__ ohi,
                                                 __half* __restrict__ olo,
                                                 const float* __restrict__ w,
                                                 const float* __restrict__ b)
{
    int row = blockIdx.x;
    int tid = threadIdx.x;
    __shared__ float redS[8], redQ[8];

    float4 v = ((const float4*)(in + (size_t)row * DGPT))[tid];
    float s = v.x + v.y + v.z + v.w;
    float q = v.x * v.x + v.y * v.y + v.z * v.z + v.w * v.w;
    #pragma unroll
    for (int o = 16; o; o >>= 1) {
        s += __shfl_xor_sync(0xffffffffu, s, o);
        q += __shfl_xor_sync(0xffffffffu, q, o);
    }
    if ((tid & 31) == 0) { redS[tid >> 5] = s; redQ[tid >> 5] = q; }
    __syncthreads();
    if (tid < 32) {
        float ts = (tid < 8) ? redS[tid] : 0.f;
        float tq = (tid < 8) ? redQ[tid] : 0.f;
        #pragma unroll
        for (int o = 4; o; o >>= 1) {
            ts += __shfl_xor_sync(0xffffffffu, ts, o);
            tq += __shfl_xor_sync(0xffffffffu, tq, o);
        }
        if (tid == 0) { redS[0] = ts; redQ[0] = tq; }
    }
    __syncthreads();
    float mean = redS[0] * (1.f / DGPT);
    float var  = redQ[0] * (1.f / DGPT) - mean * mean;
    float rstd = rsqrtf(var + 1e-5f);

    float4 wv = ((const float4*)w)[tid];
    float4 bv = ((const float4*)b)[tid];
    float n0 = (v.x - mean) * rstd * wv.x + bv.x;
    float n1 = (v.y - mean) * rstd * wv.y + bv.y;
    float n2 = (v.z - mean) * rstd * wv.z + bv.z;
    float n3 = (v.w - mean) * rstd * wv.w + bv.w;

    __half h0, l0, h1, l1, h2, l2, h3, l3;
    split_f16(n0, h0, l0); split_f16(n1, h1, l1);
    split_f16(n2, h2, l2); split_f16(n3, h3, l3);
    uint2 ho;
    __half2 p01 = __halves2half2(h0, h1), p23 = __halves2half2(h2, h3);
    ho.x = *(uint32_t*)&p01; ho.y = *(uint32_t*)&p23;
    ((uint2*)(ohi + (size_t)row * DGPT))[tid] = ho;
    if (WLO) {
        __half2 q01 = __halves2half2(l0, l1), q23 = __halves2half2(l2, l3);
        uint2 lo2;
        lo2.x = *(uint32_t*)&q01; lo2.y = *(uint32_t*)&q23;
        ((uint2*)(olo + (size_t)row * DGPT))[tid] = lo2;
    }
}

// ---------------- tensor-core helpers ----------------
__device__ __forceinline__ void ldm4(uint32_t r[4], const __half* p)
{
    uint32_t a = (uint32_t)__cvta_generic_to_shared(p);
    asm volatile("ldmatrix.sync.aligned.m8n8.x4.shared.b16 {%0,%1,%2,%3}, [%4];\n"
                 : "=r"(r[0]), "=r"(r[1]), "=r"(r[2]), "=r"(r[3]) : "r"(a));
}
__device__ __forceinline__ void mma_f32(float c[4], const uint32_t a[4], const uint32_t b[2])
{
    asm volatile(
        "mma.sync.aligned.m16n8k16.row.col.f32.f16.f16.f32 "
        "{%0,%1,%2,%3}, {%4,%5,%6,%7}, {%8,%9}, {%0,%1,%2,%3};\n"
        : "+f"(c[0]), "+f"(c[1]), "+f"(c[2]), "+f"(c[3])
        : "r"(a[0]), "r"(a[1]), "r"(a[2]), "r"(a[3]), "r"(b[0]), "r"(b[1]));
}

#define BKg 32
#define PK  40
#define SMBUF (128*PK)
#define SMMAT (2*SMBUF)
#define GS1 (2*SMMAT*2)   // 40960 B
#define GS2 (3*SMMAT*2)   // 61440 B

// ---------------- GEMM (1-term): C = Ahi @ Whi^T, +bias +res fp32 out -------
__global__ void __launch_bounds__(256) gemm_tc(
    const __half* __restrict__ Ahi,
    const __half* __restrict__ Whi,
    const float* __restrict__ bias, const float* __restrict__ res,
    float* __restrict__ C,
    int M, int N, int K)
{
    extern __shared__ __align__(16) __half sm[];
    __half* sAh = sm;
    __half* sBh = sm + SMMAT;

    const int tid  = threadIdx.x;
    const int lane = tid & 31;
    const int wid  = tid >> 5;
    const int wm   = wid >> 2;
    const int wn   = wid & 3;
    const int bm   = blockIdx.y * 128;
    const int bn   = blockIdx.x * 128;

    const int lrow = tid >> 1;
    const int lcol = (tid & 1) << 4;
    const __half* gAh = Ahi + (size_t)(bm + lrow) * K + lcol;
    const __half* gBh = Whi + (size_t)(bn + lrow) * K + lcol;

    const int a_r = wm * 64 + (lane & 15);
    const int a_c = (lane >> 4) * 8;
    const int b_r = wn * 32 + (lane >> 4) * 8 + (lane & 7);
    const int b_c = ((lane >> 3) & 1) * 8;

    float acc[4][4][4];
    #pragma unroll
    for (int mi = 0; mi < 4; mi++)
        #pragma unroll
        for (int ni = 0; ni < 4; ni++)
            #pragma unroll
            for (int r = 0; r < 4; r++) acc[mi][ni][r] = 0.f;

    uint4 rAh0, rAh1, rBh0, rBh1;

    const int NS = K / BKg;
    rAh0 = *(const uint4*)(gAh);     rAh1 = *(const uint4*)(gAh + 8);
    rBh0 = *(const uint4*)(gBh);     rBh1 = *(const uint4*)(gBh + 8);
    {
        __half* p = sAh + lrow * PK + lcol;
        *(uint4*)p = rAh0; *(uint4*)(p + 8) = rAh1;
        p = sBh + lrow * PK + lcol;
        *(uint4*)p = rBh0; *(uint4*)(p + 8) = rBh1;
    }
    __syncthreads();

    for (int s = 0; s < NS; s++) {
        if (s + 1 < NS) {
            int k0 = (s + 1) * BKg;
            rAh0 = *(const uint4*)(gAh + k0);  rAh1 = *(const uint4*)(gAh + k0 + 8);
            rBh0 = *(const uint4*)(gBh + k0);  rBh1 = *(const uint4*)(gBh + k0 + 8);
        }

        const int bo = (s & 1) * SMBUF;
        #pragma unroll
        for (int ks = 0; ks < 2; ks++) {
            const int k0 = ks * 16;
            uint32_t afh[4][4];
            #pragma unroll
            for (int mi = 0; mi < 4; mi++)
                ldm4(afh[mi], sAh + bo + (a_r + mi * 16) * PK + k0 + a_c);
            uint32_t bfh[4][2];
            #pragma unroll
            for (int np = 0; np < 2; np++) {
                uint32_t t[4];
                ldm4(t, sBh + bo + (b_r + np * 16) * PK + k0 + b_c);
                bfh[np * 2][0] = t[0]; bfh[np * 2][1] = t[1];
                bfh[np * 2 + 1][0] = t[2]; bfh[np * 2 + 1][1] = t[3];
            }
            #pragma unroll
            for (int mi = 0; mi < 4; mi++)
                #pragma unroll
                for (int ni = 0; ni < 4; ni++)
                    mma_f32(acc[mi][ni], afh[mi], bfh[ni]);
        }

        if (s + 1 < NS) {
            const int bo2 = ((s + 1) & 1) * SMBUF;
            __half* p = sAh + bo2 + lrow * PK + lcol;
            *(uint4*)p = rAh0; *(uint4*)(p + 8) = rAh1;
            p = sBh + bo2 + lrow * PK + lcol;
            *(uint4*)p = rBh0; *(uint4*)(p + 8) = rBh1;
            __syncthreads();
        }
    }

    const int er = bm + wm * 64 + (lane >> 2);
    const int ec = bn + wn * 32 + (lane & 3) * 2;
    #pragma unroll
    for (int mi = 0; mi < 4; mi++) {
        #pragma unroll
        for (int ni = 0; ni < 4; ni++) {
            const int col = ec + ni * 8;
            #pragma unroll
            for (int h = 0; h < 2; h++) {
                const size_t row = (size_t)(er + mi * 16 + h * 8);
                float v0 = acc[mi][ni][h * 2]     + bias[col];
                float v1 = acc[mi][ni][h * 2 + 1] + bias[col + 1];
                v0 += res[row * N + col];
                v1 += res[row * N + col + 1];
                float2 o; o.x = v0; o.y = v1;
                *(float2*)(C + row * N + col) = o;
            }
        }
    }
}

// ---------------- fused QKV GEMM: [M,3072] = Ahi @ Wqkv^T, fp16 hi out ------
__global__ void __launch_bounds__(256) gemm_qkv(
    const __half* __restrict__ Ahi,
    const __half* __restrict__ Wf,
    const float* __restrict__ bq, const float* __restrict__ bk,
    const float* __restrict__ bv,
    __half* __restrict__ Chi)
{
    extern __shared__ __align__(16) __half sm[];
    __half* sAh = sm;
    __half* sBh = sm + SMMAT;

    const int K = DGPT;
    const int tid  = threadIdx.x;
    const int lane = tid & 31;
    const int wid  = tid >> 5;
    const int wm   = wid >> 2;
    const int wn   = wid & 3;
    const int bm   = blockIdx.y * 128;
    const int bn   = blockIdx.x * 128;

    const int tsel = bn >> 10;
    const float* bias = (tsel == 0) ? bq : ((tsel == 1) ? bk : bv);
    const int cb = bn - (tsel << 10);

    const int lrow = tid >> 1;
    const int lcol = (tid & 1) << 4;
    const __half* gAh = Ahi + (size_t)(bm + lrow) * K + lcol;
    const __half* gBh = Wf  + (size_t)(bn + lrow) * K + lcol;

    const int a_r = wm * 64 + (lane & 15);
    const int a_c = (lane >> 4) * 8;
    const int b_r = wn * 32 + (lane >> 4) * 8 + (lane & 7);
    const int b_c = ((lane >> 3) & 1) * 8;

    float acc[4][4][4];
    #pragma unroll
    for (int mi = 0; mi < 4; mi++)
        #pragma unroll
        for (int ni = 0; ni < 4; ni++)
            #pragma unroll
            for (int r = 0; r < 4; r++) acc[mi][ni][r] = 0.f;

    uint4 rAh0, rAh1, rBh0, rBh1;
    const int NS = K / BKg;
    rAh0 = *(const uint4*)(gAh);     rAh1 = *(const uint4*)(gAh + 8);
    rBh0 = *(const uint4*)(gBh);     rBh1 = *(const uint4*)(gBh + 8);
    {
        __half* p = sAh + lrow * PK + lcol;
        *(uint4*)p = rAh0; *(uint4*)(p + 8) = rAh1;
        p = sBh + lrow * PK + lcol;
        *(uint4*)p = rBh0; *(uint4*)(p + 8) = rBh1;
    }
    __syncthreads();

    for (int s = 0; s < NS; s++) {
        if (s + 1 < NS) {
            int k0 = (s + 1) * BKg;
            rAh0 = *(const uint4*)(gAh + k0);  rAh1 = *(const uint4*)(gAh + k0 + 8);
            rBh0 = *(const uint4*)(gBh + k0);  rBh1 = *(const uint4*)(gBh + k0 + 8);
        }
        const int bo = (s & 1) * SMBUF;
        #pragma unroll
        for (int ks = 0; ks < 2; ks++) {
            const int k0 = ks * 16;
            uint32_t afh[4][4];
            #pragma unroll
            for (int mi = 0; mi < 4; mi++)
                ldm4(afh[mi], sAh + bo + (a_r + mi * 16) * PK + k0 + a_c);
            uint32_t bfh[4][2];
            #pragma unroll
            for (int np = 0; np < 2; np++) {
                uint32_t t[4];
                ldm4(t, sBh + bo + (b_r + np * 16) * PK + k0 + b_c);
                bfh[np * 2][0] = t[0]; bfh[np * 2][1] = t[1];
                bfh[np * 2 + 1][0] = t[2]; bfh[np * 2 + 1][1] = t[3];
            }
            #pragma unroll
            for (int mi = 0; mi < 4; mi++)
                #pragma unroll
                for (int ni = 0; ni < 4; ni++)
                    mma_f32(acc[mi][ni], afh[mi], bfh[ni]);
        }
        if (s + 1 < NS) {
            const int bo2 = ((s + 1) & 1) * SMBUF;
            __half* p = sAh + bo2 + lrow * PK + lcol;
            *(uint4*)p = rAh0; *(uint4*)(p + 8) = rAh1;
            p = sBh + bo2 + lrow * PK + lcol;
            *(uint4*)p = rBh0; *(uint4*)(p + 8) = rBh1;
            __syncthreads();
        }
    }

    const int er  = bm + wm * 64 + (lane >> 2);
    const int ecl = cb + wn * 32 + (lane & 3) * 2;
    const int ecg = bn + wn * 32 + (lane & 3) * 2;
    #pragma unroll
    for (int mi = 0; mi < 4; mi++) {
        #pragma unroll
        for (int ni = 0; ni < 4; ni++) {
            const int coll = ecl + ni * 8;
            const int colg = ecg + ni * 8;
            const float b0 = bias[coll], b1 = bias[coll + 1];
            #pragma unroll
            for (int h = 0; h < 2; h++) {
                const size_t row = (size_t)(er + mi * 16 + h * 8);
                float v0 = acc[mi][ni][h * 2]     + b0;
                float v1 = acc[mi][ni][h * 2 + 1] + b1;
                *(__half2*)(Chi + row * QKVS + colg) =
                    __halves2half2(__float2half_rn(v0), __float2half_rn(v1));
            }
        }
    }
}

// ---------------- fused heads GEMM: 2-term (Ahi+Alo) @ Whi^T, fp32 out ------
__global__ void __launch_bounds__(256) gemm_heads(
    const __half* __restrict__ Ahi, const __half* __restrict__ Alo,
    const __half* __restrict__ Whi,
    float* __restrict__ out)
{
    extern __shared__ __align__(16) __half sm[];
    __half* sAh = sm;
    __half* sAl = sm + SMMAT;
    __half* sBh = sm + 2 * SMMAT;

    const int K = DGPT;
    const int tid  = threadIdx.x;
    const int lane = tid & 31;
    const int wid  = tid >> 5;
    const int wm   = wid >> 2;
    const int wn   = wid & 3;
    const int bm   = blockIdx.y * 128;
    const int bn   = blockIdx.x * 128;

    const int tsel = bn >> 12;
    float* C = out + (size_t)tsel * MGPT * VGPT;
    const int cb = bn - (tsel << 12);

    const int lrow = tid >> 1;
    const int lcol = (tid & 1) << 4;
    const __half* gAh = Ahi + (size_t)(bm + lrow) * K + lcol;
    const __half* gAl = Alo + (size_t)(bm + lrow) * K + lcol;
    const __half* gBh = Whi + (size_t)(bn + lrow) * K + lcol;

    const int a_r = wm * 64 + (lane & 15);
    const int a_c = (lane >> 4) * 8;
    const int b_r = wn * 32 + (lane >> 4) * 8 + (lane & 7);
    const int b_c = ((lane >> 3) & 1) * 8;

    float acc[4][4][4];
    #pragma unroll
    for (int mi = 0; mi < 4; mi++)
        #pragma unroll
        for (int ni = 0; ni < 4; ni++)
            #pragma unroll
            for (int r = 0; r < 4; r++) acc[mi][ni][r] = 0.f;

    uint4 rAh0, rAh1, rAl0, rAl1, rBh0, rBh1;
    const int NS = K / BKg;
    rAh0 = *(const uint4*)(gAh);  rAh1 = *(const uint4*)(gAh + 8);
    rAl0 = *(const uint4*)(gAl);  rAl1 = *(const uint4*)(gAl + 8);
    rBh0 = *(const uint4*)(gBh);  rBh1 = *(const uint4*)(gBh + 8);
    {
        __half* p = sAh + lrow * PK + lcol;
        *(uint4*)p = rAh0; *(uint4*)(p + 8) = rAh1;
        p = sAl + lrow * PK + lcol;
        *(uint4*)p = rAl0; *(uint4*)(p + 8) = rAl1;
        p = sBh + lrow * PK + lcol;
        *(uint4*)p = rBh0; *(uint4*)(p + 8) = rBh1;
    }
    __syncthreads();

    for (int s = 0; s < NS; s++) {
        if (s + 1 < NS) {
            int k0 = (s + 1) * BKg;
            rAh0 = *(const uint4*)(gAh + k0);  rAh1 = *(const uint4*)(gAh + k0 + 8);
            rAl0 = *(const uint4*)(gAl + k0);  rAl1 = *(const uint4*)(gAl + k0 + 8);
            rBh0 = *(const uint4*)(gBh + k0);  rBh1 = *(const uint4*)(gBh + k0 + 8);
        }
        const int bo = (s & 1) * SMBUF;
        #pragma unroll
        for (int ks = 0; ks < 2; ks++) {
            const int k0 = ks * 16;
            uint32_t bfh[4][2];
            #pragma unroll
            for (int np = 0; np < 2; np++) {
                uint32_t t[4];
                ldm4(t, sBh + bo + (b_r + np * 16) * PK + k0 + b_c);
                bfh[np * 2][0] = t[0]; bfh[np * 2][1] = t[1];
                bfh[np * 2 + 1][0] = t[2]; bfh[np * 2 + 1][1] = t[3];
            }
            uint32_t af[4][4];
            #pragma unroll
            for (int mi = 0; mi < 4; mi++)
                ldm4(af[mi], sAh + bo + (a_r + mi * 16) * PK + k0 + a_c);
            #pragma unroll
            for (int mi = 0; mi < 4; mi++)
                #pragma unroll
                for (int ni = 0; ni < 4; ni++)
                    mma_f32(acc[mi][ni], af[mi], bfh[ni]);
            #pragma unroll
            for (int mi = 0; mi < 4; mi++)
                ldm4(af[mi], sAl + bo + (a_r + mi * 16) * PK + k0 + a_c);
            #pragma unroll
            for (int mi = 0; mi < 4; mi++)
                #pragma unroll
                for (int ni = 0; ni < 4; ni++)
                    mma_f32(acc[mi][ni], af[mi], bfh[ni]);
        }
        if (s + 1 < NS) {
            const int bo2 = ((s + 1) & 1) * SMBUF;
            __half* p = sAh + bo2 + lrow * PK + lcol;
            *(uint4*)p = rAh0; *(uint4*)(p + 8) = rAh1;
            p = sAl + bo2 + lrow * PK + lcol;
            *(uint4*)p = rAl0; *(uint4*)(p + 8) = rAl1;
            p = sBh + bo2 + lrow * PK + lcol;
            *(uint4*)p = rBh0; *(uint4*)(p + 8) = rBh1;
            __syncthreads();
        }
    }

    const int er = bm + wm * 64 + (lane >> 2);
    const int ec = cb + wn * 32 + (lane & 3) * 2;
    #pragma unroll
    for (int mi = 0; mi < 4; mi++) {
        #pragma unroll
        for (int ni = 0; ni < 4; ni++) {
            const int col = ec + ni * 8;
            #pragma unroll
            for (int h = 0; h < 2; h++) {
                const size_t row = (size_t)(er + mi * 16 + h * 8);
                float2 o;
                o.x = acc[mi][ni][h * 2];
                o.y = acc[mi][ni][h * 2 + 1];
                *(float2*)(C + row * VGPT + col) = o;
            }
        }
    }
}

// ---------------- GEMM (BN=256, warp 64x64) for W1: GELU, fp16 hi out ------
#define W1_SA (128*PK)
#define W1_SB (256*PK)
#define W1_STG (W1_SA + W1_SB)
#define GSW (2*W1_STG*2)

__global__ void __launch_bounds__(256) gemm_w1(
    const __half* __restrict__ Ahi, const __half* __restrict__ Whi,
    const float* __restrict__ bias, __half* __restrict__ Chi,
    int M, int N, int K)
{
    extern __shared__ __align__(16) __half sm[];

    const int tid  = threadIdx.x;
    const int lane = tid & 31;
    const int wid  = tid >> 5;
    const int wm   = wid >> 2;
    const int wn   = wid & 3;
    const int bm   = blockIdx.y * 128;
    const int bn   = blockIdx.x * 256;

    const int lrow = tid >> 1;
    const int lcol = (tid & 1) << 4;
    const __half* gA  = Ahi + (size_t)(bm + lrow) * K + lcol;
    const __half* gB0 = Whi + (size_t)(bn + lrow) * K + lcol;
    const __half* gB1 = Whi + (size_t)(bn + 128 + lrow) * K + lcol;

    const int a_r = wm * 64 + (lane & 15);
    const int a_c = (lane >> 4) * 8;
    const int b_r = wn * 64 + (lane >> 4) * 8 + (lane & 7);
    const int b_c = ((lane >> 3) & 1) * 8;

    float acc[4][8][4];
    #pragma unroll
    for (int mi = 0; mi < 4; mi++)
        #pragma unroll
        for (int ni = 0; ni < 8; ni++)
            #pragma unroll
            for (int r = 0; r < 4; r++) acc[mi][ni][r] = 0.f;

    uint4 rA0, rA1, rB00, rB01, rB10, rB11;

    const int NS = K / BKg;
    rA0  = *(const uint4*)(gA);      rA1  = *(const uint4*)(gA + 8);
    rB00 = *(const uint4*)(gB0);     rB01 = *(const uint4*)(gB0 + 8);
    rB10 = *(const uint4*)(gB1);     rB11 = *(const uint4*)(gB1 + 8);
    {
        __half* p = sm + lrow * PK + lcol;
        *(uint4*)p = rA0; *(uint4*)(p + 8) = rA1;
        p = sm + W1_SA + lrow * PK + lcol;
        *(uint4*)p = rB00; *(uint4*)(p + 8) = rB01;
        p = sm + W1_SA + (128 + lrow) * PK + lcol;
        *(uint4*)p = rB10; *(uint4*)(p + 8) = rB11;
    }
    __syncthreads();

    for (int s = 0; s < NS; s++) {
        if (s + 1 < NS) {
            int k0 = (s + 1) * BKg;
            rA0  = *(const uint4*)(gA + k0);   rA1  = *(const uint4*)(gA + k0 + 8);
            rB00 = *(const uint4*)(gB0 + k0);  rB01 = *(const uint4*)(gB0 + k0 + 8);
            rB10 = *(const uint4*)(gB1 + k0);  rB11 = *(const uint4*)(gB1 + k0 + 8);
        }

        const __half* stg = sm + (s & 1) * W1_STG;
        const __half* sA = stg;
        const __half* sB = stg + W1_SA;
        #pragma unroll
        for (int ks = 0; ks < 2; ks++) {
            const int k0 = ks * 16;
            uint32_t af[4][4];
            #pragma unroll
            for (int mi = 0; mi < 4; mi++)
                ldm4(af[mi], sA + (a_r + mi * 16) * PK + k0 + a_c);
            uint32_t bf[8][2];
            #pragma unroll
            for (int nb = 0; nb < 4; nb++) {
                uint32_t t[4];
                ldm4(t, sB + (b_r + nb * 16) * PK + k0 + b_c);
                bf[nb * 2][0] = t[0]; bf[nb * 2][1] = t[1];
                bf[nb * 2 + 1][0] = t[2]; bf[nb * 2 + 1][1] = t[3];
            }
            #pragma unroll
            for (int mi = 0; mi < 4; mi++)
                #pragma unroll
                for (int ni = 0; ni < 8; ni++)
                    mma_f32(acc[mi][ni], af[mi], bf[ni]);
        }

        if (s + 1 < NS) {
            __half* stg2 = sm + ((s + 1) & 1) * W1_STG;
            __half* p = stg2 + lrow * PK + lcol;
            *(uint4*)p = rA0; *(uint4*)(p + 8) = rA1;
            p = stg2 + W1_SA + lrow * PK + lcol;
            *(uint4*)p = rB00; *(uint4*)(p + 8) = rB01;
            p = stg2 + W1_SA + (128 + lrow) * PK + lcol;
            *(uint4*)p = rB10; *(uint4*)(p + 8) = rB11;
            __syncthreads();
        }
    }

    const int er = bm + wm * 64 + (lane >> 2);
    const int ec = bn + wn * 64 + (lane & 3) * 2;
    #pragma unroll
    for (int mi = 0; mi < 4; mi++) {
        #pragma unroll
        for (int ni = 0; ni < 8; ni++) {
            const int col = ec + ni * 8;
            const float b0 = bias[col], b1 = bias[col + 1];
            #pragma unroll
            for (int h = 0; h < 2; h++) {
                const size_t row = (size_t)(er + mi * 16 + h * 8);
                float v0 = acc[mi][ni][h * 2]     + b0;
                float v1 = acc[mi][ni][h * 2 + 1] + b1;
                v0 = 0.5f * v0 * (1.f + erff(v0 * 0.70710678118654752f));
                v1 = 0.5f * v1 * (1.f + erff(v1 * 0.70710678118654752f));
                *(__half2*)(Chi + row * N + col) =
                    __halves2half2(__float2half_rn(v0), __float2half_rn(v1));
            }
        }
    }
}

// ---------------- tensor-core flash attention ----------------
// Q-block 128 rows, 8 warps. S = Qhi*Khi; O += P16 * Vhi. (all hi)
#define ATS 72
#define ATT_SMEM ((128 + 2*64)*ATS*2)   // 36864 B

__global__ void __launch_bounds__(256) attn_mma(
    const __half* __restrict__ qkvh,
    __half* __restrict__ yhi)
{
    extern __shared__ __align__(16) __half sa[];
    __half* sQh = sa;                     // 128 x ATS
    __half* sKh = sa + 128 * ATS;         // 64 x ATS
    __half* sVh = sa + 192 * ATS;         // transposed: [d][kv] 64 x ATS

    const int bh = blockIdx.x;
    const int b  = bh / HGPT;
    const int h  = bh % HGPT;
    const int qb = blockIdx.y;            // 128-row q block
    const int tid  = threadIdx.x;
    const int w    = tid >> 5;
    const int lane = tid & 31;

    const size_t rowb = (size_t)(b * TGPT);
    const int hoff = h * HDH;

    // Q tile (128x64, hi)
    for (int f = tid; f < 1024; f += 256) {
        int r = f >> 3, c8 = (f & 7) * 8;
        size_t g = (rowb + qb * 128 + r) * QKVS + hoff + c8;
        *(uint4*)(sQh + r * ATS + c8) = *(const uint4*)(qkvh + g);
    }

    float O[8][4];
    #pragma unroll
    for (int t = 0; t < 8; t++)
        #pragma unroll
        for (int r = 0; r < 4; r++) O[t][r] = 0.f;
    float m1 = -1e30f, m2 = -1e30f, l1 = 0.f, l2 = 0.f;

    const int a_row  = w * 16 + (lane & 15);
    const int a_coff = (lane >> 4) * 8;
    const int b_row  = (lane >> 4) * 8 + (lane & 7);
    const int b_coff = ((lane >> 3) & 1) * 8;
    const int rl1 = w * 16 + (lane >> 2);
    const int cl0 = 2 * (lane & 3);
    const int grow1 = qb * 128 + rl1;

    const int nch = 2 * qb + 2;
    for (int ch = 0; ch < nch; ch++) {
        const int j0 = ch * 64;
        __syncthreads();
        for (int f = tid; f < 512; f += 256) {
            int r = f >> 3, c8 = (f & 7) * 8;
            size_t g = (rowb + j0 + r) * QKVS + DGPT + hoff + c8;
            *(uint4*)(sKh + r * ATS + c8) = *(const uint4*)(qkvh + g);
        }
        for (int f = tid; f < 1024; f += 256) {     // V hi transposed
            int r = f >> 4, c4 = (f & 15) * 4;
            size_t g = (rowb + j0 + r) * QKVS + 2 * DGPT + hoff + c4;
            uint2 hv = *(const uint2*)(qkvh + g);
            __half2 h01 = *(__half2*)&hv.x, h23 = *(__half2*)&hv.y;
            sVh[(c4 + 0) * ATS + r] = __low2half(h01);
            sVh[(c4 + 1) * ATS + r] = __high2half(h01);
            sVh[(c4 + 2) * ATS + r] = __low2half(h23);
            sVh[(c4 + 3) * ATS + r] = __high2half(h23);
        }
        __syncthreads();

        float S[8][4];
        #pragma unroll
        for (int t = 0; t < 8; t++)
            #pragma unroll
            for (int r = 0; r < 4; r++) S[t][r] = 0.f;

        #pragma unroll
        for (int ks = 0; ks < 4; ks++) {
            uint32_t aqh[4];
            ldm4(aqh, sQh + a_row * ATS + ks * 16 + a_coff);
            #pragma unroll
            for (int nb = 0; nb < 4; nb++) {
                uint32_t t4[4];
                ldm4(t4, sKh + (nb * 16 + b_row) * ATS + ks * 16 + b_coff);
                uint32_t bh0[2] = { t4[0], t4[1] };
                uint32_t bh1[2] = { t4[2], t4[3] };
                mma_f32(S[2 * nb],     aqh, bh0);
                mma_f32(S[2 * nb + 1], aqh, bh1);
            }
        }

        const bool diag = (ch >= 2 * qb);
        #pragma unroll
        for (int t = 0; t < 8; t++) {
            S[t][0] *= 0.125f; S[t][1] *= 0.125f;
            S[t][2] *= 0.125f; S[t][3] *= 0.125f;
            if (diag) {
                int c0 = j0 + t * 8 + cl0, c1 = c0 + 1;
                if (c0 > grow1)     S[t][0] = -1e30f;
                if (c1 > grow1)     S[t][1] = -1e30f;
                if (c0 > grow1 + 8) S[t][2] = -1e30f;
                if (c1 > grow1 + 8) S[t][3] = -1e30f;
            }
        }

        float mx1 = -1e30f, mx2 = -1e30f;
        #pragma unroll
        for (int t = 0; t < 8; t++) {
            mx1 = fmaxf(mx1, fmaxf(S[t][0], S[t][1]));
            mx2 = fmaxf(mx2, fmaxf(S[t][2], S[t][3]));
        }
        mx1 = fmaxf(mx1, __shfl_xor_sync(0xffffffffu, mx1, 1));
        mx1 = fmaxf(mx1, __shfl_xor_sync(0xffffffffu, mx1, 2));
        mx2 = fmaxf(mx2, __shfl_xor_sync(0xffffffffu, mx2, 1));
        mx2 = fmaxf(mx2, __shfl_xor_sync(0xffffffffu, mx2, 2));

        float mn1 = fmaxf(m1, mx1), mn2 = fmaxf(m2, mx2);
        float cr1 = __expf(m1 - mn1), cr2 = __expf(m2 - mn2);
        m1 = mn1; m2 = mn2;

        float s1 = 0.f, s2 = 0.f;
        uint32_t Pf[4][4];
        #pragma unroll
        for (int t = 0; t < 8; t++) {
            float p0 = __expf(S[t][0] - mn1);
            float p1 = __expf(S[t][1] - mn1);
            float p2 = __expf(S[t][2] - mn2);
            float p3 = __expf(S[t][3] - mn2);
            s1 += p0 + p1; s2 += p2 + p3;
            __half2 ph01 = __halves2half2(__float2half_rn(p0), __float2half_rn(p1));
            __half2 ph23 = __halves2half2(__float2half_rn(p2), __float2half_rn(p3));
            const int kt = t >> 1, hf = (t & 1) * 2;
            Pf[kt][hf + 0] = *(uint32_t*)&ph01;
            Pf[kt][hf + 1] = *(uint32_t*)&ph23;
        }
        s1 += __shfl_xor_sync(0xffffffffu, s1, 1);
        s1 += __shfl_xor_sync(0xffffffffu, s1, 2);
        s2 += __shfl_xor_sync(0xffffffffu, s2, 1);
        s2 += __shfl_xor_sync(0xffffffffu, s2, 2);
        l1 = l1 * cr1 + s1;
        l2 = l2 * cr2 + s2;
        #pragma unroll
        for (int t = 0; t < 8; t++) {
            O[t][0] *= cr1; O[t][1] *= cr1;
            O[t][2] *= cr2; O[t][3] *= cr2;
        }

        #pragma unroll
        for (int kt = 0; kt < 4; kt++) {
            #pragma unroll
            for (int nb = 0; nb < 4; nb++) {
                uint32_t t4[4];
                ldm4(t4, sVh + (nb * 16 + b_row) * ATS + kt * 16 + b_coff);
                uint32_t bv0[2] = { t4[0], t4[1] };
                uint32_t bv1[2] = { t4[2], t4[3] };
                mma_f32(O[2 * nb],     Pf[kt], bv0);
                mma_f32(O[2 * nb + 1], Pf[kt], bv1);
            }
        }
    }

    const float inv1 = 1.f / l1, inv2 = 1.f / l2;
    const size_t row1 = (rowb + qb * 128 + rl1) * DGPT + hoff;
    const size_t row2 = (rowb + qb * 128 + rl1 + 8) * DGPT + hoff;
    #pragma unroll
    for (int t = 0; t < 8; t++) {
        const int col = t * 8 + cl0;
        *(__half2*)(yhi + row1 + col) =
            __halves2half2(__float2half_rn(O[t][0] * inv1), __float2half_rn(O[t][1] * inv1));
        *(__half2*)(yhi + row2 + col) =
            __halves2half2(__float2half_rn(O[t][2] * inv2), __float2half_rn(O[t][3] * inv2));
    }
}

// ---------------- launcher ----------------
static inline void convhi(const float* in, __half* hi, size_t n)
{
    size_t n8 = n / 8;
    convhi_kernel<<<(unsigned)((n8 + 255) / 256), 256>>>(in, hi, n8);
}

extern "C" void kernel_launch(void* const* d_in, const int* in_sizes, int n_in,
                              void* d_out, int out_size)
{
    const int*   idx    = (const int*)  d_in[0];
    const float* tok    = (const float*)d_in[1];
    const float* pos    = (const float*)d_in[2];
    const float* ln1_w  = (const float*)d_in[3];
    const float* ln1_b  = (const float*)d_in[4];
    const float* Wq     = (const float*)d_in[5];
    const float* bq     = (const float*)d_in[6];
    const float* Wk     = (const float*)d_in[7];
    const float* bk     = (const float*)d_in[8];
    const float* Wv     = (const float*)d_in[9];
    const float* bv     = (const float*)d_in[10];
    const float* Wproj  = (const float*)d_in[11];
    const float* bproj  = (const float*)d_in[12];
    const float* ln2_w  = (const float*)d_in[13];
    const float* ln2_b  = (const float*)d_in[14];
    const float* W1     = (const float*)d_in[15];
    const float* b1     = (const float*)d_in[16];
    const float* W2     = (const float*)d_in[17];
    const float* b2     = (const float*)d_in[18];
    const float* lnf_w  = (const float*)d_in[19];
    const float* lnf_b  = (const float*)d_in[20];
    const float* Wlogit = (const float*)d_in[21];
    const float* Wdev   = (const float*)d_in[22];
    float* out = (float*)d_out;

    float* xp;
    __half *whi, *ahi, *alo, *fhi, *qkvh;
    cudaGetSymbolAddress((void**)&xp,   g_x);
    cudaGetSymbolAddress((void**)&whi,  g_whi);
    cudaGetSymbolAddress((void**)&ahi,  g_ahi);
    cudaGetSymbolAddress((void**)&alo,  g_alo);
    cudaGetSymbolAddress((void**)&fhi,  g_fhi);
    cudaGetSymbolAddress((void**)&qkvh, g_qkvh);

    cudaFuncSetAttribute((const void*)gemm_tc,    cudaFuncAttributeMaxDynamicSharedMemorySize, GS1);
    cudaFuncSetAttribute((const void*)gemm_qkv,   cudaFuncAttributeMaxDynamicSharedMemorySize, GS1);
    cudaFuncSetAttribute((const void*)gemm_heads, cudaFuncAttributeMaxDynamicSharedMemorySize, GS2);
    cudaFuncSetAttribute((const void*)gemm_w1,    cudaFuncAttributeMaxDynamicSharedMemorySize, GSW);
    cudaFuncSetAttribute((const void*)attn_mma,   cudaFuncAttributeMaxDynamicSharedMemorySize, ATT_SMEM);

    {
        size_t n4 = (LGPT * DD) / 4;
        unsigned g = (unsigned)((n4 + 255) / 256);
        convqkv_kernel<<<g, 256>>>(Wq, whi + O_QKV, 0, n4);
        convqkv_kernel<<<g, 256>>>(Wk, whi + O_QKV, 1, n4);
        convqkv_kernel<<<g, 256>>>(Wv, whi + O_QKV, 2, n4);
    }
    convhi(Wproj,  whi + O_WP,  LGPT * DD);
    convhi(W1,     whi + O_W1,  (size_t)LGPT * 4 * DD);
    convhi(W2,     whi + O_W2,  (size_t)LGPT * 4 * DD);
    convhi(Wlogit, whi + O_WLG, 4 * DD);
    convhi(Wdev,   whi + O_WDV, 4 * DD);

    dim3 gQ(QKVS / 128, MGPT / 128);
    dim3 gD(DGPT / 128, MGPT / 128);
    dim3 gW(FGPT / 256, MGPT / 128);
    dim3 gH(2 * VGPT / 128, MGPT / 128);
    dim3 gA(BGPT * HGPT, TGPT / 128);

    embed_kernel<<<(MGPT * DGPT + 255) / 256, 256>>>(idx, tok, pos, xp);

    for (int l = 0; l < LGPT; l++) {
        size_t oQ  = O_QKV + (size_t)l * 3 * DD;
        size_t oP  = O_WP  + (size_t)l * DD;
        size_t o1  = O_W1  + (size_t)l * 4 * DD;
        size_t o2  = O_W2  + (size_t)l * 4 * DD;
        size_t ob  = (size_t)l * DGPT;
        size_t obf = (size_t)l * FGPT;

        ln_kernel<0><<<MGPT, 256>>>(xp, ahi, nullptr, ln1_w + ob, ln1_b + ob);
        gemm_qkv<<<gQ, 256, GS1>>>(ahi, whi + oQ, bq + ob, bk + ob, bv + ob, qkvh);
        attn_mma<<<gA, 256, ATT_SMEM>>>(qkvh, ahi);
        gemm_tc<<<gD, 256, GS1>>>(ahi, whi + oP, bproj + ob, xp, xp, MGPT, DGPT, DGPT);

        ln_kernel<0><<<MGPT, 256>>>(xp, ahi, nullptr, ln2_w + ob, ln2_b + ob);
        gemm_w1<<<gW, 256, GSW>>>(ahi, whi + o1, b1 + obf, fhi, MGPT, FGPT, DGPT);
        gemm_tc<<<gD, 256, GS1>>>(fhi, whi + o2, b2 + ob, xp, xp, MGPT, DGPT, FGPT);
    }

    ln_kernel<1><<<MGPT, 256>>>(xp, ahi, alo, lnf_w, lnf_b);
    gemm_heads<<<gH, 256, GS2>>>(ahi, alo, whi + O_WLG, out);
}

// round 17
// speedup vs baseline: 6.9350x; 1.0268x over previous
#include <cuda_runtime.h>
#include <cuda_fp16.h>
#include <math.h>
#include <stdint.h>

// ---------------- problem constants ----------------
#define BGPT 4
#define TGPT 1024
#define DGPT 1024
#define HGPT 16
#define HDH  64
#define LGPT 8
#define VGPT 4096
#define MGPT (BGPT*TGPT)   // 4096 tokens
#define FGPT (4*DGPT)      // 4096 ff dim
#define QKVS (3*DGPT)      // fused qkv row stride (3072)

// weight layout (fp16 hi, element offsets)
#define DD    ((size_t)DGPT*DGPT)
#define O_QKV ((size_t)0)
#define O_WP  ((size_t)LGPT*3*DD)
#define O_W1  (O_WP + (size_t)LGPT*DD)
#define O_W2  (O_W1 + (size_t)LGPT*4*DD)
#define O_WLG (O_W2 + (size_t)LGPT*4*DD)
#define O_WDV (O_WLG + 4*DD)
#define WTOT  (O_WDV + 4*DD)

// ---------------- scratch (device globals; no allocs allowed) ----------------
__device__ float  g_x[MGPT*DGPT];                   // residual stream (fp32)
__device__ __half g_qkvh[(size_t)MGPT*QKVS];        // fused qkv hi
__device__ __half g_ahi[(size_t)MGPT*DGPT];         // activation hi
__device__ __half g_fhi[(size_t)MGPT*FGPT];         // ff activation hi
__device__ __half g_whi[WTOT];                      // weights hi

// ---------------- helpers ----------------
__device__ __forceinline__ void split_f16(float v, __half& h, __half& l)
{
    h = __float2half_rn(v);
    l = __float2half_rn(v - __half2float(h));
}

// ---------------- embedding ----------------
__global__ void embed_kernel(const int* __restrict__ idx,
                             const float* __restrict__ tok,
                             const float* __restrict__ pos,
                             float* __restrict__ x)
{
    int i = blockIdx.x * blockDim.x + threadIdx.x;
    if (i >= MGPT * DGPT) return;
    int row = i / DGPT;
    int d   = i - row * DGPT;
    int t   = row & (TGPT - 1);
    x[i] = tok[(size_t)idx[row] * DGPT + d] + pos[(size_t)t * DGPT + d];
}

// ---------------- fp32 -> fp16 hi (8 elems/thread) ----------------
__global__ void __launch_bounds__(256) convhi_kernel(const float* __restrict__ in,
                                                     __half* __restrict__ hi,
                                                     size_t n8)
{
    size_t i = (size_t)blockIdx.x * blockDim.x + threadIdx.x;
    if (i >= n8) return;
    size_t e = i * 8;
    float4 a = *(const float4*)(in + e);
    float4 b = *(const float4*)(in + e + 4);
    __half2 h01 = __halves2half2(__float2half_rn(a.x), __float2half_rn(a.y));
    __half2 h23 = __halves2half2(__float2half_rn(a.z), __float2half_rn(a.w));
    __half2 h45 = __halves2half2(__float2half_rn(b.x), __float2half_rn(b.y));
    __half2 h67 = __halves2half2(__float2half_rn(b.z), __float2half_rn(b.w));
    uint4 ho;
    ho.x = *(uint32_t*)&h01; ho.y = *(uint32_t*)&h23;
    ho.z = *(uint32_t*)&h45; ho.w = *(uint32_t*)&h67;
    *(uint4*)(hi + e) = ho;
}

// ---------------- fp32 -> fp16 hi, scattered into fused QKV layout ----------
__global__ void __launch_bounds__(256) convqkv_kernel(const float* __restrict__ in,
                                                      __half* __restrict__ hi,
                                                      int which, size_t n4)
{
    size_t i = (size_t)blockIdx.x * blockDim.x + threadIdx.x;
    if (i >= n4) return;
    size_t e = i * 4;
    size_t layer = e / DD;
    size_t rem   = e - layer * DD;
    size_t de    = layer * 3 * DD + (size_t)which * DD + rem;
    float4 v = *(const float4*)(in + e);
    __half2 h01 = __halves2half2(__float2half_rn(v.x), __float2half_rn(v.y));
    __half2 h23 = __halves2half2(__float2half_rn(v.z), __float2half_rn(v.w));
    uint2 ho;
    ho.x = *(uint32_t*)&h01; ho.y = *(uint32_t*)&h23;
    *(uint2*)(hi + de) = ho;
}

// ---------------- layernorm (single pass): fp32 in -> fp16 hi out ----------
__global__ void __launch_bounds__(256) ln_kernel(const float* __restrict__ in,
                                                 __half* __restrict__ ohi,
                                                 const float* __restrict__ w,
                                                 const float* __restrict__ b)
{
    int row = blockIdx.x;
    int tid = threadIdx.x;
    __shared__ float redS[8], redQ[8];

    float4 v = ((const float4*)(in + (size_t)row * DGPT))[tid];
    float s = v.x + v.y + v.z + v.w;
    float q = v.x * v.x + v.y * v.y + v.z * v.z + v.w * v.w;
    #pragma unroll
    for (int o = 16; o; o >>= 1) {
        s += __shfl_xor_sync(0xffffffffu, s, o);
        q += __shfl_xor_sync(0xffffffffu, q, o);
    }
    if ((tid & 31) == 0) { redS[tid >> 5] = s; redQ[tid >> 5] = q; }
    __syncthreads();
    if (tid < 32) {
        float ts = (tid < 8) ? redS[tid] : 0.f;
        float tq = (tid < 8) ? redQ[tid] : 0.f;
        #pragma unroll
        for (int o = 4; o; o >>= 1) {
            ts += __shfl_xor_sync(0xffffffffu, ts, o);
            tq += __shfl_xor_sync(0xffffffffu, tq, o);
        }
        if (tid == 0) { redS[0] = ts; redQ[0] = tq; }
    }
    __syncthreads();
    float mean = redS[0] * (1.f / DGPT);
    float var  = redQ[0] * (1.f / DGPT) - mean * mean;
    float rstd = rsqrtf(var + 1e-5f);

    float4 wv = ((const float4*)w)[tid];
    float4 bv = ((const float4*)b)[tid];
    float n0 = (v.x - mean) * rstd * wv.x + bv.x;
    float n1 = (v.y - mean) * rstd * wv.y + bv.y;
    float n2 = (v.z - mean) * rstd * wv.z + bv.z;
    float n3 = (v.w - mean) * rstd * wv.w + bv.w;

    __half2 p01 = __halves2half2(__float2half_rn(n0), __float2half_rn(n1));
    __half2 p23 = __halves2half2(__float2half_rn(n2), __float2half_rn(n3));
    uint2 ho;
    ho.x = *(uint32_t*)&p01; ho.y = *(uint32_t*)&p23;
    ((uint2*)(ohi + (size_t)row * DGPT))[tid] = ho;
}

// ---------------- tensor-core helpers ----------------
__device__ __forceinline__ void ldm4(uint32_t r[4], const __half* p)
{
    uint32_t a = (uint32_t)__cvta_generic_to_shared(p);
    asm volatile("ldmatrix.sync.aligned.m8n8.x4.shared.b16 {%0,%1,%2,%3}, [%4];\n"
                 : "=r"(r[0]), "=r"(r[1]), "=r"(r[2]), "=r"(r[3]) : "r"(a));
}
__device__ __forceinline__ void mma_f32(float c[4], const uint32_t a[4], const uint32_t b[2])
{
    asm volatile(
        "mma.sync.aligned.m16n8k16.row.col.f32.f16.f16.f32 "
        "{%0,%1,%2,%3}, {%4,%5,%6,%7}, {%8,%9}, {%0,%1,%2,%3};\n"
        : "+f"(c[0]), "+f"(c[1]), "+f"(c[2]), "+f"(c[3])
        : "r"(a[0]), "r"(a[1]), "r"(a[2]), "r"(a[3]), "r"(b[0]), "r"(b[1]));
}

#define BKg 32
#define PK  40
#define SMBUF (128*PK)
#define SMMAT (2*SMBUF)
#define GS1 (2*SMMAT*2)   // 40960 B

// ---------------- GEMM (1-term): C = Ahi @ Whi^T, +bias +res fp32 out -------
__global__ void __launch_bounds__(256) gemm_tc(
    const __half* __restrict__ Ahi,
    const __half* __restrict__ Whi,
    const float* __restrict__ bias, const float* __restrict__ res,
    float* __restrict__ C,
    int M, int N, int K)
{
    extern __shared__ __align__(16) __half sm[];
    __half* sAh = sm;
    __half* sBh = sm + SMMAT;

    const int tid  = threadIdx.x;
    const int lane = tid & 31;
    const int wid  = tid >> 5;
    const int wm   = wid >> 2;
    const int wn   = wid & 3;
    const int bm   = blockIdx.y * 128;
    const int bn   = blockIdx.x * 128;

    const int lrow = tid >> 1;
    const int lcol = (tid & 1) << 4;
    const __half* gAh = Ahi + (size_t)(bm + lrow) * K + lcol;
    const __half* gBh = Whi + (size_t)(bn + lrow) * K + lcol;

    const int a_r = wm * 64 + (lane & 15);
    const int a_c = (lane >> 4) * 8;
    const int b_r = wn * 32 + (lane >> 4) * 8 + (lane & 7);
    const int b_c = ((lane >> 3) & 1) * 8;

    float acc[4][4][4];
    #pragma unroll
    for (int mi = 0; mi < 4; mi++)
        #pragma unroll
        for (int ni = 0; ni < 4; ni++)
            #pragma unroll
            for (int r = 0; r < 4; r++) acc[mi][ni][r] = 0.f;

    uint4 rAh0, rAh1, rBh0, rBh1;

    const int NS = K / BKg;
    rAh0 = *(const uint4*)(gAh);     rAh1 = *(const uint4*)(gAh + 8);
    rBh0 = *(const uint4*)(gBh);     rBh1 = *(const uint4*)(gBh + 8);
    {
        __half* p = sAh + lrow * PK + lcol;
        *(uint4*)p = rAh0; *(uint4*)(p + 8) = rAh1;
        p = sBh + lrow * PK + lcol;
        *(uint4*)p = rBh0; *(uint4*)(p + 8) = rBh1;
    }
    __syncthreads();

    for (int s = 0; s < NS; s++) {
        if (s + 1 < NS) {
            int k0 = (s + 1) * BKg;
            rAh0 = *(const uint4*)(gAh + k0);  rAh1 = *(const uint4*)(gAh + k0 + 8);
            rBh0 = *(const uint4*)(gBh + k0);  rBh1 = *(const uint4*)(gBh + k0 + 8);
        }

        const int bo = (s & 1) * SMBUF;
        #pragma unroll
        for (int ks = 0; ks < 2; ks++) {
            const int k0 = ks * 16;
            uint32_t afh[4][4];
            #pragma unroll
            for (int mi = 0; mi < 4; mi++)
                ldm4(afh[mi], sAh + bo + (a_r + mi * 16) * PK + k0 + a_c);
            uint32_t bfh[4][2];
            #pragma unroll
            for (int np = 0; np < 2; np++) {
                uint32_t t[4];
                ldm4(t, sBh + bo + (b_r + np * 16) * PK + k0 + b_c);
                bfh[np * 2][0] = t[0]; bfh[np * 2][1] = t[1];
                bfh[np * 2 + 1][0] = t[2]; bfh[np * 2 + 1][1] = t[3];
            }
            #pragma unroll
            for (int mi = 0; mi < 4; mi++)
                #pragma unroll
                for (int ni = 0; ni < 4; ni++)
                    mma_f32(acc[mi][ni], afh[mi], bfh[ni]);
        }

        if (s + 1 < NS) {
            const int bo2 = ((s + 1) & 1) * SMBUF;
            __half* p = sAh + bo2 + lrow * PK + lcol;
            *(uint4*)p = rAh0; *(uint4*)(p + 8) = rAh1;
            p = sBh + bo2 + lrow * PK + lcol;
            *(uint4*)p = rBh0; *(uint4*)(p + 8) = rBh1;
            __syncthreads();
        }
    }

    const int er = bm + wm * 64 + (lane >> 2);
    const int ec = bn + wn * 32 + (lane & 3) * 2;
    #pragma unroll
    for (int mi = 0; mi < 4; mi++) {
        #pragma unroll
        for (int ni = 0; ni < 4; ni++) {
            const int col = ec + ni * 8;
            #pragma unroll
            for (int h = 0; h < 2; h++) {
                const size_t row = (size_t)(er + mi * 16 + h * 8);
                float v0 = acc[mi][ni][h * 2]     + bias[col];
                float v1 = acc[mi][ni][h * 2 + 1] + bias[col + 1];
                v0 += res[row * N + col];
                v1 += res[row * N + col + 1];
                float2 o; o.x = v0; o.y = v1;
                *(float2*)(C + row * N + col) = o;
            }
        }
    }
}

// ---------------- fused QKV GEMM: [M,3072] = Ahi @ Wqkv^T, fp16 hi out ------
__global__ void __launch_bounds__(256) gemm_qkv(
    const __half* __restrict__ Ahi,
    const __half* __restrict__ Wf,
    const float* __restrict__ bq, const float* __restrict__ bk,
    const float* __restrict__ bv,
    __half* __restrict__ Chi)
{
    extern __shared__ __align__(16) __half sm[];
    __half* sAh = sm;
    __half* sBh = sm + SMMAT;

    const int K = DGPT;
    const int tid  = threadIdx.x;
    const int lane = tid & 31;
    const int wid  = tid >> 5;
    const int wm   = wid >> 2;
    const int wn   = wid & 3;
    const int bm   = blockIdx.y * 128;
    const int bn   = blockIdx.x * 128;

    const int tsel = bn >> 10;
    const float* bias = (tsel == 0) ? bq : ((tsel == 1) ? bk : bv);
    const int cb = bn - (tsel << 10);

    const int lrow = tid >> 1;
    const int lcol = (tid & 1) << 4;
    const __half* gAh = Ahi + (size_t)(bm + lrow) * K + lcol;
    const __half* gBh = Wf  + (size_t)(bn + lrow) * K + lcol;

    const int a_r = wm * 64 + (lane & 15);
    const int a_c = (lane >> 4) * 8;
    const int b_r = wn * 32 + (lane >> 4) * 8 + (lane & 7);
    const int b_c = ((lane >> 3) & 1) * 8;

    float acc[4][4][4];
    #pragma unroll
    for (int mi = 0; mi < 4; mi++)
        #pragma unroll
        for (int ni = 0; ni < 4; ni++)
            #pragma unroll
            for (int r = 0; r < 4; r++) acc[mi][ni][r] = 0.f;

    uint4 rAh0, rAh1, rBh0, rBh1;
    const int NS = K / BKg;
    rAh0 = *(const uint4*)(gAh);     rAh1 = *(const uint4*)(gAh + 8);
    rBh0 = *(const uint4*)(gBh);     rBh1 = *(const uint4*)(gBh + 8);
    {
        __half* p = sAh + lrow * PK + lcol;
        *(uint4*)p = rAh0; *(uint4*)(p + 8) = rAh1;
        p = sBh + lrow * PK + lcol;
        *(uint4*)p = rBh0; *(uint4*)(p + 8) = rBh1;
    }
    __syncthreads();

    for (int s = 0; s < NS; s++) {
        if (s + 1 < NS) {
            int k0 = (s + 1) * BKg;
            rAh0 = *(const uint4*)(gAh + k0);  rAh1 = *(const uint4*)(gAh + k0 + 8);
            rBh0 = *(const uint4*)(gBh + k0);  rBh1 = *(const uint4*)(gBh + k0 + 8);
        }
        const int bo = (s & 1) * SMBUF;
        #pragma unroll
        for (int ks = 0; ks < 2; ks++) {
            const int k0 = ks * 16;
            uint32_t afh[4][4];
            #pragma unroll
            for (int mi = 0; mi < 4; mi++)
                ldm4(afh[mi], sAh + bo + (a_r + mi * 16) * PK + k0 + a_c);
            uint32_t bfh[4][2];
            #pragma unroll
            for (int np = 0; np < 2; np++) {
                uint32_t t[4];
                ldm4(t, sBh + bo + (b_r + np * 16) * PK + k0 + b_c);
                bfh[np * 2][0] = t[0]; bfh[np * 2][1] = t[1];
                bfh[np * 2 + 1][0] = t[2]; bfh[np * 2 + 1][1] = t[3];
            }
            #pragma unroll
            for (int mi = 0; mi < 4; mi++)
                #pragma unroll
                for (int ni = 0; ni < 4; ni++)
                    mma_f32(acc[mi][ni], afh[mi], bfh[ni]);
        }
        if (s + 1 < NS) {
            const int bo2 = ((s + 1) & 1) * SMBUF;
            __half* p = sAh + bo2 + lrow * PK + lcol;
            *(uint4*)p = rAh0; *(uint4*)(p + 8) = rAh1;
            p = sBh + bo2 + lrow * PK + lcol;
            *(uint4*)p = rBh0; *(uint4*)(p + 8) = rBh1;
            __syncthreads();
        }
    }

    const int er  = bm + wm * 64 + (lane >> 2);
    const int ecl = cb + wn * 32 + (lane & 3) * 2;
    const int ecg = bn + wn * 32 + (lane & 3) * 2;
    #pragma unroll
    for (int mi = 0; mi < 4; mi++) {
        #pragma unroll
        for (int ni = 0; ni < 4; ni++) {
            const int coll = ecl + ni * 8;
            const int colg = ecg + ni * 8;
            const float b0 = bias[coll], b1 = bias[coll + 1];
            #pragma unroll
            for (int h = 0; h < 2; h++) {
                const size_t row = (size_t)(er + mi * 16 + h * 8);
                float v0 = acc[mi][ni][h * 2]     + b0;
                float v1 = acc[mi][ni][h * 2 + 1] + b1;
                *(__half2*)(Chi + row * QKVS + colg) =
                    __halves2half2(__float2half_rn(v0), __float2half_rn(v1));
            }
        }
    }
}

// ---------------- fused heads GEMM: 1-term Ahi @ Whi^T, fp32 out ------------
__global__ void __launch_bounds__(256) gemm_heads(
    const __half* __restrict__ Ahi,
    const __half* __restrict__ Whi,
    float* __restrict__ out)
{
    extern __shared__ __align__(16) __half sm[];
    __half* sAh = sm;
    __half* sBh = sm + SMMAT;

    const int K = DGPT;
    const int tid  = threadIdx.x;
    const int lane = tid & 31;
    const int wid  = tid >> 5;
    const int wm   = wid >> 2;
    const int wn   = wid & 3;
    const int bm   = blockIdx.y * 128;
    const int bn   = blockIdx.x * 128;

    const int tsel = bn >> 12;
    float* C = out + (size_t)tsel * MGPT * VGPT;
    const int cb = bn - (tsel << 12);

    const int lrow = tid >> 1;
    const int lcol = (tid & 1) << 4;
    const __half* gAh = Ahi + (size_t)(bm + lrow) * K + lcol;
    const __half* gBh = Whi + (size_t)(bn + lrow) * K + lcol;

    const int a_r = wm * 64 + (lane & 15);
    const int a_c = (lane >> 4) * 8;
    const int b_r = wn * 32 + (lane >> 4) * 8 + (lane & 7);
    const int b_c = ((lane >> 3) & 1) * 8;

    float acc[4][4][4];
    #pragma unroll
    for (int mi = 0; mi < 4; mi++)
        #pragma unroll
        for (int ni = 0; ni < 4; ni++)
            #pragma unroll
            for (int r = 0; r < 4; r++) acc[mi][ni][r] = 0.f;

    uint4 rAh0, rAh1, rBh0, rBh1;
    const int NS = K / BKg;
    rAh0 = *(const uint4*)(gAh);  rAh1 = *(const uint4*)(gAh + 8);
    rBh0 = *(const uint4*)(gBh);  rBh1 = *(const uint4*)(gBh + 8);
    {
        __half* p = sAh + lrow * PK + lcol;
        *(uint4*)p = rAh0; *(uint4*)(p + 8) = rAh1;
        p = sBh + lrow * PK + lcol;
        *(uint4*)p = rBh0; *(uint4*)(p + 8) = rBh1;
    }
    __syncthreads();

    for (int s = 0; s < NS; s++) {
        if (s + 1 < NS) {
            int k0 = (s + 1) * BKg;
            rAh0 = *(const uint4*)(gAh + k0);  rAh1 = *(const uint4*)(gAh + k0 + 8);
            rBh0 = *(const uint4*)(gBh + k0);  rBh1 = *(const uint4*)(gBh + k0 + 8);
        }
        const int bo = (s & 1) * SMBUF;
        #pragma unroll
        for (int ks = 0; ks < 2; ks++) {
            const int k0 = ks * 16;
            uint32_t afh[4][4];
            #pragma unroll
            for (int mi = 0; mi < 4; mi++)
                ldm4(afh[mi], sAh + bo + (a_r + mi * 16) * PK + k0 + a_c);
            uint32_t bfh[4][2];
            #pragma unroll
            for (int np = 0; np < 2; np++) {
                uint32_t t[4];
                ldm4(t, sBh + bo + (b_r + np * 16) * PK + k0 + b_c);
                bfh[np * 2][0] = t[0]; bfh[np * 2][1] = t[1];
                bfh[np * 2 + 1][0] = t[2]; bfh[np * 2 + 1][1] = t[3];
            }
            #pragma unroll
            for (int mi = 0; mi < 4; mi++)
                #pragma unroll
                for (int ni = 0; ni < 4; ni++)
                    mma_f32(acc[mi][ni], afh[mi], bfh[ni]);
        }
        if (s + 1 < NS) {
            const int bo2 = ((s + 1) & 1) * SMBUF;
            __half* p = sAh + bo2 + lrow * PK + lcol;
            *(uint4*)p = rAh0; *(uint4*)(p + 8) = rAh1;
            p = sBh + bo2 + lrow * PK + lcol;
            *(uint4*)p = rBh0; *(uint4*)(p + 8) = rBh1;
            __syncthreads();
        }
    }

    const int er = bm + wm * 64 + (lane >> 2);
    const int ec = cb + wn * 32 + (lane & 3) * 2;
    #pragma unroll
    for (int mi = 0; mi < 4; mi++) {
        #pragma unroll
        for (int ni = 0; ni < 4; ni++) {
            const int col = ec + ni * 8;
            #pragma unroll
            for (int h = 0; h < 2; h++) {
                const size_t row = (size_t)(er + mi * 16 + h * 8);
                float2 o;
                o.x = acc[mi][ni][h * 2];
                o.y = acc[mi][ni][h * 2 + 1];
                *(float2*)(C + row * VGPT + col) = o;
            }
        }
    }
}

// ---------------- GEMM (BN=256, warp 64x64) for W1: GELU, fp16 hi out ------
#define W1_SA (128*PK)
#define W1_SB (256*PK)
#define W1_STG (W1_SA + W1_SB)
#define GSW (2*W1_STG*2)

__global__ void __launch_bounds__(256) gemm_w1(
    const __half* __restrict__ Ahi, const __half* __restrict__ Whi,
    const float* __restrict__ bias, __half* __restrict__ Chi,
    int M, int N, int K)
{
    extern __shared__ __align__(16) __half sm[];

    const int tid  = threadIdx.x;
    const int lane = tid & 31;
    const int wid  = tid >> 5;
    const int wm   = wid >> 2;
    const int wn   = wid & 3;
    const int bm   = blockIdx.y * 128;
    const int bn   = blockIdx.x * 256;

    const int lrow = tid >> 1;
    const int lcol = (tid & 1) << 4;
    const __half* gA  = Ahi + (size_t)(bm + lrow) * K + lcol;
    const __half* gB0 = Whi + (size_t)(bn + lrow) * K + lcol;
    const __half* gB1 = Whi + (size_t)(bn + 128 + lrow) * K + lcol;

    const int a_r = wm * 64 + (lane & 15);
    const int a_c = (lane >> 4) * 8;
    const int b_r = wn * 64 + (lane >> 4) * 8 + (lane & 7);
    const int b_c = ((lane >> 3) & 1) * 8;

    float acc[4][8][4];
    #pragma unroll
    for (int mi = 0; mi < 4; mi++)
        #pragma unroll
        for (int ni = 0; ni < 8; ni++)
            #pragma unroll
            for (int r = 0; r < 4; r++) acc[mi][ni][r] = 0.f;

    uint4 rA0, rA1, rB00, rB01, rB10, rB11;

    const int NS = K / BKg;
    rA0  = *(const uint4*)(gA);      rA1  = *(const uint4*)(gA + 8);
    rB00 = *(const uint4*)(gB0);     rB01 = *(const uint4*)(gB0 + 8);
    rB10 = *(const uint4*)(gB1);     rB11 = *(const uint4*)(gB1 + 8);
    {
        __half* p = sm + lrow * PK + lcol;
        *(uint4*)p = rA0; *(uint4*)(p + 8) = rA1;
        p = sm + W1_SA + lrow * PK + lcol;
        *(uint4*)p = rB00; *(uint4*)(p + 8) = rB01;
        p = sm + W1_SA + (128 + lrow) * PK + lcol;
        *(uint4*)p = rB10; *(uint4*)(p + 8) = rB11;
    }
    __syncthreads();

    for (int s = 0; s < NS; s++) {
        if (s + 1 < NS) {
            int k0 = (s + 1) * BKg;
            rA0  = *(const uint4*)(gA + k0);   rA1  = *(const uint4*)(gA + k0 + 8);
            rB00 = *(const uint4*)(gB0 + k0);  rB01 = *(const uint4*)(gB0 + k0 + 8);
            rB10 = *(const uint4*)(gB1 + k0);  rB11 = *(const uint4*)(gB1 + k0 + 8);
        }

        const __half* stg = sm + (s & 1) * W1_STG;
        const __half* sA = stg;
        const __half* sB = stg + W1_SA;
        #pragma unroll
        for (int ks = 0; ks < 2; ks++) {
            const int k0 = ks * 16;
            uint32_t af[4][4];
            #pragma unroll
            for (int mi = 0; mi < 4; mi++)
                ldm4(af[mi], sA + (a_r + mi * 16) * PK + k0 + a_c);
            uint32_t bf[8][2];
            #pragma unroll
            for (int nb = 0; nb < 4; nb++) {
                uint32_t t[4];
                ldm4(t, sB + (b_r + nb * 16) * PK + k0 + b_c);
                bf[nb * 2][0] = t[0]; bf[nb * 2][1] = t[1];
                bf[nb * 2 + 1][0] = t[2]; bf[nb * 2 + 1][1] = t[3];
            }
            #pragma unroll
            for (int mi = 0; mi < 4; mi++)
                #pragma unroll
                for (int ni = 0; ni < 8; ni++)
                    mma_f32(acc[mi][ni], af[mi], bf[ni]);
        }

        if (s + 1 < NS) {
            __half* stg2 = sm + ((s + 1) & 1) * W1_STG;
            __half* p = stg2 + lrow * PK + lcol;
            *(uint4*)p = rA0; *(uint4*)(p + 8) = rA1;
            p = stg2 + W1_SA + lrow * PK + lcol;
            *(uint4*)p = rB00; *(uint4*)(p + 8) = rB01;
            p = stg2 + W1_SA + (128 + lrow) * PK + lcol;
            *(uint4*)p = rB10; *(uint4*)(p + 8) = rB11;
            __syncthreads();
        }
    }

    const int er = bm + wm * 64 + (lane >> 2);
    const int ec = bn + wn * 64 + (lane & 3) * 2;
    #pragma unroll
    for (int mi = 0; mi < 4; mi++) {
        #pragma unroll
        for (int ni = 0; ni < 8; ni++) {
            const int col = ec + ni * 8;
            const float b0 = bias[col], b1 = bias[col + 1];
            #pragma unroll
            for (int h = 0; h < 2; h++) {
                const size_t row = (size_t)(er + mi * 16 + h * 8);
                float v0 = acc[mi][ni][h * 2]     + b0;
                float v1 = acc[mi][ni][h * 2 + 1] + b1;
                v0 = 0.5f * v0 * (1.f + erff(v0 * 0.70710678118654752f));
                v1 = 0.5f * v1 * (1.f + erff(v1 * 0.70710678118654752f));
                *(__half2*)(Chi + row * N + col) =
                    __halves2half2(__float2half_rn(v0), __float2half_rn(v1));
            }
        }
    }
}

// ---------------- tensor-core flash attention ----------------
// Q-block 128 rows, 8 warps. S = Qhi*Khi; O += P16 * Vhi. (all hi)
#define ATS 72
#define ATT_SMEM ((128 + 2*64)*ATS*2)   // 36864 B

__global__ void __launch_bounds__(256) attn_mma(
    const __half* __restrict__ qkvh,
    __half* __restrict__ yhi)
{
    extern __shared__ __align__(16) __half sa[];
    __half* sQh = sa;                     // 128 x ATS
    __half* sKh = sa + 128 * ATS;         // 64 x ATS
    __half* sVh = sa + 192 * ATS;         // transposed: [d][kv] 64 x ATS

    const int bh = blockIdx.x;
    const int b  = bh / HGPT;
    const int h  = bh % HGPT;
    const int qb = blockIdx.y;            // 128-row q block
    const int tid  = threadIdx.x;
    const int w    = tid >> 5;
    const int lane = tid & 31;

    const size_t rowb = (size_t)(b * TGPT);
    const int hoff = h * HDH;

    // Q tile (128x64, hi)
    for (int f = tid; f < 1024; f += 256) {
        int r = f >> 3, c8 = (f & 7) * 8;
        size_t g = (rowb + qb * 128 + r) * QKVS + hoff + c8;
        *(uint4*)(sQh + r * ATS + c8) = *(const uint4*)(qkvh + g);
    }

    float O[8][4];
    #pragma unroll
    for (int t = 0; t < 8; t++)
        #pragma unroll
        for (int r = 0; r < 4; r++) O[t][r] = 0.f;
    float m1 = -1e30f, m2 = -1e30f, l1 = 0.f, l2 = 0.f;

    const int a_row  = w * 16 + (lane & 15);
    const int a_coff = (lane >> 4) * 8;
    const int b_row  = (lane >> 4) * 8 + (lane & 7);
    const int b_coff = ((lane >> 3) & 1) * 8;
    const int rl1 = w * 16 + (lane >> 2);
    const int cl0 = 2 * (lane & 3);
    const int grow1 = qb * 128 + rl1;

    const int nch = 2 * qb + 2;
    for (int ch = 0; ch < nch; ch++) {
        const int j0 = ch * 64;
        __syncthreads();
        for (int f = tid; f < 512; f += 256) {
            int r = f >> 3, c8 = (f & 7) * 8;
            size_t g = (rowb + j0 + r) * QKVS + DGPT + hoff + c8;
            *(uint4*)(sKh + r * ATS + c8) = *(const uint4*)(qkvh + g);
        }
        for (int f = tid; f < 1024; f += 256) {     // V hi transposed
            int r = f >> 4, c4 = (f & 15) * 4;
            size_t g = (rowb + j0 + r) * QKVS + 2 * DGPT + hoff + c4;
            uint2 hv = *(const uint2*)(qkvh + g);
            __half2 h01 = *(__half2*)&hv.x, h23 = *(__half2*)&hv.y;
            sVh[(c4 + 0) * ATS + r] = __low2half(h01);
            sVh[(c4 + 1) * ATS + r] = __high2half(h01);
            sVh[(c4 + 2) * ATS + r] = __low2half(h23);
            sVh[(c4 + 3) * ATS + r] = __high2half(h23);
        }
        __syncthreads();

        float S[8][4];
        #pragma unroll
        for (int t = 0; t < 8; t++)
            #pragma unroll
            for (int r = 0; r < 4; r++) S[t][r] = 0.f;

        #pragma unroll
        for (int ks = 0; ks < 4; ks++) {
            uint32_t aqh[4];
            ldm4(aqh, sQh + a_row * ATS + ks * 16 + a_coff);
            #pragma unroll
            for (int nb = 0; nb < 4; nb++) {
                uint32_t t4[4];
                ldm4(t4, sKh + (nb * 16 + b_row) * ATS + ks * 16 + b_coff);
                uint32_t bh0[2] = { t4[0], t4[1] };
                uint32_t bh1[2] = { t4[2], t4[3] };
                mma_f32(S[2 * nb],     aqh, bh0);
                mma_f32(S[2 * nb + 1], aqh, bh1);
            }
        }

        const bool diag = (ch >= 2 * qb);
        #pragma unroll
        for (int t = 0; t < 8; t++) {
            S[t][0] *= 0.125f; S[t][1] *= 0.125f;
            S[t][2] *= 0.125f; S[t][3] *= 0.125f;
            if (diag) {
                int c0 = j0 + t * 8 + cl0, c1 = c0 + 1;
                if (c0 > grow1)     S[t][0] = -1e30f;
                if (c1 > grow1)     S[t][1] = -1e30f;
                if (c0 > grow1 + 8) S[t][2] = -1e30f;
                if (c1 > grow1 + 8) S[t][3] = -1e30f;
            }
        }

        float mx1 = -1e30f, mx2 = -1e30f;
        #pragma unroll
        for (int t = 0; t < 8; t++) {
            mx1 = fmaxf(mx1, fmaxf(S[t][0], S[t][1]));
            mx2 = fmaxf(mx2, fmaxf(S[t][2], S[t][3]));
        }
        mx1 = fmaxf(mx1, __shfl_xor_sync(0xffffffffu, mx1, 1));
        mx1 = fmaxf(mx1, __shfl_xor_sync(0xffffffffu, mx1, 2));
        mx2 = fmaxf(mx2, __shfl_xor_sync(0xffffffffu, mx2, 1));
        mx2 = fmaxf(mx2, __shfl_xor_sync(0xffffffffu, mx2, 2));

        float mn1 = fmaxf(m1, mx1), mn2 = fmaxf(m2, mx2);
        float cr1 = __expf(m1 - mn1), cr2 = __expf(m2 - mn2);
        m1 = mn1; m2 = mn2;

        float s1 = 0.f, s2 = 0.f;
        uint32_t Pf[4][4];
        #pragma unroll
        for (int t = 0; t < 8; t++) {
            float p0 = __expf(S[t][0] - mn1);
            float p1 = __expf(S[t][1] - mn1);
            float p2 = __expf(S[t][2] - mn2);
            float p3 = __expf(S[t][3] - mn2);
            s1 += p0 + p1; s2 += p2 + p3;
            __half2 ph01 = __halves2half2(__float2half_rn(p0), __float2half_rn(p1));
            __half2 ph23 = __halves2half2(__float2half_rn(p2), __float2half_rn(p3));
            const int kt = t >> 1, hf = (t & 1) * 2;
            Pf[kt][hf + 0] = *(uint32_t*)&ph01;
            Pf[kt][hf + 1] = *(uint32_t*)&ph23;
        }
        s1 += __shfl_xor_sync(0xffffffffu, s1, 1);
        s1 += __shfl_xor_sync(0xffffffffu, s1, 2);
        s2 += __shfl_xor_sync(0xffffffffu, s2, 1);
        s2 += __shfl_xor_sync(0xffffffffu, s2, 2);
        l1 = l1 * cr1 + s1;
        l2 = l2 * cr2 + s2;
        #pragma unroll
        for (int t = 0; t < 8; t++) {
            O[t][0] *= cr1; O[t][1] *= cr1;
            O[t][2] *= cr2; O[t][3] *= cr2;
        }

        #pragma unroll
        for (int kt = 0; kt < 4; kt++) {
            #pragma unroll
            for (int nb = 0; nb < 4; nb++) {
                uint32_t t4[4];
                ldm4(t4, sVh + (nb * 16 + b_row) * ATS + kt * 16 + b_coff);
                uint32_t bv0[2] = { t4[0], t4[1] };
                uint32_t bv1[2] = { t4[2], t4[3] };
                mma_f32(O[2 * nb],     Pf[kt], bv0);
                mma_f32(O[2 * nb + 1], Pf[kt], bv1);
            }
        }
    }

    const float inv1 = 1.f / l1, inv2 = 1.f / l2;
    const size_t row1 = (rowb + qb * 128 + rl1) * DGPT + hoff;
    const size_t row2 = (rowb + qb * 128 + rl1 + 8) * DGPT + hoff;
    #pragma unroll
    for (int t = 0; t < 8; t++) {
        const int col = t * 8 + cl0;
        *(__half2*)(yhi + row1 + col) =
            __halves2half2(__float2half_rn(O[t][0] * inv1), __float2half_rn(O[t][1] * inv1));
        *(__half2*)(yhi + row2 + col) =
            __halves2half2(__float2half_rn(O[t][2] * inv2), __float2half_rn(O[t][3] * inv2));
    }
}

// ---------------- launcher ----------------
static inline void convhi(const float* in, __half* hi, size_t n)
{
    size_t n8 = n / 8;
    convhi_kernel<<<(unsigned)((n8 + 255) / 256), 256>>>(in, hi, n8);
}

extern "C" void kernel_launch(void* const* d_in, const int* in_sizes, int n_in,
                              void* d_out, int out_size)
{
    const int*   idx    = (const int*)  d_in[0];
    const float* tok    = (const float*)d_in[1];
    const float* pos    = (const float*)d_in[2];
    const float* ln1_w  = (const float*)d_in[3];
    const float* ln1_b  = (const float*)d_in[4];
    const float* Wq     = (const float*)d_in[5];
    const float* bq     = (const float*)d_in[6];
    const float* Wk     = (const float*)d_in[7];
    const float* bk     = (const float*)d_in[8];
    const float* Wv     = (const float*)d_in[9];
    const float* bv     = (const float*)d_in[10];
    const float* Wproj  = (const float*)d_in[11];
    const float* bproj  = (const float*)d_in[12];
    const float* ln2_w  = (const float*)d_in[13];
    const float* ln2_b  = (const float*)d_in[14];
    const float* W1     = (const float*)d_in[15];
    const float* b1     = (const float*)d_in[16];
    const float* W2     = (const float*)d_in[17];
    const float* b2     = (const float*)d_in[18];
    const float* lnf_w  = (const float*)d_in[19];
    const float* lnf_b  = (const float*)d_in[20];
    const float* Wlogit = (const float*)d_in[21];
    const float* Wdev   = (const float*)d_in[22];
    float* out = (float*)d_out;

    float* xp;
    __half *whi, *ahi, *fhi, *qkvh;
    cudaGetSymbolAddress((void**)&xp,   g_x);
    cudaGetSymbolAddress((void**)&whi,  g_whi);
    cudaGetSymbolAddress((void**)&ahi,  g_ahi);
    cudaGetSymbolAddress((void**)&fhi,  g_fhi);
    cudaGetSymbolAddress((void**)&qkvh, g_qkvh);

    cudaFuncSetAttribute((const void*)gemm_tc,    cudaFuncAttributeMaxDynamicSharedMemorySize, GS1);
    cudaFuncSetAttribute((const void*)gemm_qkv,   cudaFuncAttributeMaxDynamicSharedMemorySize, GS1);
    cudaFuncSetAttribute((const void*)gemm_heads, cudaFuncAttributeMaxDynamicSharedMemorySize, GS1);
    cudaFuncSetAttribute((const void*)gemm_w1,    cudaFuncAttributeMaxDynamicSharedMemorySize, GSW);
    cudaFuncSetAttribute((const void*)attn_mma,   cudaFuncAttributeMaxDynamicSharedMemorySize, ATT_SMEM);

    {
        size_t n4 = (LGPT * DD) / 4;
        unsigned g = (unsigned)((n4 + 255) / 256);
        convqkv_kernel<<<g, 256>>>(Wq, whi + O_QKV, 0, n4);
        convqkv_kernel<<<g, 256>>>(Wk, whi + O_QKV, 1, n4);
        convqkv_kernel<<<g, 256>>>(Wv, whi + O_QKV, 2, n4);
    }
    convhi(Wproj,  whi + O_WP,  LGPT * DD);
    convhi(W1,     whi + O_W1,  (size_t)LGPT * 4 * DD);
    convhi(W2,     whi + O_W2,  (size_t)LGPT * 4 * DD);
    convhi(Wlogit, whi + O_WLG, 4 * DD);
    convhi(Wdev,   whi + O_WDV, 4 * DD);

    dim3 gQ(QKVS / 128, MGPT / 128);
    dim3 gD(DGPT / 128, MGPT / 128);
    dim3 gW(FGPT / 256, MGPT / 128);
    dim3 gH(2 * VGPT / 128, MGPT / 128);
    dim3 gA(BGPT * HGPT, TGPT / 128);

    embed_kernel<<<(MGPT * DGPT + 255) / 256, 256>>>(idx, tok, pos, xp);

    for (int l = 0; l < LGPT; l++) {
        size_t oQ  = O_QKV + (size_t)l * 3 * DD;
        size_t oP  = O_WP  + (size_t)l * DD;
        size_t o1  = O_W1  + (size_t)l * 4 * DD;
        size_t o2  = O_W2  + (size_t)l * 4 * DD;
        size_t ob  = (size_t)l * DGPT;
        size_t obf = (size_t)l * FGPT;

        ln_kernel<<<MGPT, 256>>>(xp, ahi, ln1_w + ob, ln1_b + ob);
        gemm_qkv<<<gQ, 256, GS1>>>(ahi, whi + oQ, bq + ob, bk + ob, bv + ob, qkvh);
        attn_mma<<<gA, 256, ATT_SMEM>>>(qkvh, ahi);
        gemm_tc<<<gD, 256, GS1>>>(ahi, whi + oP, bproj + ob, xp, xp, MGPT, DGPT, DGPT);

        ln_kernel<<<MGPT, 256>>>(xp, ahi, ln2_w + ob, ln2_b + ob);
        gemm_w1<<<gW, 256, GSW>>>(ahi, whi + o1, b1 + obf, fhi, MGPT, FGPT, DGPT);
        gemm_tc<<<gD, 256, GS1>>>(fhi, whi + o2, b2 + ob, xp, xp, MGPT, DGPT, FGPT);
    }

    ln_kernel<<<MGPT, 256>>>(xp, ahi, lnf_w, lnf_b);
    gemm_heads<<<gH, 256, GS1>>>(ahi, whi + O_WLG, out);
}